// round 1
// baseline (speedup 1.0000x reference)
#include <cuda_runtime.h>
#include <cuda_bf16.h>
#include <math.h>

// Problem constants
#define NR 64
#define NT 8
#define LD 128
#define LP 16
#define LT 144          // LD + LP
#define BSZ 512
#define MM 1024
#define NN 2048         // LDPC_N
#define NTH 256

#define SQ2F 1.41421356237309504880f

// -------- scratch (device globals; no runtime allocation) --------
__device__ float g_Ur[128 * 128];
__device__ float g_UrT[128 * 128];
__device__ float g_F[BSZ * 16 * LD];   // F (B,16,128)
__device__ float g_Vs[BSZ * MM];       // theta - z - lambda1, (B,1024)

// ================= K0: build Ur / UrT =================
__global__ void const_kernel(const float* __restrict__ rUr, const float* __restrict__ iUr) {
    int e = blockIdx.x * blockDim.x + threadIdx.x;
    if (e >= 128 * 128) return;
    int i = e >> 7, j = e & 127;
    float v, vt;
    // Ur = [[r, -i],[i, r]]
    if (i < 64) v = (j < 64) ? rUr[i * 64 + j] : -iUr[i * 64 + (j - 64)];
    else        v = (j < 64) ? iUr[(i - 64) * 64 + j] : rUr[(i - 64) * 64 + (j - 64)];
    g_Ur[e] = v;
    // UrT = [[rT, iT],[-iT, rT]]
    if (i < 64) vt = (j < 64) ? rUr[j * 64 + i] : iUr[(j - 64) * 64 + i];
    else        vt = (j < 64) ? -iUr[j * 64 + (i - 64)] : rUr[(j - 64) * 64 + (i - 64)];
    g_UrT[e] = vt;
}

// ================= K_v: V = theta - z - lambda1 =================
__global__ void v_kernel(const float* __restrict__ theta, const float* __restrict__ z,
                         const float* __restrict__ l1) {
    int e = blockIdx.x * blockDim.x + threadIdx.x;
    if (e < BSZ * MM) {
        int m = e & (MM - 1);
        g_Vs[e] = theta[m] - z[e] - l1[e];
    }
}

// ================= K1: per-batch chain =================
// smem layout (floats)
#define O_XXP   0        // 2304
#define O_UTX   2304     // 2304
#define O_H     4608     // 1024
#define O_URH   5632     // 1024  (later reused for UrHv)
#define O_HV    6656     // 1024
#define O_CH    7680     // 2048  delta chunk 128x16
#define O_YC    9728     // 2048  YYp chunk 128x16
#define O_D     11776    // 1024
#define O_HVE   12800    // 1024
#define O_HN    13824    // 1024
#define O_W     14848    // 2048
#define O_WTW   16896    // 256
#define SMEM_FLOATS 17152

__global__ void batch_kernel(
    const float* __restrict__ sigma2, const float* __restrict__ X,
    const float* __restrict__ XXp, const float* __restrict__ Y,
    const float* __restrict__ YYp, const float* __restrict__ H,
    const float* __restrict__ lambda_W,
    const float* __restrict__ rUt, const float* __restrict__ iUt,
    const float* __restrict__ tao_p, const float* __restrict__ eps_p,
    const float* __restrict__ factor_p,
    float* __restrict__ out_Hnew, float* __restrict__ out_lamW)
{
    extern __shared__ float sm[];
    float* sXXp = sm + O_XXP;
    float* sUtX = sm + O_UTX;
    float* sH   = sm + O_H;
    float* sUrH = sm + O_URH;
    float* sHv  = sm + O_HV;
    float* sCh  = sm + O_CH;
    float* sYc  = sm + O_YC;
    float* sD   = sm + O_D;
    float* sHve = sm + O_HVE;
    float* sHn  = sm + O_HN;
    float* sW   = sm + O_W;
    float* sWTW = sm + O_WTW;

    const int b = blockIdx.x;
    const int tid = threadIdx.x;
    const float tao = tao_p[0];

    // ---- load XXp[b], H[b] ----
    const float* XXpb = XXp + (size_t)b * 16 * LT;
    for (int i = tid; i < 16 * LT; i += NTH) sXXp[i] = XXpb[i];
    const float* Hb = H + (size_t)b * 128 * 8;
    for (int i = tid; i < 1024; i += NTH) sH[i] = Hb[i];
    __syncthreads();

    // ---- UtTXXp = UtT @ XXp  (16 x 144) ----
    for (int e = tid; e < 16 * LT; e += NTH) {
        int i = e / LT, l = e % LT;
        float acc = 0.f;
        if (i < 8) {
            #pragma unroll
            for (int k = 0; k < 8; k++) {
                acc += rUt[k * 8 + i] * sXXp[k * LT + l];
                acc += iUt[k * 8 + i] * sXXp[(8 + k) * LT + l];
            }
        } else {
            int i2 = i - 8;
            #pragma unroll
            for (int k = 0; k < 8; k++) {
                acc -= iUt[k * 8 + i2] * sXXp[k * LT + l];
                acc += rUt[k * 8 + i2] * sXXp[(8 + k) * LT + l];
            }
        }
        sUtX[e] = acc;
    }
    // ---- UrH_temp = UrT @ H[b]  (128 x 8) ----
    for (int e = tid; e < 1024; e += NTH) {
        int r = e >> 3, c = e & 7;
        float acc = 0.f;
        const float* urt = g_UrT + r * 128;
        #pragma unroll 4
        for (int k = 0; k < 128; k++) acc += urt[k] * sH[k * 8 + c];
        sUrH[e] = acc;
    }
    __syncthreads();

    // ---- Hv_temp = _blkb(UrH) @ Ut  (128 x 8) ----
    for (int e = tid; e < 1024; e += NTH) {
        int r = e >> 3, c = e & 7;
        float acc = 0.f;
        if (r < 64) {
            #pragma unroll
            for (int k = 0; k < 8; k++)
                acc += sUrH[r * 8 + k] * rUt[k * 8 + c] - sUrH[(64 + r) * 8 + k] * iUt[k * 8 + c];
        } else {
            int r2 = r - 64;
            #pragma unroll
            for (int k = 0; k < 8; k++)
                acc += sUrH[(64 + r2) * 8 + k] * rUt[k * 8 + c] + sUrH[r2 * 8 + k] * iUt[k * 8 + c];
        }
        sHv[e] = acc;
    }
    __syncthreads();

    // ---- chunked: delta_temp = Hv@UtTXXp - UrT@YYp, accumulate D = delta @ UtTXXpT ----
    float dacc[4] = {0.f, 0.f, 0.f, 0.f};
    const float* YYpb = YYp + (size_t)b * 128 * LT;
    for (int lc = 0; lc < 9; lc++) {
        int l0 = lc * 16;
        for (int e = tid; e < 2048; e += NTH) {
            int k = e >> 4, j = e & 15;
            sYc[e] = YYpb[k * LT + l0 + j];
        }
        __syncthreads();
        for (int e = tid; e < 2048; e += NTH) {
            int r = e >> 4, j = e & 15;
            int l = l0 + j;
            float acc = 0.f;
            if (r < 64) {
                #pragma unroll
                for (int t = 0; t < 8; t++)
                    acc += sHv[r * 8 + t] * sUtX[t * LT + l] - sHv[(64 + r) * 8 + t] * sUtX[(8 + t) * LT + l];
            } else {
                int r2 = r - 64;
                #pragma unroll
                for (int t = 0; t < 8; t++)
                    acc += sHv[(64 + r2) * 8 + t] * sUtX[t * LT + l] + sHv[r2 * 8 + t] * sUtX[(8 + t) * LT + l];
            }
            const float* urt = g_UrT + r * 128;
            float acc2 = 0.f;
            #pragma unroll 4
            for (int k = 0; k < 128; k++) acc2 += urt[k] * sYc[k * 16 + j];
            sCh[e] = acc - acc2;
        }
        __syncthreads();
        #pragma unroll
        for (int q = 0; q < 4; q++) {
            int idx = tid + NTH * q;
            int r = idx >> 3, t = idx & 7;
            float a = dacc[q];
            if (r < 64) {
                #pragma unroll
                for (int j = 0; j < 16; j++) {
                    int l = l0 + j;
                    a += sCh[r * 16 + j] * sUtX[t * LT + l] + sCh[(64 + r) * 16 + j] * sUtX[(8 + t) * LT + l];
                }
            } else {
                int r2 = r - 64;
                #pragma unroll
                for (int j = 0; j < 16; j++) {
                    int l = l0 + j;
                    a += sCh[(64 + r2) * 16 + j] * sUtX[t * LT + l] - sCh[r2 * 16 + j] * sUtX[(8 + t) * LT + l];
                }
            }
            dacc[q] = a;
        }
        __syncthreads();
    }
    #pragma unroll
    for (int q = 0; q < 4; q++) sD[tid + NTH * q] = dacc[q];
    __syncthreads();

    // ---- Hvest = Hv - tao*D ; soft-threshold ----
    for (int e = tid; e < 1024; e += NTH) sHve[e] = sHv[e] - tao * sD[e];
    __syncthreads();
    {
        float thr = tao * eps_p[0] * sigma2[b];
        for (int e = tid; e < 512; e += NTH) {
            float re = sHve[e], im = sHve[e + 512];
            float mag = sqrtf(re * re + im * im);
            float s = fmaxf(mag - thr, 0.f) / mag;
            sHve[e] = re * s;
            sHve[e + 512] = im * s;
        }
    }
    __syncthreads();

    // ---- UrHv = Ur @ Hvest ----
    for (int e = tid; e < 1024; e += NTH) {
        int r = e >> 3, c = e & 7;
        float acc = 0.f;
        const float* ur = g_Ur + r * 128;
        #pragma unroll 4
        for (int k = 0; k < 128; k++) acc += ur[k] * sHve[k * 8 + c];
        sUrH[e] = acc;  // reuse buffer
    }
    __syncthreads();

    // ---- H_new = _blkb(UrHv) @ UtT2 ----
    for (int e = tid; e < 1024; e += NTH) {
        int r = e >> 3, c = e & 7;
        float acc = 0.f;
        if (r < 64) {
            #pragma unroll
            for (int k = 0; k < 8; k++)
                acc += sUrH[r * 8 + k] * rUt[c * 8 + k] + sUrH[(64 + r) * 8 + k] * iUt[c * 8 + k];
        } else {
            int r2 = r - 64;
            #pragma unroll
            for (int k = 0; k < 8; k++)
                acc += sUrH[(64 + r2) * 8 + k] * rUt[c * 8 + k] - sUrH[r2 * 8 + k] * iUt[c * 8 + k];
        }
        sHn[e] = acc;
        out_Hnew[(size_t)b * 1024 + e] = acc;
    }
    __syncthreads();

    // ---- W = _blkb(H_new)  (128 x 16) ----
    for (int e = tid; e < 2048; e += NTH) {
        int r = e >> 4, i = e & 15;
        float v;
        if (r < 64) v = (i < 8) ? sHn[r * 8 + i] : -sHn[(64 + r) * 8 + (i - 8)];
        else        v = (i < 8) ? sHn[r * 8 + i] : sHn[(r - 64) * 8 + (i - 8)];
        sW[e] = v;
    }
    __syncthreads();

    // ---- WTW ----
    {
        int i = tid >> 4, j = tid & 15;
        float acc = 0.f;
        #pragma unroll 4
        for (int r = 0; r < 128; r++) acc += sW[r * 16 + i] * sW[r * 16 + j];
        sWTW[tid] = acc;
    }
    __syncthreads();

    // ---- F = W^T Y + lamW*X - WTW@X  -> g_F ----
    float lamW = factor_p[0] * lambda_W[b];
    const float* Yb = Y + (size_t)b * 128 * LD;
    const float* Xb = X + (size_t)b * 16 * LD;
    float* Fb = g_F + (size_t)b * 16 * LD;
    for (int e = tid; e < 2048; e += NTH) {
        int i = e >> 7, l = e & 127;
        float acc = 0.f;
        #pragma unroll 4
        for (int r = 0; r < 128; r++) acc += sW[r * 16 + i] * Yb[r * LD + l];
        float acc2 = 0.f;
        #pragma unroll
        for (int j = 0; j < 16; j++) acc2 += sWTW[i * 16 + j] * Xb[j * LD + l];
        Fb[e] = acc + lamW * Xb[e] - acc2;
    }
    if (tid == 0) out_lamW[b] = lamW;
}

// ================= GEMM1: T1 = A^T V ; epilogue -> u_new =================
__global__ void gemm1_kernel(const float* __restrict__ A, const float* __restrict__ Lambda_A,
                             const float* __restrict__ lambda_W, const float* __restrict__ rho_p,
                             const float* __restrict__ kappa_p, const float* __restrict__ factor_p,
                             float* __restrict__ out_u)
{
    __shared__ float As[16][64];      // [k(m)][n]
    __shared__ float Bst[64][17];     // [b][k(m)]
    int n0 = blockIdx.x * 64, b0 = blockIdx.y * 64;
    int lid = threadIdx.x;
    int tx = lid & 15, ty = lid >> 4;
    float c[4][4] = {};
    for (int m0 = 0; m0 < MM; m0 += 16) {
        #pragma unroll
        for (int t = 0; t < 4; t++) {
            int idx = lid + NTH * t;
            int i = idx >> 6, j = idx & 63;
            As[i][j] = A[(size_t)(m0 + i) * NN + n0 + j];
        }
        #pragma unroll
        for (int t = 0; t < 4; t++) {
            int idx = lid + NTH * t;
            int i = idx & 15, jb = idx >> 4;
            Bst[jb][i] = g_Vs[(size_t)(b0 + jb) * MM + m0 + i];
        }
        __syncthreads();
        #pragma unroll
        for (int kk = 0; kk < 16; kk++) {
            float a[4], bb[4];
            #pragma unroll
            for (int q = 0; q < 4; q++) a[q] = As[kk][tx * 4 + q];
            #pragma unroll
            for (int q = 0; q < 4; q++) bb[q] = Bst[ty * 4 + q][kk];
            #pragma unroll
            for (int qi = 0; qi < 4; qi++)
                #pragma unroll
                for (int qj = 0; qj < 4; qj++)
                    c[qi][qj] += a[qi] * bb[qj];
        }
        __syncthreads();
    }
    float rho = rho_p[0], kappa = kappa_p[0], factor = factor_p[0];
    #pragma unroll
    for (int qi = 0; qi < 4; qi++) {
        int n = n0 + tx * 4 + qi;
        int l = n >> 4, t = (n >> 1) & 7, ci = n & 1;
        float la = Lambda_A[n];
        #pragma unroll
        for (int qj = 0; qj < 4; qj++) {
            int b = b0 + ty * 4 + qj;
            float lamW = factor * lambda_W[b];
            float fbres = 2.f * lamW - 2.f * SQ2F * g_F[(size_t)b * NN + (ci * 8 + t) * LD + l];
            float qv = rho * c[qi][qj] + fbres - kappa;
            float w = 1.f / (rho * la + 4.f * lamW - 2.f * kappa);
            float u = qv * w;
            u = fminf(fmaxf(u, 0.f), 1.f);
            out_u[(size_t)b * NN + n] = u;
        }
    }
}

// ================= GEMM2: Au = A u_new ; epilogue -> z_new, lambda1_new =================
__global__ void gemm2_kernel(const float* __restrict__ A, const float* __restrict__ u_new,
                             const float* __restrict__ theta, const float* __restrict__ z_old,
                             const float* __restrict__ l1_old, const float* __restrict__ relax_p,
                             const float* __restrict__ acc_p,
                             float* __restrict__ out_z, float* __restrict__ out_l1)
{
    __shared__ float Ast[64][17];  // [m][k(n)]
    __shared__ float Bst[64][17];  // [b][k(n)]
    int m0 = blockIdx.x * 64, b0 = blockIdx.y * 64;
    int lid = threadIdx.x;
    int tx = lid & 15, ty = lid >> 4;
    float c[4][4] = {};
    for (int n0 = 0; n0 < NN; n0 += 16) {
        #pragma unroll
        for (int t = 0; t < 4; t++) {
            int idx = lid + NTH * t;
            int i = idx & 15, j = idx >> 4;
            Ast[j][i] = A[(size_t)(m0 + j) * NN + n0 + i];
        }
        #pragma unroll
        for (int t = 0; t < 4; t++) {
            int idx = lid + NTH * t;
            int i = idx & 15, jb = idx >> 4;
            Bst[jb][i] = u_new[(size_t)(b0 + jb) * NN + n0 + i];
        }
        __syncthreads();
        #pragma unroll
        for (int kk = 0; kk < 16; kk++) {
            float a[4], bb[4];
            #pragma unroll
            for (int q = 0; q < 4; q++) a[q] = Ast[tx * 4 + q][kk];
            #pragma unroll
            for (int q = 0; q < 4; q++) bb[q] = Bst[ty * 4 + q][kk];
            #pragma unroll
            for (int qi = 0; qi < 4; qi++)
                #pragma unroll
                for (int qj = 0; qj < 4; qj++)
                    c[qi][qj] += a[qi] * bb[qj];
        }
        __syncthreads();
    }
    float relax = relax_p[0], acc = acc_p[0];
    #pragma unroll
    for (int qi = 0; qi < 4; qi++) {
        int m = m0 + tx * 4 + qi;
        float th = theta[m];
        #pragma unroll
        for (int qj = 0; qj < 4; qj++) {
            int b = b0 + ty * 4 + qj;
            float zo = z_old[(size_t)b * MM + m];
            float lo = l1_old[(size_t)b * MM + m];
            float ztemp = th - relax * c[qi][qj] - (1.f - relax) * (th - zo) - lo;
            float zn = fmaxf(ztemp, 0.f);
            float ln = zn - ztemp;
            out_z[(size_t)b * MM + m] = zn + acc * (zn - zo);
            out_l1[(size_t)b * MM + m] = ln + acc * (ln - lo);
        }
    }
}

// ================= K4: X_new / XXp_new / acc_new =================
__global__ void x_kernel(const float* __restrict__ u_new, const float* __restrict__ rXp,
                         const float* __restrict__ iXp, const float* __restrict__ accnew_in,
                         float* __restrict__ out_X, float* __restrict__ out_XXp,
                         float* __restrict__ out_acc)
{
    int e = blockIdx.x * blockDim.x + threadIdx.x;
    const int total = BSZ * 16 * LT;
    if (e < total) {
        int b = e / (16 * LT);
        int rem = e - b * (16 * LT);
        int row = rem / LT, l = rem - row * LT;
        int t = row & 7, ci = row >> 3;
        float v;
        if (l < LD) {
            float u = u_new[(size_t)b * NN + l * 16 + t * 2 + ci];
            v = (1.f - 2.f * u) / SQ2F;
            out_X[(size_t)b * 16 * LD + row * LD + l] = v;
        } else {
            int lp = l - LD;
            v = (ci == 0) ? rXp[(size_t)b * NT * LP + t * LP + lp]
                          : iXp[(size_t)b * NT * LP + t * LP + lp];
        }
        out_XXp[e] = v;
    }
    if (e == 0) out_acc[0] = accnew_in[0];
}

// ================= launch =================
extern "C" void kernel_launch(void* const* d_in, const int* in_sizes, int n_in,
                              void* d_out, int out_size) {
    (void)in_sizes; (void)n_in; (void)out_size;
    const float* sigma2   = (const float*)d_in[0];
    const float* X        = (const float*)d_in[1];
    const float* XXp      = (const float*)d_in[2];
    const float* Y        = (const float*)d_in[3];
    const float* YYp      = (const float*)d_in[4];
    const float* rXp      = (const float*)d_in[5];
    const float* iXp      = (const float*)d_in[6];
    const float* H        = (const float*)d_in[7];
    const float* lambda_W = (const float*)d_in[8];
    /* d_in[9] = u (unused by reference) */
    const float* z        = (const float*)d_in[10];
    const float* lambda1  = (const float*)d_in[11];
    const float* acc_new  = (const float*)d_in[12];
    const float* A        = (const float*)d_in[13];
    const float* Lambda_A = (const float*)d_in[14];
    const float* theta    = (const float*)d_in[15];
    const float* rUr      = (const float*)d_in[16];
    const float* iUr      = (const float*)d_in[17];
    const float* rUt      = (const float*)d_in[18];
    const float* iUt      = (const float*)d_in[19];
    const float* rho      = (const float*)d_in[20];
    const float* kappa    = (const float*)d_in[21];
    const float* epsilon  = (const float*)d_in[22];
    const float* tao      = (const float*)d_in[23];
    const float* factor   = (const float*)d_in[24];
    const float* relax    = (const float*)d_in[25];
    const float* acc      = (const float*)d_in[26];

    float* out = (float*)d_out;
    float* out_X    = out;                // 512*16*128 = 1048576
    float* out_XXp  = out + 1048576;      // 512*16*144 = 1179648
    float* out_H    = out + 2228224;      // 512*128*8  = 524288
    float* out_lamW = out + 2752512;      // 512
    float* out_u    = out + 2753024;      // 512*2048   = 1048576
    float* out_z    = out + 3801600;      // 512*1024   = 524288
    float* out_l1   = out + 4325888;      // 512*1024   = 524288
    float* out_acc  = out + 4850176;      // 1

    cudaFuncSetAttribute(batch_kernel, cudaFuncAttributeMaxDynamicSharedMemorySize,
                         SMEM_FLOATS * sizeof(float));

    const_kernel<<<64, 256>>>(rUr, iUr);
    v_kernel<<<(BSZ * MM + 255) / 256, 256>>>(theta, z, lambda1);
    batch_kernel<<<BSZ, NTH, SMEM_FLOATS * sizeof(float)>>>(
        sigma2, X, XXp, Y, YYp, H, lambda_W, rUt, iUt, tao, epsilon, factor,
        out_H, out_lamW);
    {
        dim3 g(NN / 64, BSZ / 64);
        gemm1_kernel<<<g, NTH>>>(A, Lambda_A, lambda_W, rho, kappa, factor, out_u);
    }
    {
        dim3 g(MM / 64, BSZ / 64);
        gemm2_kernel<<<g, NTH>>>(A, out_u, theta, z, lambda1, relax, acc, out_z, out_l1);
    }
    x_kernel<<<(BSZ * 16 * LT + 255) / 256, 256>>>(out_u, rXp, iXp, acc_new,
                                                   out_X, out_XXp, out_acc);
}

// round 2
// speedup vs baseline: 3.1307x; 3.1307x over previous
#include <cuda_runtime.h>
#include <cuda_bf16.h>
#include <math.h>

// Problem constants
#define NR 64
#define NT 8
#define LD 128
#define LP 16
#define LT 144          // LD + LP
#define BSZ 512
#define MM 1024
#define NN 2048         // LDPC_N
#define NTH 256

#define SQ2F 1.41421356237309504880f

// -------- scratch (device globals; no runtime allocation) --------
__device__ float g_Ur[128 * 128];    // Ur[i][j] ; note UrT[r][k] == Ur[k][r]
__device__ float g_UrT[128 * 128];   // UrT[i][j]; note Ur[r][k]  == UrT[k][r]
__device__ float g_F[BSZ * 16 * LD]; // F (B,16,128)
__device__ float g_Vs[BSZ * MM];     // theta - z - lambda1, (B,1024)

// ================= K0: build Ur / UrT =================
__global__ void const_kernel(const float* __restrict__ rUr, const float* __restrict__ iUr) {
    int e = blockIdx.x * blockDim.x + threadIdx.x;
    if (e >= 128 * 128) return;
    int i = e >> 7, j = e & 127;
    float v, vt;
    // Ur = [[r, -i],[i, r]]
    if (i < 64) v = (j < 64) ? rUr[i * 64 + j] : -iUr[i * 64 + (j - 64)];
    else        v = (j < 64) ? iUr[(i - 64) * 64 + j] : rUr[(i - 64) * 64 + (j - 64)];
    g_Ur[e] = v;
    // UrT = [[rT, iT],[-iT, rT]]  ( == Ur^T )
    if (i < 64) vt = (j < 64) ? rUr[j * 64 + i] : iUr[(j - 64) * 64 + i];
    else        vt = (j < 64) ? -iUr[j * 64 + (i - 64)] : rUr[(j - 64) * 64 + (i - 64)];
    g_UrT[e] = vt;
}

// ================= K_v: V = theta - z - lambda1 =================
__global__ void v_kernel(const float* __restrict__ theta, const float* __restrict__ z,
                         const float* __restrict__ l1) {
    int e = blockIdx.x * blockDim.x + threadIdx.x;
    if (e < BSZ * MM) {
        int m = e & (MM - 1);
        g_Vs[e] = theta[m] - z[e] - l1[e];
    }
}

// ================= K1: per-batch chain (restructured) =================
// smem layout (floats)
#define O_XXP   0        // 2304  XXp (16 x 144)
#define O_UTXT  2304     // 2304  UtX transposed: [l][i] (144 x 16)
#define O_HG    4608     // 3072  [k][24]: c0-7 H, c8-15 G_re, c16-23 G_im
#define O_T     7680     // 3072  [r][24]: c0-7 UrH, c8-15 T_re, c16-23 T_im
#define O_HV    10752    // 1024  Hv_temp (128 x 8) -> later UrHv
#define O_S     11776    // 256   Gram S (16 x 16)
#define O_EF    12032    // 128   E (8x8) then F (8x8)
#define O_HVE   12160    // 1024  Hvest -> later H_new
#define O_W     13184    // 2048  W (128 x 16)
#define O_WTW   15232    // 256
#define O_CHUNK 15488    // 2080  chunk buffer (max of 16x130 and 16x128)
#define O_UT    17568    // 128   rUt(64) iUt(64)
#define SMEM_FLOATS 17696   // 70784 bytes

__global__ void batch_kernel(
    const float* __restrict__ sigma2, const float* __restrict__ X,
    const float* __restrict__ XXp, const float* __restrict__ Y,
    const float* __restrict__ YYp, const float* __restrict__ H,
    const float* __restrict__ lambda_W,
    const float* __restrict__ rUt, const float* __restrict__ iUt,
    const float* __restrict__ tao_p, const float* __restrict__ eps_p,
    const float* __restrict__ factor_p,
    float* __restrict__ out_Hnew, float* __restrict__ out_lamW)
{
    extern __shared__ float sm[];
    float* sXXp = sm + O_XXP;
    float* sUtXT = sm + O_UTXT;
    float* sHG  = sm + O_HG;
    float* sT   = sm + O_T;
    float* sHv  = sm + O_HV;
    float* sS   = sm + O_S;
    float* sEF  = sm + O_EF;
    float* sHve = sm + O_HVE;
    float* sW   = sm + O_W;
    float* sWTW = sm + O_WTW;
    float* sCh  = sm + O_CHUNK;
    float* sUt  = sm + O_UT;

    const int b = blockIdx.x;
    const int tid = threadIdx.x;
    const float tao = tao_p[0];

    // ---- A: load XXp, H (into sHG cols 0..7), Ut ----
    const float* XXpb = XXp + (size_t)b * 16 * LT;
    for (int i = tid; i < 16 * LT; i += NTH) sXXp[i] = XXpb[i];
    const float* Hb = H + (size_t)b * 128 * 8;
    for (int e = tid; e < 1024; e += NTH) {
        int k = e >> 3, c = e & 7;
        sHG[k * 24 + c] = Hb[e];
    }
    if (tid < 128) sUt[tid] = (tid < 64) ? rUt[tid] : iUt[tid - 64];
    __syncthreads();

    // ---- B: UtXT[l][i] = (UtT @ XXp)[i][l] ----
    for (int e = tid; e < 16 * LT; e += NTH) {
        int i = e & 15, l = e >> 4;
        float acc = 0.f;
        if (i < 8) {
            #pragma unroll
            for (int k = 0; k < 8; k++) {
                acc += sUt[k * 8 + i] * sXXp[k * LT + l];
                acc += sUt[64 + k * 8 + i] * sXXp[(8 + k) * LT + l];
            }
        } else {
            int i2 = i - 8;
            #pragma unroll
            for (int k = 0; k < 8; k++) {
                acc -= sUt[64 + k * 8 + i2] * sXXp[k * LT + l];
                acc += sUt[k * 8 + i2] * sXXp[(8 + k) * LT + l];
            }
        }
        sUtXT[l * 16 + i] = acc;
    }
    __syncthreads();

    // ---- C: Gram S[i][j] = sum_l UtX[i][l]*UtX[j][l] ----
    {
        int i = tid >> 4, j = tid & 15;
        float acc = 0.f;
        #pragma unroll 4
        for (int l = 0; l < LT; l++) acc += sUtXT[l * 16 + i] * sUtXT[l * 16 + j];
        sS[tid] = acc;
    }
    __syncthreads();

    // ---- C2: E = S00+S11, F = S01-S10 ----
    if (tid < 128) {
        int q = tid & 63, k = q >> 3, t = q & 7;
        if (tid < 64) sEF[tid] = sS[k * 16 + t] + sS[(8 + k) * 16 + 8 + t];
        else          sEF[tid] = sS[k * 16 + 8 + t] - sS[(8 + k) * 16 + t];
    }
    // (covered by the sync inside the first chunk iteration below)

    // ---- E: G_re = YYp @ rex^T, G_im = YYp @ imx^T  (chunked over l) ----
    {
        const float* YYpb = YYp + (size_t)b * 128 * LT;
        const int krow = tid >> 1, sel = tid & 1;
        float acc[8] = {};
        for (int lc = 0; lc < 9; lc++) {
            int l0 = lc * 16;
            // load chunk: sCh[j][k] with pad 130
            for (int e = tid; e < 2048; e += NTH) {
                int kk = e >> 4, j = e & 15;
                sCh[j * 130 + kk] = YYpb[kk * LT + l0 + j];
            }
            __syncthreads();
            #pragma unroll
            for (int j = 0; j < 16; j++) {
                float y = sCh[j * 130 + krow];
                int l = l0 + j;
                float4 u0 = *(const float4*)&sUtXT[l * 16 + sel * 8];
                float4 u1 = *(const float4*)&sUtXT[l * 16 + sel * 8 + 4];
                acc[0] += y * u0.x; acc[1] += y * u0.y; acc[2] += y * u0.z; acc[3] += y * u0.w;
                acc[4] += y * u1.x; acc[5] += y * u1.y; acc[6] += y * u1.z; acc[7] += y * u1.w;
            }
            __syncthreads();
        }
        #pragma unroll
        for (int t = 0; t < 8; t++) sHG[krow * 24 + 8 + sel * 8 + t] = acc[t];
    }
    __syncthreads();

    // ---- F: sT = UrT @ [H | G_re | G_im]   (128x24, k=128) ----
    // UrT[r][k] = g_Ur[k*128 + r]  (coalesced)
    {
        const int r = tid >> 1, c0 = (tid & 1) * 12;
        float acc[12] = {};
        #pragma unroll 4
        for (int k = 0; k < 128; k++) {
            float w = g_Ur[k * 128 + r];
            float4 h0 = *(const float4*)&sHG[k * 24 + c0];
            float4 h1 = *(const float4*)&sHG[k * 24 + c0 + 4];
            float4 h2 = *(const float4*)&sHG[k * 24 + c0 + 8];
            acc[0] += w * h0.x; acc[1] += w * h0.y; acc[2]  += w * h0.z; acc[3]  += w * h0.w;
            acc[4] += w * h1.x; acc[5] += w * h1.y; acc[6]  += w * h1.z; acc[7]  += w * h1.w;
            acc[8] += w * h2.x; acc[9] += w * h2.y; acc[10] += w * h2.z; acc[11] += w * h2.w;
        }
        #pragma unroll
        for (int q = 0; q < 12; q++) sT[r * 24 + c0 + q] = acc[q];
    }
    __syncthreads();

    // ---- G: Hv_temp (128x8) from UrH (= sT cols 0..7) ----
    {
        const int r = tid >> 1, c0 = (tid & 1) * 4;
        #pragma unroll
        for (int c = c0; c < c0 + 4; c++) {
            float acc = 0.f;
            if (r < 64) {
                #pragma unroll
                for (int k = 0; k < 8; k++)
                    acc += sT[r * 24 + k] * sUt[k * 8 + c] - sT[(64 + r) * 24 + k] * sUt[64 + k * 8 + c];
            } else {
                #pragma unroll
                for (int k = 0; k < 8; k++)
                    acc += sT[r * 24 + k] * sUt[k * 8 + c] + sT[(r - 64) * 24 + k] * sUt[64 + k * 8 + c];
            }
            sHv[r * 8 + c] = acc;
        }
    }
    __syncthreads();

    // ---- H: D and Hvest ----
    {
        const int r = tid >> 1, t0 = (tid & 1) * 4;
        #pragma unroll
        for (int t = t0; t < t0 + 4; t++) {
            float s = 0.f;
            if (r < 64) {
                #pragma unroll
                for (int k = 0; k < 8; k++)
                    s += sHv[r * 8 + k] * sEF[k * 8 + t] + sHv[(64 + r) * 8 + k] * sEF[64 + k * 8 + t];
                s -= sT[r * 24 + 8 + t] + sT[(64 + r) * 24 + 16 + t];
            } else {
                int r2 = r - 64;
                #pragma unroll
                for (int k = 0; k < 8; k++)
                    s += sHv[r * 8 + k] * sEF[k * 8 + t] - sHv[r2 * 8 + k] * sEF[64 + k * 8 + t];
                s -= sT[r * 24 + 8 + t] - sT[r2 * 24 + 16 + t];
            }
            sHve[r * 8 + t] = sHv[r * 8 + t] - tao * s;
        }
    }
    __syncthreads();

    // ---- I: soft threshold ----
    {
        float thr = tao * eps_p[0] * sigma2[b];
        for (int e = tid; e < 512; e += NTH) {
            float re = sHve[e], im = sHve[e + 512];
            float mag = sqrtf(re * re + im * im);
            float s = fmaxf(mag - thr, 0.f) / mag;
            sHve[e] = re * s;
            sHve[e + 512] = im * s;
        }
    }
    __syncthreads();

    // ---- J: UrHv = Ur @ Hvest  (Ur[r][k] = g_UrT[k*128+r]) -> sHv ----
    {
        const int r = tid >> 1, c0 = (tid & 1) * 4;
        float acc[4] = {};
        #pragma unroll 4
        for (int k = 0; k < 128; k++) {
            float w = g_UrT[k * 128 + r];
            float4 h = *(const float4*)&sHve[k * 8 + c0];
            acc[0] += w * h.x; acc[1] += w * h.y; acc[2] += w * h.z; acc[3] += w * h.w;
        }
        __syncthreads();   // everyone done reading sHv before overwrite
        #pragma unroll
        for (int q = 0; q < 4; q++) sHv[r * 8 + c0 + q] = acc[q];
    }
    __syncthreads();

    // ---- K: H_new = blkb(UrHv) @ UtT2 -> sHve + gmem ----
    {
        const int r = tid >> 1, c0 = (tid & 1) * 4;
        #pragma unroll
        for (int c = c0; c < c0 + 4; c++) {
            float acc = 0.f;
            if (r < 64) {
                #pragma unroll
                for (int k = 0; k < 8; k++)
                    acc += sHv[r * 8 + k] * sUt[c * 8 + k] + sHv[(64 + r) * 8 + k] * sUt[64 + c * 8 + k];
            } else {
                #pragma unroll
                for (int k = 0; k < 8; k++)
                    acc += sHv[r * 8 + k] * sUt[c * 8 + k] - sHv[(r - 64) * 8 + k] * sUt[64 + c * 8 + k];
            }
            sHve[r * 8 + c] = acc;
            out_Hnew[(size_t)b * 1024 + r * 8 + c] = acc;
        }
    }
    __syncthreads();

    // ---- L: W = blkb(H_new) (128 x 16) ----
    for (int e = tid; e < 2048; e += NTH) {
        int r = e >> 4, i = e & 15;
        float v;
        if (r < 64) v = (i < 8) ? sHve[r * 8 + i] : -sHve[(64 + r) * 8 + (i - 8)];
        else        v = (i < 8) ? sHve[r * 8 + i] : sHve[(r - 64) * 8 + (i - 8)];
        sW[e] = v;
    }
    __syncthreads();

    // ---- L2: WTW ----
    {
        int i = tid >> 4, j = tid & 15;
        float acc = 0.f;
        #pragma unroll 4
        for (int r = 0; r < 128; r++) acc += sW[r * 16 + i] * sW[r * 16 + j];
        sWTW[tid] = acc;
    }
    __syncthreads();

    // ---- M: F = W^T Y + lamW*X - WTW@X  -> g_F ----
    {
        float lamW = factor_p[0] * lambda_W[b];
        const float* Yb = Y + (size_t)b * 128 * LD;
        const float* Xb = X + (size_t)b * 16 * LD;
        float* Fb = g_F + (size_t)b * 16 * LD;
        const int l = tid & 127, ih = tid >> 7;
        float acc[8] = {};
        for (int rc = 0; rc < 8; rc++) {
            for (int e = tid; e < 2048; e += NTH) {
                int r = e >> 7, ll = e & 127;
                sCh[r * 128 + ll] = Yb[(rc * 16 + r) * 128 + ll];
            }
            __syncthreads();
            #pragma unroll
            for (int r = 0; r < 16; r++) {
                float y = sCh[r * 128 + l];
                float4 w0 = *(const float4*)&sW[(rc * 16 + r) * 16 + ih * 8];
                float4 w1 = *(const float4*)&sW[(rc * 16 + r) * 16 + ih * 8 + 4];
                acc[0] += w0.x * y; acc[1] += w0.y * y; acc[2] += w0.z * y; acc[3] += w0.w * y;
                acc[4] += w1.x * y; acc[5] += w1.y * y; acc[6] += w1.z * y; acc[7] += w1.w * y;
            }
            __syncthreads();
        }
        float xv[16];
        #pragma unroll
        for (int j = 0; j < 16; j++) xv[j] = Xb[j * 128 + l];
        #pragma unroll
        for (int q = 0; q < 8; q++) {
            int i = ih * 8 + q;
            float v = acc[q] + lamW * xv[i];
            #pragma unroll
            for (int j = 0; j < 16; j++) v -= sWTW[i * 16 + j] * xv[j];
            Fb[i * 128 + l] = v;
        }
        if (tid == 0) out_lamW[b] = lamW;
    }
}

// ================= GEMM1: T1 = A^T V ; epilogue -> u_new =================
// C[n, b], n0..n0+63, b0..b0+63; 128 threads, 8x4 microtile
__global__ void gemm1_kernel(const float* __restrict__ A, const float* __restrict__ Lambda_A,
                             const float* __restrict__ lambda_W, const float* __restrict__ rho_p,
                             const float* __restrict__ kappa_p, const float* __restrict__ factor_p,
                             float* __restrict__ out_u)
{
    __shared__ float As[16 * 64];   // [k][n]
    __shared__ float Bs[16 * 68];   // [k][b] padded
    int n0 = blockIdx.x * 64, b0 = blockIdx.y * 64;
    int tid = threadIdx.x;
    int tx = tid & 7, ty = tid >> 3;
    float c[8][4] = {};
    float ra[8], rb[8];
    #pragma unroll
    for (int q = 0; q < 8; q++) {
        int e = tid + 128 * q;
        ra[q] = A[(size_t)(e >> 6) * NN + n0 + (e & 63)];
        rb[q] = g_Vs[(size_t)(b0 + (e >> 4)) * MM + (e & 15)];
    }
    for (int ch = 0; ch < 64; ch++) {
        #pragma unroll
        for (int q = 0; q < 8; q++) {
            int e = tid + 128 * q;
            As[(e >> 6) * 64 + (e & 63)] = ra[q];
            Bs[(e & 15) * 68 + (e >> 4)] = rb[q];
        }
        __syncthreads();
        if (ch < 63) {
            int mk = (ch + 1) * 16;
            #pragma unroll
            for (int q = 0; q < 8; q++) {
                int e = tid + 128 * q;
                ra[q] = A[(size_t)(mk + (e >> 6)) * NN + n0 + (e & 63)];
                rb[q] = g_Vs[(size_t)(b0 + (e >> 4)) * MM + mk + (e & 15)];
            }
        }
        #pragma unroll
        for (int kk = 0; kk < 16; kk++) {
            float4 a0 = *(const float4*)&As[kk * 64 + tx * 8];
            float4 a1 = *(const float4*)&As[kk * 64 + tx * 8 + 4];
            float4 bv = *(const float4*)&Bs[kk * 68 + ty * 4];
            float av[8] = {a0.x, a0.y, a0.z, a0.w, a1.x, a1.y, a1.z, a1.w};
            float bb[4] = {bv.x, bv.y, bv.z, bv.w};
            #pragma unroll
            for (int qi = 0; qi < 8; qi++)
                #pragma unroll
                for (int qj = 0; qj < 4; qj++)
                    c[qi][qj] += av[qi] * bb[qj];
        }
        __syncthreads();
    }
    float rho = rho_p[0], kappa = kappa_p[0], factor = factor_p[0];
    #pragma unroll
    for (int qi = 0; qi < 8; qi++) {
        int n = n0 + tx * 8 + qi;
        int l = n >> 4, t = (n >> 1) & 7, ci = n & 1;
        float la = Lambda_A[n];
        #pragma unroll
        for (int qj = 0; qj < 4; qj++) {
            int b = b0 + ty * 4 + qj;
            float lamW = factor * lambda_W[b];
            float fbres = 2.f * lamW - 2.f * SQ2F * g_F[(size_t)b * NN + (ci * 8 + t) * LD + l];
            float qv = rho * c[qi][qj] + fbres - kappa;
            float w = 1.f / (rho * la + 4.f * lamW - 2.f * kappa);
            float u = qv * w;
            u = fminf(fmaxf(u, 0.f), 1.f);
            out_u[(size_t)b * NN + n] = u;
        }
    }
}

// ================= GEMM2: Au = A u_new ; epilogue -> z_new, lambda1_new =================
// C[m, b]; 128 threads, 8x4 microtile
__global__ void gemm2_kernel(const float* __restrict__ A, const float* __restrict__ u_new,
                             const float* __restrict__ theta, const float* __restrict__ z_old,
                             const float* __restrict__ l1_old, const float* __restrict__ relax_p,
                             const float* __restrict__ acc_p,
                             float* __restrict__ out_z, float* __restrict__ out_l1)
{
    __shared__ float As[16 * 68];   // [k][m] padded
    __shared__ float Bs[16 * 68];   // [k][b] padded
    int m0 = blockIdx.x * 64, b0 = blockIdx.y * 64;
    int tid = threadIdx.x;
    int tx = tid & 7, ty = tid >> 3;
    float c[8][4] = {};
    float ra[8], rb[8];
    #pragma unroll
    for (int q = 0; q < 8; q++) {
        int e = tid + 128 * q;
        ra[q] = A[(size_t)(m0 + (e >> 4)) * NN + (e & 15)];
        rb[q] = u_new[(size_t)(b0 + (e >> 4)) * NN + (e & 15)];
    }
    for (int ch = 0; ch < 128; ch++) {
        #pragma unroll
        for (int q = 0; q < 8; q++) {
            int e = tid + 128 * q;
            As[(e & 15) * 68 + (e >> 4)] = ra[q];
            Bs[(e & 15) * 68 + (e >> 4)] = rb[q];
        }
        __syncthreads();
        if (ch < 127) {
            int nk = (ch + 1) * 16;
            #pragma unroll
            for (int q = 0; q < 8; q++) {
                int e = tid + 128 * q;
                ra[q] = A[(size_t)(m0 + (e >> 4)) * NN + nk + (e & 15)];
                rb[q] = u_new[(size_t)(b0 + (e >> 4)) * NN + nk + (e & 15)];
            }
        }
        #pragma unroll
        for (int kk = 0; kk < 16; kk++) {
            float4 a0 = *(const float4*)&As[kk * 68 + tx * 8];
            float4 a1 = *(const float4*)&As[kk * 68 + tx * 8 + 4];
            float4 bv = *(const float4*)&Bs[kk * 68 + ty * 4];
            float av[8] = {a0.x, a0.y, a0.z, a0.w, a1.x, a1.y, a1.z, a1.w};
            float bb[4] = {bv.x, bv.y, bv.z, bv.w};
            #pragma unroll
            for (int qi = 0; qi < 8; qi++)
                #pragma unroll
                for (int qj = 0; qj < 4; qj++)
                    c[qi][qj] += av[qi] * bb[qj];
        }
        __syncthreads();
    }
    float relax = relax_p[0], acc = acc_p[0];
    #pragma unroll
    for (int qi = 0; qi < 8; qi++) {
        int m = m0 + tx * 8 + qi;
        float th = theta[m];
        #pragma unroll
        for (int qj = 0; qj < 4; qj++) {
            int b = b0 + ty * 4 + qj;
            float zo = z_old[(size_t)b * MM + m];
            float lo = l1_old[(size_t)b * MM + m];
            float ztemp = th - relax * c[qi][qj] - (1.f - relax) * (th - zo) - lo;
            float zn = fmaxf(ztemp, 0.f);
            float ln = zn - ztemp;
            out_z[(size_t)b * MM + m] = zn + acc * (zn - zo);
            out_l1[(size_t)b * MM + m] = ln + acc * (ln - lo);
        }
    }
}

// ================= K4: X_new / XXp_new / acc_new =================
__global__ void x_kernel(const float* __restrict__ u_new, const float* __restrict__ rXp,
                         const float* __restrict__ iXp, const float* __restrict__ accnew_in,
                         float* __restrict__ out_X, float* __restrict__ out_XXp,
                         float* __restrict__ out_acc)
{
    int e = blockIdx.x * blockDim.x + threadIdx.x;
    const int total = BSZ * 16 * LT;
    if (e < total) {
        int b = e / (16 * LT);
        int rem = e - b * (16 * LT);
        int row = rem / LT, l = rem - row * LT;
        int t = row & 7, ci = row >> 3;
        float v;
        if (l < LD) {
            float u = u_new[(size_t)b * NN + l * 16 + t * 2 + ci];
            v = (1.f - 2.f * u) / SQ2F;
            out_X[(size_t)b * 16 * LD + row * LD + l] = v;
        } else {
            int lp = l - LD;
            v = (ci == 0) ? rXp[(size_t)b * NT * LP + t * LP + lp]
                          : iXp[(size_t)b * NT * LP + t * LP + lp];
        }
        out_XXp[e] = v;
    }
    if (e == 0) out_acc[0] = accnew_in[0];
}

// ================= launch =================
extern "C" void kernel_launch(void* const* d_in, const int* in_sizes, int n_in,
                              void* d_out, int out_size) {
    (void)in_sizes; (void)n_in; (void)out_size;
    const float* sigma2   = (const float*)d_in[0];
    const float* X        = (const float*)d_in[1];
    const float* XXp      = (const float*)d_in[2];
    const float* Y        = (const float*)d_in[3];
    const float* YYp      = (const float*)d_in[4];
    const float* rXp      = (const float*)d_in[5];
    const float* iXp      = (const float*)d_in[6];
    const float* H        = (const float*)d_in[7];
    const float* lambda_W = (const float*)d_in[8];
    const float* z        = (const float*)d_in[10];
    const float* lambda1  = (const float*)d_in[11];
    const float* acc_new  = (const float*)d_in[12];
    const float* A        = (const float*)d_in[13];
    const float* Lambda_A = (const float*)d_in[14];
    const float* theta    = (const float*)d_in[15];
    const float* rUr      = (const float*)d_in[16];
    const float* iUr      = (const float*)d_in[17];
    const float* rUt      = (const float*)d_in[18];
    const float* iUt      = (const float*)d_in[19];
    const float* rho      = (const float*)d_in[20];
    const float* kappa    = (const float*)d_in[21];
    const float* epsilon  = (const float*)d_in[22];
    const float* tao      = (const float*)d_in[23];
    const float* factor   = (const float*)d_in[24];
    const float* relax    = (const float*)d_in[25];
    const float* acc      = (const float*)d_in[26];

    float* out = (float*)d_out;
    float* out_X    = out;                // 512*16*128 = 1048576
    float* out_XXp  = out + 1048576;      // 512*16*144 = 1179648
    float* out_H    = out + 2228224;      // 512*128*8  = 524288
    float* out_lamW = out + 2752512;      // 512
    float* out_u    = out + 2753024;      // 512*2048   = 1048576
    float* out_z    = out + 3801600;      // 512*1024   = 524288
    float* out_l1   = out + 4325888;      // 512*1024   = 524288
    float* out_acc  = out + 4850176;      // 1

    cudaFuncSetAttribute(batch_kernel, cudaFuncAttributeMaxDynamicSharedMemorySize,
                         SMEM_FLOATS * sizeof(float));

    const_kernel<<<64, 256>>>(rUr, iUr);
    v_kernel<<<(BSZ * MM + 255) / 256, 256>>>(theta, z, lambda1);
    batch_kernel<<<BSZ, NTH, SMEM_FLOATS * sizeof(float)>>>(
        sigma2, X, XXp, Y, YYp, H, lambda_W, rUt, iUt, tao, epsilon, factor,
        out_H, out_lamW);
    {
        dim3 g(NN / 64, BSZ / 64);
        gemm1_kernel<<<g, 128>>>(A, Lambda_A, lambda_W, rho, kappa, factor, out_u);
    }
    {
        dim3 g(MM / 64, BSZ / 64);
        gemm2_kernel<<<g, 128>>>(A, out_u, theta, z, lambda1, relax, acc, out_z, out_l1);
    }
    x_kernel<<<(BSZ * 16 * LT + 255) / 256, 256>>>(out_u, rXp, iXp, acc_new,
                                                   out_X, out_XXp, out_acc);
}

// round 4
// speedup vs baseline: 4.5472x; 1.4525x over previous
#include <cuda_runtime.h>
#include <cuda_bf16.h>
#include <math.h>
#include <stdint.h>

// Problem constants
#define NR 64
#define NT 8
#define LD 128
#define LP 16
#define LT 144          // LD + LP
#define BSZ 512
#define MM 1024
#define NN 2048         // LDPC_N
#define NTH 256

#define SQ2F 1.41421356237309504880f

// -------- scratch (device globals; no runtime allocation) --------
__device__ float g_Ur[128 * 128];    // Ur[i][j]
__device__ float g_UrT[128 * 128];   // UrT[i][j]
__device__ float g_F[BSZ * NN];      // fbres permuted: [b][n]
__device__ float g_Vs[BSZ * MM];     // theta - z - lambda1, (B,1024)
__device__ float g_AT[NN * MM];      // A^T : [n][m]

// ================= mma.sync helpers =================
__device__ __forceinline__ uint32_t smem_to_u32(const void* smem_ptr) {
    uint32_t addr;
    asm("{ .reg .u64 tmp; cvta.to.shared.u64 tmp, %1; cvt.u32.u64 %0, tmp; }"
        : "=r"(addr) : "l"(smem_ptr));
    return addr;
}

__device__ __forceinline__ void cp16(uint32_t s, const float* g) {
    asm volatile("cp.async.cg.shared.global [%0], [%1], 16;" :: "r"(s), "l"(g) : "memory");
}
#define CP_COMMIT() asm volatile("cp.async.commit_group;" ::: "memory")
#define CP_WAIT1()  asm volatile("cp.async.wait_group 1;" ::: "memory")
#define CP_WAIT0()  asm volatile("cp.async.wait_group 0;" ::: "memory")

__device__ __forceinline__ uint32_t f2tf(float f) {
    uint32_t r;
    asm("cvt.rna.tf32.f32 %0, %1;" : "=r"(r) : "f"(f));
    return r;
}

__device__ __forceinline__ void mma_tf32(float* c, const uint32_t* a, const uint32_t* b) {
    asm volatile(
        "mma.sync.aligned.m16n8k8.row.col.f32.tf32.tf32.f32 "
        "{%0,%1,%2,%3}, {%4,%5,%6,%7}, {%8,%9}, {%0,%1,%2,%3};"
        : "+f"(c[0]), "+f"(c[1]), "+f"(c[2]), "+f"(c[3])
        : "r"(a[0]), "r"(a[1]), "r"(a[2]), "r"(a[3]), "r"(b[0]), "r"(b[1]));
}

// ---- shared tile mainloop: C[64x64] += P_tile[64,K] * Q_tile[64,K]^T ----
// 128 threads (4 warps, 2x2 of 32x32). smem tiles [2][64][20] (pad row=20 floats).
#define TILE_F (64 * 20)
__device__ __forceinline__ void tile_gemm(const float* __restrict__ Pg0,
                                          const float* __restrict__ Qg0,
                                          int K, float c[2][4][4],
                                          float* sP, float* sQ)
{
    const int tid = threadIdx.x;
    const int lane = tid & 31, wid = tid >> 5;
    const int wm = wid & 1, wn = wid >> 1;
    const int lrow = tid >> 2, lquad = tid & 3;

    uint32_t sPb = smem_to_u32(sP), sQb = smem_to_u32(sQ);
    const int NK = K >> 4;
    const float* Pg = Pg0 + (size_t)lrow * K + lquad * 4;
    const float* Qg = Qg0 + (size_t)lrow * K + lquad * 4;
    const uint32_t spA0 = sPb + (uint32_t)(lrow * 20 + lquad * 4) * 4;
    const uint32_t spA1 = sPb + (uint32_t)((lrow + 32) * 20 + lquad * 4) * 4;
    const uint32_t sqA0 = sQb + (uint32_t)(lrow * 20 + lquad * 4) * 4;
    const uint32_t sqA1 = sQb + (uint32_t)((lrow + 32) * 20 + lquad * 4) * 4;

    // prologue: stage 0, 1
    {
        const float* p = Pg;  const float* q = Qg;
        cp16(spA0, p); cp16(spA1, p + (size_t)32 * K);
        cp16(sqA0, q); cp16(sqA1, q + (size_t)32 * K);
        CP_COMMIT();
        p = Pg + 16; q = Qg + 16;
        uint32_t off = TILE_F * 4;
        cp16(spA0 + off, p); cp16(spA1 + off, p + (size_t)32 * K);
        cp16(sqA0 + off, q); cp16(sqA1 + off, q + (size_t)32 * K);
        CP_COMMIT();
    }

    const int arow = lane >> 2, acol = lane & 3;
    for (int kt = 0; kt < NK; kt++) {
        CP_WAIT1();
        __syncthreads();
        const float* Pbuf = sP + (kt & 1) * TILE_F;
        const float* Qbuf = sQ + (kt & 1) * TILE_F;
        #pragma unroll
        for (int ks = 0; ks < 2; ks++) {
            const int k0 = ks * 8 + acol;
            uint32_t a[2][4], bq[4][2];
            #pragma unroll
            for (int mt = 0; mt < 2; mt++) {
                const int m = wm * 32 + mt * 16 + arow;
                a[mt][0] = f2tf(Pbuf[m * 20 + k0]);
                a[mt][1] = f2tf(Pbuf[(m + 8) * 20 + k0]);
                a[mt][2] = f2tf(Pbuf[m * 20 + k0 + 4]);
                a[mt][3] = f2tf(Pbuf[(m + 8) * 20 + k0 + 4]);
            }
            #pragma unroll
            for (int nt = 0; nt < 4; nt++) {
                const int n = wn * 32 + nt * 8 + arow;
                bq[nt][0] = f2tf(Qbuf[n * 20 + k0]);
                bq[nt][1] = f2tf(Qbuf[n * 20 + k0 + 4]);
            }
            #pragma unroll
            for (int mt = 0; mt < 2; mt++)
                #pragma unroll
                for (int nt = 0; nt < 4; nt++)
                    mma_tf32(c[mt][nt], a[mt], bq[nt]);
        }
        __syncthreads();
        if (kt + 2 < NK) {
            uint32_t off = (uint32_t)((kt & 1) * TILE_F) * 4;
            const float* p = Pg + (kt + 2) * 16;
            const float* q = Qg + (kt + 2) * 16;
            cp16(spA0 + off, p); cp16(spA1 + off, p + (size_t)32 * K);
            cp16(sqA0 + off, q); cp16(sqA1 + off, q + (size_t)32 * K);
        }
        CP_COMMIT();
    }
    CP_WAIT0();
}

// ================= K0: build Ur / UrT =================
__global__ void const_kernel(const float* __restrict__ rUr, const float* __restrict__ iUr) {
    int e = blockIdx.x * blockDim.x + threadIdx.x;
    if (e >= 128 * 128) return;
    int i = e >> 7, j = e & 127;
    float v, vt;
    if (i < 64) v = (j < 64) ? rUr[i * 64 + j] : -iUr[i * 64 + (j - 64)];
    else        v = (j < 64) ? iUr[(i - 64) * 64 + j] : rUr[(i - 64) * 64 + (j - 64)];
    g_Ur[e] = v;
    if (i < 64) vt = (j < 64) ? rUr[j * 64 + i] : iUr[(j - 64) * 64 + i];
    else        vt = (j < 64) ? -iUr[j * 64 + (i - 64)] : rUr[(j - 64) * 64 + (i - 64)];
    g_UrT[e] = vt;
}

// ================= K_v: V = theta - z - lambda1 =================
__global__ void v_kernel(const float* __restrict__ theta, const float* __restrict__ z,
                         const float* __restrict__ l1) {
    int e = blockIdx.x * blockDim.x + threadIdx.x;
    if (e < BSZ * MM) {
        int m = e & (MM - 1);
        g_Vs[e] = theta[m] - z[e] - l1[e];
    }
}

// ================= K_at: g_AT[n][m] = A[m][n] =================
__global__ void at_kernel(const float* __restrict__ A) {
    __shared__ float t[32][33];
    int n0 = blockIdx.x * 32, m0 = blockIdx.y * 32;
    int tx = threadIdx.x, ty = threadIdx.y;
    #pragma unroll
    for (int q = 0; q < 4; q++)
        t[ty + 8 * q][tx] = A[(size_t)(m0 + ty + 8 * q) * NN + n0 + tx];
    __syncthreads();
    #pragma unroll
    for (int q = 0; q < 4; q++)
        g_AT[(size_t)(n0 + ty + 8 * q) * MM + m0 + tx] = t[tx][ty + 8 * q];
}

// ================= K1: per-batch chain =================
#define O_XXP   0
#define O_UTXT  2304
#define O_HG    4608
#define O_T     7680
#define O_HV    10752
#define O_S     11776
#define O_EF    12032
#define O_HVE   12160
#define O_W     13184
#define O_WTW   15232
#define O_CHUNK 15488
#define O_UT    17568
#define SMEM_FLOATS 17696

__global__ void batch_kernel(
    const float* __restrict__ sigma2, const float* __restrict__ X,
    const float* __restrict__ XXp, const float* __restrict__ Y,
    const float* __restrict__ YYp, const float* __restrict__ H,
    const float* __restrict__ lambda_W,
    const float* __restrict__ rUt, const float* __restrict__ iUt,
    const float* __restrict__ tao_p, const float* __restrict__ eps_p,
    const float* __restrict__ factor_p,
    float* __restrict__ out_Hnew, float* __restrict__ out_lamW)
{
    extern __shared__ float sm[];
    float* sXXp = sm + O_XXP;
    float* sUtXT = sm + O_UTXT;
    float* sHG  = sm + O_HG;
    float* sT   = sm + O_T;
    float* sHv  = sm + O_HV;
    float* sS   = sm + O_S;
    float* sEF  = sm + O_EF;
    float* sHve = sm + O_HVE;
    float* sW   = sm + O_W;
    float* sWTW = sm + O_WTW;
    float* sCh  = sm + O_CHUNK;
    float* sUt  = sm + O_UT;

    const int b = blockIdx.x;
    const int tid = threadIdx.x;
    const float tao = tao_p[0];

    const float* XXpb = XXp + (size_t)b * 16 * LT;
    for (int i = tid; i < 16 * LT; i += NTH) sXXp[i] = XXpb[i];
    const float* Hb = H + (size_t)b * 128 * 8;
    for (int e = tid; e < 1024; e += NTH) {
        int k = e >> 3, c = e & 7;
        sHG[k * 24 + c] = Hb[e];
    }
    if (tid < 128) sUt[tid] = (tid < 64) ? rUt[tid] : iUt[tid - 64];
    __syncthreads();

    for (int e = tid; e < 16 * LT; e += NTH) {
        int i = e & 15, l = e >> 4;
        float acc = 0.f;
        if (i < 8) {
            #pragma unroll
            for (int k = 0; k < 8; k++) {
                acc += sUt[k * 8 + i] * sXXp[k * LT + l];
                acc += sUt[64 + k * 8 + i] * sXXp[(8 + k) * LT + l];
            }
        } else {
            int i2 = i - 8;
            #pragma unroll
            for (int k = 0; k < 8; k++) {
                acc -= sUt[64 + k * 8 + i2] * sXXp[k * LT + l];
                acc += sUt[k * 8 + i2] * sXXp[(8 + k) * LT + l];
            }
        }
        sUtXT[l * 16 + i] = acc;
    }
    __syncthreads();

    {
        int i = tid >> 4, j = tid & 15;
        float acc = 0.f;
        #pragma unroll 4
        for (int l = 0; l < LT; l++) acc += sUtXT[l * 16 + i] * sUtXT[l * 16 + j];
        sS[tid] = acc;
    }
    __syncthreads();

    if (tid < 128) {
        int q = tid & 63, k = q >> 3, t = q & 7;
        if (tid < 64) sEF[tid] = sS[k * 16 + t] + sS[(8 + k) * 16 + 8 + t];
        else          sEF[tid] = sS[k * 16 + 8 + t] - sS[(8 + k) * 16 + t];
    }

    {
        const float* YYpb = YYp + (size_t)b * 128 * LT;
        const int krow = tid >> 1, sel = tid & 1;
        float acc[8] = {};
        for (int lc = 0; lc < 9; lc++) {
            int l0 = lc * 16;
            for (int e = tid; e < 2048; e += NTH) {
                int kk = e >> 4, j = e & 15;
                sCh[j * 130 + kk] = YYpb[kk * LT + l0 + j];
            }
            __syncthreads();
            #pragma unroll
            for (int j = 0; j < 16; j++) {
                float y = sCh[j * 130 + krow];
                int l = l0 + j;
                float4 u0 = *(const float4*)&sUtXT[l * 16 + sel * 8];
                float4 u1 = *(const float4*)&sUtXT[l * 16 + sel * 8 + 4];
                acc[0] += y * u0.x; acc[1] += y * u0.y; acc[2] += y * u0.z; acc[3] += y * u0.w;
                acc[4] += y * u1.x; acc[5] += y * u1.y; acc[6] += y * u1.z; acc[7] += y * u1.w;
            }
            __syncthreads();
        }
        #pragma unroll
        for (int t = 0; t < 8; t++) sHG[krow * 24 + 8 + sel * 8 + t] = acc[t];
    }
    __syncthreads();

    {
        const int r = tid >> 1, c0 = (tid & 1) * 12;
        float acc[12] = {};
        #pragma unroll 4
        for (int k = 0; k < 128; k++) {
            float w = g_Ur[k * 128 + r];
            float4 h0 = *(const float4*)&sHG[k * 24 + c0];
            float4 h1 = *(const float4*)&sHG[k * 24 + c0 + 4];
            float4 h2 = *(const float4*)&sHG[k * 24 + c0 + 8];
            acc[0] += w * h0.x; acc[1] += w * h0.y; acc[2]  += w * h0.z; acc[3]  += w * h0.w;
            acc[4] += w * h1.x; acc[5] += w * h1.y; acc[6]  += w * h1.z; acc[7]  += w * h1.w;
            acc[8] += w * h2.x; acc[9] += w * h2.y; acc[10] += w * h2.z; acc[11] += w * h2.w;
        }
        #pragma unroll
        for (int q = 0; q < 12; q++) sT[r * 24 + c0 + q] = acc[q];
    }
    __syncthreads();

    {
        const int r = tid >> 1, c0 = (tid & 1) * 4;
        #pragma unroll
        for (int c = c0; c < c0 + 4; c++) {
            float acc = 0.f;
            if (r < 64) {
                #pragma unroll
                for (int k = 0; k < 8; k++)
                    acc += sT[r * 24 + k] * sUt[k * 8 + c] - sT[(64 + r) * 24 + k] * sUt[64 + k * 8 + c];
            } else {
                #pragma unroll
                for (int k = 0; k < 8; k++)
                    acc += sT[r * 24 + k] * sUt[k * 8 + c] + sT[(r - 64) * 24 + k] * sUt[64 + k * 8 + c];
            }
            sHv[r * 8 + c] = acc;
        }
    }
    __syncthreads();

    {
        const int r = tid >> 1, t0 = (tid & 1) * 4;
        #pragma unroll
        for (int t = t0; t < t0 + 4; t++) {
            float s = 0.f;
            if (r < 64) {
                #pragma unroll
                for (int k = 0; k < 8; k++)
                    s += sHv[r * 8 + k] * sEF[k * 8 + t] + sHv[(64 + r) * 8 + k] * sEF[64 + k * 8 + t];
                s -= sT[r * 24 + 8 + t] + sT[(64 + r) * 24 + 16 + t];
            } else {
                int r2 = r - 64;
                #pragma unroll
                for (int k = 0; k < 8; k++)
                    s += sHv[r * 8 + k] * sEF[k * 8 + t] - sHv[r2 * 8 + k] * sEF[64 + k * 8 + t];
                s -= sT[r * 24 + 8 + t] - sT[r2 * 24 + 16 + t];
            }
            sHve[r * 8 + t] = sHv[r * 8 + t] - tao * s;
        }
    }
    __syncthreads();

    {
        float thr = tao * eps_p[0] * sigma2[b];
        for (int e = tid; e < 512; e += NTH) {
            float re = sHve[e], im = sHve[e + 512];
            float mag = sqrtf(re * re + im * im);
            float s = fmaxf(mag - thr, 0.f) / mag;
            sHve[e] = re * s;
            sHve[e + 512] = im * s;
        }
    }
    __syncthreads();

    {
        const int r = tid >> 1, c0 = (tid & 1) * 4;
        float acc[4] = {};
        #pragma unroll 4
        for (int k = 0; k < 128; k++) {
            float w = g_UrT[k * 128 + r];
            float4 h = *(const float4*)&sHve[k * 8 + c0];
            acc[0] += w * h.x; acc[1] += w * h.y; acc[2] += w * h.z; acc[3] += w * h.w;
        }
        __syncthreads();
        #pragma unroll
        for (int q = 0; q < 4; q++) sHv[r * 8 + c0 + q] = acc[q];
    }
    __syncthreads();

    {
        const int r = tid >> 1, c0 = (tid & 1) * 4;
        #pragma unroll
        for (int c = c0; c < c0 + 4; c++) {
            float acc = 0.f;
            if (r < 64) {
                #pragma unroll
                for (int k = 0; k < 8; k++)
                    acc += sHv[r * 8 + k] * sUt[c * 8 + k] + sHv[(64 + r) * 8 + k] * sUt[64 + c * 8 + k];
            } else {
                #pragma unroll
                for (int k = 0; k < 8; k++)
                    acc += sHv[r * 8 + k] * sUt[c * 8 + k] - sHv[(r - 64) * 8 + k] * sUt[64 + c * 8 + k];
            }
            sHve[r * 8 + c] = acc;
            out_Hnew[(size_t)b * 1024 + r * 8 + c] = acc;
        }
    }
    __syncthreads();

    for (int e = tid; e < 2048; e += NTH) {
        int r = e >> 4, i = e & 15;
        float v;
        if (r < 64) v = (i < 8) ? sHve[r * 8 + i] : -sHve[(64 + r) * 8 + (i - 8)];
        else        v = (i < 8) ? sHve[r * 8 + i] : sHve[(r - 64) * 8 + (i - 8)];
        sW[e] = v;
    }
    __syncthreads();

    {
        int i = tid >> 4, j = tid & 15;
        float acc = 0.f;
        #pragma unroll 4
        for (int r = 0; r < 128; r++) acc += sW[r * 16 + i] * sW[r * 16 + j];
        sWTW[tid] = acc;
    }
    __syncthreads();

    {
        float lamW = factor_p[0] * lambda_W[b];
        const float* Yb = Y + (size_t)b * 128 * LD;
        const float* Xb = X + (size_t)b * 16 * LD;
        float* Fb = g_F + (size_t)b * NN;
        const int l = tid & 127, ih = tid >> 7;
        float acc[8] = {};
        for (int rc = 0; rc < 8; rc++) {
            for (int e = tid; e < 2048; e += NTH) {
                int r = e >> 7, ll = e & 127;
                sCh[r * 128 + ll] = Yb[(rc * 16 + r) * 128 + ll];
            }
            __syncthreads();
            #pragma unroll
            for (int r = 0; r < 16; r++) {
                float y = sCh[r * 128 + l];
                float4 w0 = *(const float4*)&sW[(rc * 16 + r) * 16 + ih * 8];
                float4 w1 = *(const float4*)&sW[(rc * 16 + r) * 16 + ih * 8 + 4];
                acc[0] += w0.x * y; acc[1] += w0.y * y; acc[2] += w0.z * y; acc[3] += w0.w * y;
                acc[4] += w1.x * y; acc[5] += w1.y * y; acc[6] += w1.z * y; acc[7] += w1.w * y;
            }
            __syncthreads();
        }
        float xv[16];
        #pragma unroll
        for (int j = 0; j < 16; j++) xv[j] = Xb[j * 128 + l];
        #pragma unroll
        for (int q = 0; q < 8; q++) {
            int i = ih * 8 + q;
            float v = acc[q] + lamW * xv[i];
            #pragma unroll
            for (int j = 0; j < 16; j++) v -= sWTW[i * 16 + j] * xv[j];
            int n = l * 16 + (i & 7) * 2 + (i >> 3);
            Fb[n] = 2.f * lamW - 2.f * SQ2F * v;
        }
        if (tid == 0) out_lamW[b] = lamW;
    }
}

// ================= MMA GEMM1: C[b,n] = V[b,:]·AT[n,:]; epilogue -> u_new =================
__global__ __launch_bounds__(128)
void mma_gemm1(const float* __restrict__ La, const float* __restrict__ lamWv,
               const float* __restrict__ rho_p, const float* __restrict__ kappa_p,
               float* __restrict__ out_u)
{
    __shared__ float sP[2 * TILE_F];
    __shared__ float sQ[2 * TILE_F];
    const int n0 = blockIdx.x * 64, b0 = blockIdx.y * 64;
    float c[2][4][4] = {};
    tile_gemm(g_Vs + (size_t)b0 * MM, g_AT + (size_t)n0 * MM, MM, c, sP, sQ);

    const int lane = threadIdx.x & 31, wid = threadIdx.x >> 5;
    const int wm = wid & 1, wn = wid >> 1;
    const float rho = rho_p[0], kappa = kappa_p[0];
    #pragma unroll
    for (int mt = 0; mt < 2; mt++)
        #pragma unroll
        for (int rr = 0; rr < 2; rr++) {
            const int b = b0 + wm * 32 + mt * 16 + (lane >> 2) + rr * 8;
            const float lamW = lamWv[b];
            const float den = 4.f * lamW - 2.f * kappa;
            const float* gFb = g_F + (size_t)b * NN;
            float* uout = out_u + (size_t)b * NN;
            #pragma unroll
            for (int nt = 0; nt < 4; nt++) {
                const int n = n0 + wn * 32 + nt * 8 + (lane & 3) * 2;
                float2 fb = *(const float2*)(gFb + n);
                float la0 = La[n], la1 = La[n + 1];
                float c0 = c[mt][nt][rr * 2 + 0];
                float c1 = c[mt][nt][rr * 2 + 1];
                float u0 = (rho * c0 + fb.x - kappa) * (1.f / (rho * la0 + den));
                float u1 = (rho * c1 + fb.y - kappa) * (1.f / (rho * la1 + den));
                u0 = fminf(fmaxf(u0, 0.f), 1.f);
                u1 = fminf(fmaxf(u1, 0.f), 1.f);
                *(float2*)(uout + n) = make_float2(u0, u1);
            }
        }
}

// ================= MMA GEMM2: C[b,m] = u[b,:]·A[m,:]; epilogue -> z,l1 =================
__global__ __launch_bounds__(128)
void mma_gemm2(const float* __restrict__ A, const float* __restrict__ u_in,
               const float* __restrict__ theta, const float* __restrict__ z_old,
               const float* __restrict__ l1_old, const float* __restrict__ relax_p,
               const float* __restrict__ acc_p,
               float* __restrict__ out_z, float* __restrict__ out_l1)
{
    __shared__ float sP[2 * TILE_F];
    __shared__ float sQ[2 * TILE_F];
    const int m0 = blockIdx.x * 64, b0 = blockIdx.y * 64;
    float c[2][4][4] = {};
    tile_gemm(u_in + (size_t)b0 * NN, A + (size_t)m0 * NN, NN, c, sP, sQ);

    const int lane = threadIdx.x & 31, wid = threadIdx.x >> 5;
    const int wm = wid & 1, wn = wid >> 1;
    const float relax = relax_p[0], acc = acc_p[0];
    #pragma unroll
    for (int mt = 0; mt < 2; mt++)
        #pragma unroll
        for (int rr = 0; rr < 2; rr++) {
            const int b = b0 + wm * 32 + mt * 16 + (lane >> 2) + rr * 8;
            const float* zob = z_old + (size_t)b * MM;
            const float* lob = l1_old + (size_t)b * MM;
            float* zout = out_z + (size_t)b * MM;
            float* lout = out_l1 + (size_t)b * MM;
            #pragma unroll
            for (int nt = 0; nt < 4; nt++) {
                const int m = m0 + wn * 32 + nt * 8 + (lane & 3) * 2;
                float2 zo = *(const float2*)(zob + m);
                float2 lo = *(const float2*)(lob + m);
                float th0 = theta[m], th1 = theta[m + 1];
                float c0 = c[mt][nt][rr * 2 + 0];
                float c1 = c[mt][nt][rr * 2 + 1];
                float zt0 = th0 - relax * c0 - (1.f - relax) * (th0 - zo.x) - lo.x;
                float zt1 = th1 - relax * c1 - (1.f - relax) * (th1 - zo.y) - lo.y;
                float zn0 = fmaxf(zt0, 0.f), zn1 = fmaxf(zt1, 0.f);
                float ln0 = zn0 - zt0, ln1 = zn1 - zt1;
                *(float2*)(zout + m) = make_float2(zn0 + acc * (zn0 - zo.x),
                                                   zn1 + acc * (zn1 - zo.y));
                *(float2*)(lout + m) = make_float2(ln0 + acc * (ln0 - lo.x),
                                                   ln1 + acc * (ln1 - lo.y));
            }
        }
}

// ================= K4: X_new / XXp_new / acc_new =================
__global__ void x_kernel(const float* __restrict__ u_new, const float* __restrict__ rXp,
                         const float* __restrict__ iXp, const float* __restrict__ accnew_in,
                         float* __restrict__ out_X, float* __restrict__ out_XXp,
                         float* __restrict__ out_acc)
{
    int e = blockIdx.x * blockDim.x + threadIdx.x;
    const int total = BSZ * 16 * LT;
    if (e < total) {
        int b = e / (16 * LT);
        int rem = e - b * (16 * LT);
        int row = rem / LT, l = rem - row * LT;
        int t = row & 7, ci = row >> 3;
        float v;
        if (l < LD) {
            float u = u_new[(size_t)b * NN + l * 16 + t * 2 + ci];
            v = (1.f - 2.f * u) / SQ2F;
            out_X[(size_t)b * 16 * LD + row * LD + l] = v;
        } else {
            int lp = l - LD;
            v = (ci == 0) ? rXp[(size_t)b * NT * LP + t * LP + lp]
                          : iXp[(size_t)b * NT * LP + t * LP + lp];
        }
        out_XXp[e] = v;
    }
    if (e == 0) out_acc[0] = accnew_in[0];
}

// ================= launch =================
extern "C" void kernel_launch(void* const* d_in, const int* in_sizes, int n_in,
                              void* d_out, int out_size) {
    (void)in_sizes; (void)n_in; (void)out_size;
    const float* sigma2   = (const float*)d_in[0];
    const float* X        = (const float*)d_in[1];
    const float* XXp      = (const float*)d_in[2];
    const float* Y        = (const float*)d_in[3];
    const float* YYp      = (const float*)d_in[4];
    const float* rXp      = (const float*)d_in[5];
    const float* iXp      = (const float*)d_in[6];
    const float* H        = (const float*)d_in[7];
    const float* lambda_W = (const float*)d_in[8];
    const float* z        = (const float*)d_in[10];
    const float* lambda1  = (const float*)d_in[11];
    const float* acc_new  = (const float*)d_in[12];
    const float* A        = (const float*)d_in[13];
    const float* Lambda_A = (const float*)d_in[14];
    const float* theta    = (const float*)d_in[15];
    const float* rUr      = (const float*)d_in[16];
    const float* iUr      = (const float*)d_in[17];
    const float* rUt      = (const float*)d_in[18];
    const float* iUt      = (const float*)d_in[19];
    const float* rho      = (const float*)d_in[20];
    const float* kappa    = (const float*)d_in[21];
    const float* epsilon  = (const float*)d_in[22];
    const float* tao      = (const float*)d_in[23];
    const float* factor   = (const float*)d_in[24];
    const float* relax    = (const float*)d_in[25];
    const float* acc      = (const float*)d_in[26];

    float* out = (float*)d_out;
    float* out_X    = out;
    float* out_XXp  = out + 1048576;
    float* out_H    = out + 2228224;
    float* out_lamW = out + 2752512;
    float* out_u    = out + 2753024;
    float* out_z    = out + 3801600;
    float* out_l1   = out + 4325888;
    float* out_acc  = out + 4850176;

    cudaFuncSetAttribute(batch_kernel, cudaFuncAttributeMaxDynamicSharedMemorySize,
                         SMEM_FLOATS * sizeof(float));

    const_kernel<<<64, 256>>>(rUr, iUr);
    v_kernel<<<(BSZ * MM + 255) / 256, 256>>>(theta, z, lambda1);
    at_kernel<<<dim3(64, 32), dim3(32, 8)>>>(A);
    batch_kernel<<<BSZ, NTH, SMEM_FLOATS * sizeof(float)>>>(
        sigma2, X, XXp, Y, YYp, H, lambda_W, rUt, iUt, tao, epsilon, factor,
        out_H, out_lamW);
    mma_gemm1<<<dim3(NN / 64, BSZ / 64), 128>>>(Lambda_A, out_lamW, rho, kappa, out_u);
    mma_gemm2<<<dim3(MM / 64, BSZ / 64), 128>>>(A, out_u, theta, z, lambda1, relax, acc,
                                                out_z, out_l1);
    x_kernel<<<(BSZ * 16 * LT + 255) / 256, 256>>>(out_u, rXp, iXp, acc_new,
                                                   out_X, out_XXp, out_acc);
}

// round 6
// speedup vs baseline: 4.8517x; 1.0670x over previous
#include <cuda_runtime.h>
#include <cuda_bf16.h>
#include <math.h>
#include <stdint.h>

// Problem constants
#define NR 64
#define NT 8
#define LD 128
#define LP 16
#define LT 144          // LD + LP
#define BSZ 512
#define MM 1024
#define NN 2048         // LDPC_N

#define SQ2F 1.41421356237309504880f

// -------- scratch (device globals; no runtime allocation) --------
__device__ float g_Ur[128 * 128];     // Ur[i][j] row-major (k = j contiguous)
__device__ float g_UrT[128 * 128];    // UrT[i][j] row-major
__device__ float g_F[BSZ * NN];       // fbres permuted: [b][n]
__device__ float g_Vs[BSZ * MM];      // theta - z - lambda1
__device__ float g_AT[NN * MM];       // A^T
__device__ float g_HGT[BSZ * 24 * 128];   // per batch: HG^T  [c][k]
__device__ float g_T[BSZ * 24 * 128];     // T = UrT@HG stored [b][c][r]
__device__ float g_EF[BSZ * 128];         // E(64) then F(64) per batch
__device__ float g_HveT[BSZ * 8 * 128];   // Hvest^T [c][r]
__device__ float g_UrHvT[BSZ * 8 * 128];  // UrHv   [c][r]

// ================= mma.sync helpers =================
__device__ __forceinline__ uint32_t smem_to_u32(const void* smem_ptr) {
    uint32_t addr;
    asm("{ .reg .u64 tmp; cvta.to.shared.u64 tmp, %1; cvt.u32.u64 %0, tmp; }"
        : "=r"(addr) : "l"(smem_ptr));
    return addr;
}

__device__ __forceinline__ void cp16(uint32_t s, const float* g) {
    asm volatile("cp.async.cg.shared.global [%0], [%1], 16;" :: "r"(s), "l"(g) : "memory");
}
#define CP_COMMIT() asm volatile("cp.async.commit_group;" ::: "memory")
#define CP_WAIT1()  asm volatile("cp.async.wait_group 1;" ::: "memory")
#define CP_WAIT0()  asm volatile("cp.async.wait_group 0;" ::: "memory")

__device__ __forceinline__ uint32_t f2tf(float f) {
    uint32_t r;
    asm("cvt.rna.tf32.f32 %0, %1;" : "=r"(r) : "f"(f));
    return r;
}

__device__ __forceinline__ void mma_tf32(float* c, const uint32_t* a, const uint32_t* b) {
    asm volatile(
        "mma.sync.aligned.m16n8k8.row.col.f32.tf32.tf32.f32 "
        "{%0,%1,%2,%3}, {%4,%5,%6,%7}, {%8,%9}, {%0,%1,%2,%3};"
        : "+f"(c[0]), "+f"(c[1]), "+f"(c[2]), "+f"(c[3])
        : "r"(a[0]), "r"(a[1]), "r"(a[2]), "r"(a[3]), "r"(b[0]), "r"(b[1]));
}

// ---- shared tile mainloop: C[64x64] += P_tile[64,K] * Q_tile[64,K]^T ----
// 128 threads (4 warps, 2x2 of 32x32). smem tiles [2][64][20] (pad row=20 floats).
// PRECISE: 3xTF32 split (hi*hi + hi*lo + lo*hi) for ~fp32 accuracy.
#define TILE_F (64 * 20)
template<bool PRECISE>
__device__ __forceinline__ void tile_gemm(const float* __restrict__ Pg0,
                                          const float* __restrict__ Qg0,
                                          int K, float c[2][4][4],
                                          float* sP, float* sQ)
{
    const int tid = threadIdx.x;
    const int lane = tid & 31, wid = tid >> 5;
    const int wm = wid & 1, wn = wid >> 1;
    const int lrow = tid >> 2, lquad = tid & 3;

    uint32_t sPb = smem_to_u32(sP), sQb = smem_to_u32(sQ);
    const int NK = K >> 4;
    const float* Pg = Pg0 + (size_t)lrow * K + lquad * 4;
    const float* Qg = Qg0 + (size_t)lrow * K + lquad * 4;
    const uint32_t spA0 = sPb + (uint32_t)(lrow * 20 + lquad * 4) * 4;
    const uint32_t spA1 = sPb + (uint32_t)((lrow + 32) * 20 + lquad * 4) * 4;
    const uint32_t sqA0 = sQb + (uint32_t)(lrow * 20 + lquad * 4) * 4;
    const uint32_t sqA1 = sQb + (uint32_t)((lrow + 32) * 20 + lquad * 4) * 4;

    {
        const float* p = Pg;  const float* q = Qg;
        cp16(spA0, p); cp16(spA1, p + (size_t)32 * K);
        cp16(sqA0, q); cp16(sqA1, q + (size_t)32 * K);
        CP_COMMIT();
        p = Pg + 16; q = Qg + 16;
        uint32_t off = TILE_F * 4;
        cp16(spA0 + off, p); cp16(spA1 + off, p + (size_t)32 * K);
        cp16(sqA0 + off, q); cp16(sqA1 + off, q + (size_t)32 * K);
        CP_COMMIT();
    }

    const int arow = lane >> 2, acol = lane & 3;
    for (int kt = 0; kt < NK; kt++) {
        CP_WAIT1();
        __syncthreads();
        const float* Pbuf = sP + (kt & 1) * TILE_F;
        const float* Qbuf = sQ + (kt & 1) * TILE_F;
        #pragma unroll
        for (int ks = 0; ks < 2; ks++) {
            const int k0 = ks * 8 + acol;
            uint32_t a[2][4], bq[4][2];
            uint32_t al[2][4], bl[4][2];
            #pragma unroll
            for (int mt = 0; mt < 2; mt++) {
                const int m = wm * 32 + mt * 16 + arow;
                float v0 = Pbuf[m * 20 + k0];
                float v1 = Pbuf[(m + 8) * 20 + k0];
                float v2 = Pbuf[m * 20 + k0 + 4];
                float v3 = Pbuf[(m + 8) * 20 + k0 + 4];
                a[mt][0] = f2tf(v0); a[mt][1] = f2tf(v1);
                a[mt][2] = f2tf(v2); a[mt][3] = f2tf(v3);
                if (PRECISE) {
                    al[mt][0] = f2tf(v0 - __uint_as_float(a[mt][0]));
                    al[mt][1] = f2tf(v1 - __uint_as_float(a[mt][1]));
                    al[mt][2] = f2tf(v2 - __uint_as_float(a[mt][2]));
                    al[mt][3] = f2tf(v3 - __uint_as_float(a[mt][3]));
                }
            }
            #pragma unroll
            for (int nt = 0; nt < 4; nt++) {
                const int n = wn * 32 + nt * 8 + arow;
                float w0 = Qbuf[n * 20 + k0];
                float w1 = Qbuf[n * 20 + k0 + 4];
                bq[nt][0] = f2tf(w0); bq[nt][1] = f2tf(w1);
                if (PRECISE) {
                    bl[nt][0] = f2tf(w0 - __uint_as_float(bq[nt][0]));
                    bl[nt][1] = f2tf(w1 - __uint_as_float(bq[nt][1]));
                }
            }
            #pragma unroll
            for (int mt = 0; mt < 2; mt++)
                #pragma unroll
                for (int nt = 0; nt < 4; nt++) {
                    if (PRECISE) {
                        mma_tf32(c[mt][nt], a[mt], bl[nt]);
                        mma_tf32(c[mt][nt], al[mt], bq[nt]);
                    }
                    mma_tf32(c[mt][nt], a[mt], bq[nt]);
                }
        }
        __syncthreads();
        if (kt + 2 < NK) {
            uint32_t off = (uint32_t)((kt & 1) * TILE_F) * 4;
            const float* p = Pg + (kt + 2) * 16;
            const float* q = Qg + (kt + 2) * 16;
            cp16(spA0 + off, p); cp16(spA1 + off, p + (size_t)32 * K);
            cp16(sqA0 + off, q); cp16(sqA1 + off, q + (size_t)32 * K);
        }
        CP_COMMIT();
    }
    CP_WAIT0();
}

// ================= K0: build Ur / UrT =================
__global__ void const_kernel(const float* __restrict__ rUr, const float* __restrict__ iUr) {
    int e = blockIdx.x * blockDim.x + threadIdx.x;
    if (e >= 128 * 128) return;
    int i = e >> 7, j = e & 127;
    float v, vt;
    if (i < 64) v = (j < 64) ? rUr[i * 64 + j] : -iUr[i * 64 + (j - 64)];
    else        v = (j < 64) ? iUr[(i - 64) * 64 + j] : rUr[(i - 64) * 64 + (j - 64)];
    g_Ur[e] = v;
    if (i < 64) vt = (j < 64) ? rUr[j * 64 + i] : iUr[(j - 64) * 64 + i];
    else        vt = (j < 64) ? -iUr[j * 64 + (i - 64)] : rUr[(j - 64) * 64 + (i - 64)];
    g_UrT[e] = vt;
}

// ================= K_v: V = theta - z - lambda1 =================
__global__ void v_kernel(const float* __restrict__ theta, const float* __restrict__ z,
                         const float* __restrict__ l1) {
    int e = blockIdx.x * blockDim.x + threadIdx.x;
    if (e < BSZ * MM) {
        int m = e & (MM - 1);
        g_Vs[e] = theta[m] - z[e] - l1[e];
    }
}

// ================= K_at: g_AT[n][m] = A[m][n] =================
__global__ void at_kernel(const float* __restrict__ A) {
    __shared__ float t[32][33];
    int n0 = blockIdx.x * 32, m0 = blockIdx.y * 32;
    int tx = threadIdx.x, ty = threadIdx.y;
    #pragma unroll
    for (int q = 0; q < 4; q++)
        t[ty + 8 * q][tx] = A[(size_t)(m0 + ty + 8 * q) * NN + n0 + tx];
    __syncthreads();
    #pragma unroll
    for (int q = 0; q < 4; q++)
        g_AT[(size_t)(n0 + ty + 8 * q) * MM + m0 + tx] = t[tx][ty + 8 * q];
}

// ================= K1a: per-batch front phases -> g_HGT, g_EF =================
__global__ __launch_bounds__(256)
void k1a_kernel(const float* __restrict__ XXp, const float* __restrict__ YYp,
                const float* __restrict__ H,
                const float* __restrict__ rUt, const float* __restrict__ iUt)
{
    __shared__ float sXXp[16 * LT];
    __shared__ float sUtXT[LT * 16];
    __shared__ float sS[256];
    __shared__ float sCh[16 * 130];
    __shared__ float sUt[128];

    const int b = blockIdx.x;
    const int tid = threadIdx.x;

    const float* XXpb = XXp + (size_t)b * 16 * LT;
    for (int i = tid; i < 16 * LT; i += 256) sXXp[i] = XXpb[i];
    if (tid < 128) sUt[tid] = (tid < 64) ? rUt[tid] : iUt[tid - 64];
    __syncthreads();

    for (int e = tid; e < 16 * LT; e += 256) {
        int i = e & 15, l = e >> 4;
        float acc = 0.f;
        if (i < 8) {
            #pragma unroll
            for (int k = 0; k < 8; k++) {
                acc += sUt[k * 8 + i] * sXXp[k * LT + l];
                acc += sUt[64 + k * 8 + i] * sXXp[(8 + k) * LT + l];
            }
        } else {
            int i2 = i - 8;
            #pragma unroll
            for (int k = 0; k < 8; k++) {
                acc -= sUt[64 + k * 8 + i2] * sXXp[k * LT + l];
                acc += sUt[k * 8 + i2] * sXXp[(8 + k) * LT + l];
            }
        }
        sUtXT[l * 16 + i] = acc;
    }
    __syncthreads();

    {
        int i = tid >> 4, j = tid & 15;
        float acc = 0.f;
        #pragma unroll 4
        for (int l = 0; l < LT; l++) acc += sUtXT[l * 16 + i] * sUtXT[l * 16 + j];
        sS[tid] = acc;
    }
    __syncthreads();

    if (tid < 128) {
        int q = tid & 63, k = q >> 3, t = q & 7;
        float v;
        if (tid < 64) v = sS[k * 16 + t] + sS[(8 + k) * 16 + 8 + t];
        else          v = sS[k * 16 + 8 + t] - sS[(8 + k) * 16 + t];
        g_EF[(size_t)b * 128 + tid] = v;
    }

    {
        const float* Hb = H + (size_t)b * 1024;
        for (int e = tid; e < 1024; e += 256) {
            int k = e >> 3, c = e & 7;
            g_HGT[(size_t)b * 3072 + c * 128 + k] = Hb[e];
        }
    }

    {
        const float* YYpb = YYp + (size_t)b * 128 * LT;
        const int krow = tid >> 1, sel = tid & 1;
        float acc[8] = {};
        for (int lc = 0; lc < 9; lc++) {
            int l0 = lc * 16;
            for (int e = tid; e < 2048; e += 256) {
                int kk = e >> 4, j = e & 15;
                sCh[j * 130 + kk] = YYpb[kk * LT + l0 + j];
            }
            __syncthreads();
            #pragma unroll
            for (int j = 0; j < 16; j++) {
                float y = sCh[j * 130 + krow];
                int l = l0 + j;
                float4 u0 = *(const float4*)&sUtXT[l * 16 + sel * 8];
                float4 u1 = *(const float4*)&sUtXT[l * 16 + sel * 8 + 4];
                acc[0] += y * u0.x; acc[1] += y * u0.y; acc[2] += y * u0.z; acc[3] += y * u0.w;
                acc[4] += y * u1.x; acc[5] += y * u1.y; acc[6] += y * u1.z; acc[7] += y * u1.w;
            }
            __syncthreads();
        }
        #pragma unroll
        for (int t = 0; t < 8; t++)
            g_HGT[(size_t)b * 3072 + (8 + sel * 8 + t) * 128 + krow] = acc[t];
    }
}

// ================= mega GEMM (3xTF32 precise): Out[q][m0+p] = P[m0+p,:]·Q[q,:] =================
__global__ __launch_bounds__(128)
void mega_gemm(const float* __restrict__ P, const float* __restrict__ Q,
               float* __restrict__ Out)
{
    __shared__ float buf[4 * TILE_F];
    const int m0 = blockIdx.x * 64;
    const int q0 = blockIdx.y * 64;
    float c[2][4][4] = {};
    tile_gemm<true>(P + (size_t)m0 * 128, Q + (size_t)q0 * 128, 128, c, buf, buf + 2 * TILE_F);
    __syncthreads();

    const int tid = threadIdx.x;
    const int lane = tid & 31, wid = tid >> 5;
    const int wm = wid & 1, wn = wid >> 1;
    #pragma unroll
    for (int mt = 0; mt < 2; mt++)
        #pragma unroll
        for (int nt = 0; nt < 4; nt++)
            #pragma unroll
            for (int k = 0; k < 4; k++) {
                int p = wm * 32 + mt * 16 + (lane >> 2) + (k >> 1) * 8;
                int q = wn * 32 + nt * 8 + (lane & 3) * 2 + (k & 1);
                buf[p * 68 + q] = c[mt][nt][k];
            }
    __syncthreads();
    #pragma unroll 4
    for (int i = 0; i < 32; i++) {
        int idx = i * 128 + tid;
        int p = idx & 63, q = idx >> 6;
        Out[(size_t)(q0 + q) * 128 + m0 + p] = buf[p * 68 + q];
    }
}

// ================= K3: Hv, D, Hvest, soft-threshold -> g_HveT =================
__global__ __launch_bounds__(256)
void k3_kernel(const float* __restrict__ sigma2,
               const float* __restrict__ rUt, const float* __restrict__ iUt,
               const float* __restrict__ tao_p, const float* __restrict__ eps_p)
{
    __shared__ float sTc[24 * 128];
    __shared__ float sEF[128];
    __shared__ float sUt[128];
    __shared__ float sHv[1024];
    __shared__ float sHve[1024];

    const int b = blockIdx.x;
    const int tid = threadIdx.x;
    const float tao = tao_p[0];

    for (int i = tid; i < 3072; i += 256) sTc[i] = g_T[(size_t)b * 3072 + i];
    if (tid < 128) {
        sEF[tid] = g_EF[(size_t)b * 128 + tid];
        sUt[tid] = (tid < 64) ? rUt[tid] : iUt[tid - 64];
    }
    __syncthreads();

    {
        const int r = tid >> 1, c0 = (tid & 1) * 4;
        #pragma unroll
        for (int c = c0; c < c0 + 4; c++) {
            float acc = 0.f;
            if (r < 64) {
                #pragma unroll
                for (int k = 0; k < 8; k++)
                    acc += sTc[k * 128 + r] * sUt[k * 8 + c] - sTc[k * 128 + 64 + r] * sUt[64 + k * 8 + c];
            } else {
                #pragma unroll
                for (int k = 0; k < 8; k++)
                    acc += sTc[k * 128 + r] * sUt[k * 8 + c] + sTc[k * 128 + r - 64] * sUt[64 + k * 8 + c];
            }
            sHv[r * 8 + c] = acc;
        }
    }
    __syncthreads();

    {
        const int r = tid >> 1, t0 = (tid & 1) * 4;
        #pragma unroll
        for (int t = t0; t < t0 + 4; t++) {
            float s = 0.f;
            if (r < 64) {
                #pragma unroll
                for (int k = 0; k < 8; k++)
                    s += sHv[r * 8 + k] * sEF[k * 8 + t] + sHv[(64 + r) * 8 + k] * sEF[64 + k * 8 + t];
                s -= sTc[(8 + t) * 128 + r] + sTc[(16 + t) * 128 + 64 + r];
            } else {
                int r2 = r - 64;
                #pragma unroll
                for (int k = 0; k < 8; k++)
                    s += sHv[r * 8 + k] * sEF[k * 8 + t] - sHv[r2 * 8 + k] * sEF[64 + k * 8 + t];
                s -= sTc[(8 + t) * 128 + r] - sTc[(16 + t) * 128 + r2];
            }
            sHve[r * 8 + t] = sHv[r * 8 + t] - tao * s;
        }
    }
    __syncthreads();

    {
        float thr = tao * eps_p[0] * sigma2[b];
        for (int e = tid; e < 512; e += 256) {
            float re = sHve[e], im = sHve[e + 512];
            float mag = sqrtf(re * re + im * im);
            float s = fmaxf(mag - thr, 0.f) / mag;
            sHve[e] = re * s;
            sHve[e + 512] = im * s;
        }
    }
    __syncthreads();

    for (int i = tid; i < 1024; i += 256) {
        int c = i >> 7, r = i & 127;
        g_HveT[(size_t)b * 1024 + i] = sHve[r * 8 + c];
    }
}

// ================= K5: H_new, W, WTW, F (fbres) =================
__global__ __launch_bounds__(256)
void k5_kernel(const float* __restrict__ X, const float* __restrict__ Y,
               const float* __restrict__ lambda_W,
               const float* __restrict__ rUt, const float* __restrict__ iUt,
               const float* __restrict__ factor_p,
               float* __restrict__ out_Hnew, float* __restrict__ out_lamW)
{
    __shared__ float sUc[1024];
    __shared__ float sUt[128];
    __shared__ float sHN[1024];
    __shared__ float sW[2048];
    __shared__ float sWTW[256];
    __shared__ float sCh[2048];

    const int b = blockIdx.x;
    const int tid = threadIdx.x;

    for (int i = tid; i < 1024; i += 256) sUc[i] = g_UrHvT[(size_t)b * 1024 + i];
    if (tid < 128) sUt[tid] = (tid < 64) ? rUt[tid] : iUt[tid - 64];
    __syncthreads();

    {
        const int r = tid >> 1, c0 = (tid & 1) * 4;
        #pragma unroll
        for (int c = c0; c < c0 + 4; c++) {
            float acc = 0.f;
            if (r < 64) {
                #pragma unroll
                for (int k = 0; k < 8; k++)
                    acc += sUc[k * 128 + r] * sUt[c * 8 + k] + sUc[k * 128 + 64 + r] * sUt[64 + c * 8 + k];
            } else {
                #pragma unroll
                for (int k = 0; k < 8; k++)
                    acc += sUc[k * 128 + r] * sUt[c * 8 + k] - sUc[k * 128 + r - 64] * sUt[64 + c * 8 + k];
            }
            sHN[r * 8 + c] = acc;
            out_Hnew[(size_t)b * 1024 + r * 8 + c] = acc;
        }
    }
    __syncthreads();

    for (int e = tid; e < 2048; e += 256) {
        int r = e >> 4, i = e & 15;
        float v;
        if (r < 64) v = (i < 8) ? sHN[r * 8 + i] : -sHN[(64 + r) * 8 + (i - 8)];
        else        v = (i < 8) ? sHN[r * 8 + i] : sHN[(r - 64) * 8 + (i - 8)];
        sW[e] = v;
    }
    __syncthreads();

    {
        int i = tid >> 4, j = tid & 15;
        float acc = 0.f;
        #pragma unroll 4
        for (int r = 0; r < 128; r++) acc += sW[r * 16 + i] * sW[r * 16 + j];
        sWTW[tid] = acc;
    }
    __syncthreads();

    {
        float lamW = factor_p[0] * lambda_W[b];
        const float* Yb = Y + (size_t)b * 128 * LD;
        const float* Xb = X + (size_t)b * 16 * LD;
        float* Fb = g_F + (size_t)b * NN;
        const int l = tid & 127, ih = tid >> 7;
        float acc[8] = {};
        for (int rc = 0; rc < 8; rc++) {
            for (int e = tid; e < 2048; e += 256) {
                int r = e >> 7, ll = e & 127;
                sCh[r * 128 + ll] = Yb[(rc * 16 + r) * 128 + ll];
            }
            __syncthreads();
            #pragma unroll
            for (int r = 0; r < 16; r++) {
                float y = sCh[r * 128 + l];
                float4 w0 = *(const float4*)&sW[(rc * 16 + r) * 16 + ih * 8];
                float4 w1 = *(const float4*)&sW[(rc * 16 + r) * 16 + ih * 8 + 4];
                acc[0] += w0.x * y; acc[1] += w0.y * y; acc[2] += w0.z * y; acc[3] += w0.w * y;
                acc[4] += w1.x * y; acc[5] += w1.y * y; acc[6] += w1.z * y; acc[7] += w1.w * y;
            }
            __syncthreads();
        }
        float xv[16];
        #pragma unroll
        for (int j = 0; j < 16; j++) xv[j] = Xb[j * 128 + l];
        #pragma unroll
        for (int q = 0; q < 8; q++) {
            int i = ih * 8 + q;
            float v = acc[q] + lamW * xv[i];
            #pragma unroll
            for (int j = 0; j < 16; j++) v -= sWTW[i * 16 + j] * xv[j];
            int n = l * 16 + (i & 7) * 2 + (i >> 3);
            Fb[n] = 2.f * lamW - 2.f * SQ2F * v;
        }
        if (tid == 0) out_lamW[b] = lamW;
    }
}

// ================= MMA GEMM1: C[b,n] = V[b,:]·AT[n,:]; epilogue -> u_new =================
__global__ __launch_bounds__(128)
void mma_gemm1(const float* __restrict__ La, const float* __restrict__ lamWv,
               const float* __restrict__ rho_p, const float* __restrict__ kappa_p,
               float* __restrict__ out_u)
{
    __shared__ float sP[2 * TILE_F];
    __shared__ float sQ[2 * TILE_F];
    const int n0 = blockIdx.x * 64, b0 = blockIdx.y * 64;
    float c[2][4][4] = {};
    tile_gemm<false>(g_Vs + (size_t)b0 * MM, g_AT + (size_t)n0 * MM, MM, c, sP, sQ);

    const int lane = threadIdx.x & 31, wid = threadIdx.x >> 5;
    const int wm = wid & 1, wn = wid >> 1;
    const float rho = rho_p[0], kappa = kappa_p[0];
    #pragma unroll
    for (int mt = 0; mt < 2; mt++)
        #pragma unroll
        for (int rr = 0; rr < 2; rr++) {
            const int b = b0 + wm * 32 + mt * 16 + (lane >> 2) + rr * 8;
            const float lamW = lamWv[b];
            const float den = 4.f * lamW - 2.f * kappa;
            const float* gFb = g_F + (size_t)b * NN;
            float* uout = out_u + (size_t)b * NN;
            #pragma unroll
            for (int nt = 0; nt < 4; nt++) {
                const int n = n0 + wn * 32 + nt * 8 + (lane & 3) * 2;
                float2 fb = *(const float2*)(gFb + n);
                float la0 = La[n], la1 = La[n + 1];
                float c0 = c[mt][nt][rr * 2 + 0];
                float c1 = c[mt][nt][rr * 2 + 1];
                float u0 = (rho * c0 + fb.x - kappa) * (1.f / (rho * la0 + den));
                float u1 = (rho * c1 + fb.y - kappa) * (1.f / (rho * la1 + den));
                u0 = fminf(fmaxf(u0, 0.f), 1.f);
                u1 = fminf(fmaxf(u1, 0.f), 1.f);
                *(float2*)(uout + n) = make_float2(u0, u1);
            }
        }
}

// ================= MMA GEMM2: C[b,m] = u[b,:]·A[m,:]; epilogue -> z,l1 =================
__global__ __launch_bounds__(128)
void mma_gemm2(const float* __restrict__ A, const float* __restrict__ u_in,
               const float* __restrict__ theta, const float* __restrict__ z_old,
               const float* __restrict__ l1_old, const float* __restrict__ relax_p,
               const float* __restrict__ acc_p,
               float* __restrict__ out_z, float* __restrict__ out_l1)
{
    __shared__ float sP[2 * TILE_F];
    __shared__ float sQ[2 * TILE_F];
    const int m0 = blockIdx.x * 64, b0 = blockIdx.y * 64;
    float c[2][4][4] = {};
    tile_gemm<false>(u_in + (size_t)b0 * NN, A + (size_t)m0 * NN, NN, c, sP, sQ);

    const int lane = threadIdx.x & 31, wid = threadIdx.x >> 5;
    const int wm = wid & 1, wn = wid >> 1;
    const float relax = relax_p[0], acc = acc_p[0];
    #pragma unroll
    for (int mt = 0; mt < 2; mt++)
        #pragma unroll
        for (int rr = 0; rr < 2; rr++) {
            const int b = b0 + wm * 32 + mt * 16 + (lane >> 2) + rr * 8;
            const float* zob = z_old + (size_t)b * MM;
            const float* lob = l1_old + (size_t)b * MM;
            float* zout = out_z + (size_t)b * MM;
            float* lout = out_l1 + (size_t)b * MM;
            #pragma unroll
            for (int nt = 0; nt < 4; nt++) {
                const int m = m0 + wn * 32 + nt * 8 + (lane & 3) * 2;
                float2 zo = *(const float2*)(zob + m);
                float2 lo = *(const float2*)(lob + m);
                float th0 = theta[m], th1 = theta[m + 1];
                float c0 = c[mt][nt][rr * 2 + 0];
                float c1 = c[mt][nt][rr * 2 + 1];
                float zt0 = th0 - relax * c0 - (1.f - relax) * (th0 - zo.x) - lo.x;
                float zt1 = th1 - relax * c1 - (1.f - relax) * (th1 - zo.y) - lo.y;
                float zn0 = fmaxf(zt0, 0.f), zn1 = fmaxf(zt1, 0.f);
                float ln0 = zn0 - zt0, ln1 = zn1 - zt1;
                *(float2*)(zout + m) = make_float2(zn0 + acc * (zn0 - zo.x),
                                                   zn1 + acc * (zn1 - zo.y));
                *(float2*)(lout + m) = make_float2(ln0 + acc * (ln0 - lo.x),
                                                   ln1 + acc * (ln1 - lo.y));
            }
        }
}

// ================= K4: X_new / XXp_new / acc_new =================
__global__ void x_kernel(const float* __restrict__ u_new, const float* __restrict__ rXp,
                         const float* __restrict__ iXp, const float* __restrict__ accnew_in,
                         float* __restrict__ out_X, float* __restrict__ out_XXp,
                         float* __restrict__ out_acc)
{
    int e = blockIdx.x * blockDim.x + threadIdx.x;
    const int total = BSZ * 16 * LT;
    if (e < total) {
        int b = e / (16 * LT);
        int rem = e - b * (16 * LT);
        int row = rem / LT, l = rem - row * LT;
        int t = row & 7, ci = row >> 3;
        float v;
        if (l < LD) {
            float u = u_new[(size_t)b * NN + l * 16 + t * 2 + ci];
            v = (1.f - 2.f * u) / SQ2F;
            out_X[(size_t)b * 16 * LD + row * LD + l] = v;
        } else {
            int lp = l - LD;
            v = (ci == 0) ? rXp[(size_t)b * NT * LP + t * LP + lp]
                          : iXp[(size_t)b * NT * LP + t * LP + lp];
        }
        out_XXp[e] = v;
    }
    if (e == 0) out_acc[0] = accnew_in[0];
}

// ================= launch =================
extern "C" void kernel_launch(void* const* d_in, const int* in_sizes, int n_in,
                              void* d_out, int out_size) {
    (void)in_sizes; (void)n_in; (void)out_size;
    const float* sigma2   = (const float*)d_in[0];
    const float* X        = (const float*)d_in[1];
    const float* XXp      = (const float*)d_in[2];
    const float* Y        = (const float*)d_in[3];
    const float* YYp      = (const float*)d_in[4];
    const float* rXp      = (const float*)d_in[5];
    const float* iXp      = (const float*)d_in[6];
    const float* H        = (const float*)d_in[7];
    const float* lambda_W = (const float*)d_in[8];
    const float* z        = (const float*)d_in[10];
    const float* lambda1  = (const float*)d_in[11];
    const float* acc_new  = (const float*)d_in[12];
    const float* A        = (const float*)d_in[13];
    const float* Lambda_A = (const float*)d_in[14];
    const float* theta    = (const float*)d_in[15];
    const float* rUr      = (const float*)d_in[16];
    const float* iUr      = (const float*)d_in[17];
    const float* rUt      = (const float*)d_in[18];
    const float* iUt      = (const float*)d_in[19];
    const float* rho      = (const float*)d_in[20];
    const float* kappa    = (const float*)d_in[21];
    const float* epsilon  = (const float*)d_in[22];
    const float* tao      = (const float*)d_in[23];
    const float* factor   = (const float*)d_in[24];
    const float* relax    = (const float*)d_in[25];
    const float* acc      = (const float*)d_in[26];

    float* out = (float*)d_out;
    float* out_X    = out;
    float* out_XXp  = out + 1048576;
    float* out_H    = out + 2228224;
    float* out_lamW = out + 2752512;
    float* out_u    = out + 2753024;
    float* out_z    = out + 3801600;
    float* out_l1   = out + 4325888;
    float* out_acc  = out + 4850176;

    float* dg_Ur, *dg_UrT, *dg_HGT, *dg_T, *dg_HveT, *dg_UrHvT;
    cudaGetSymbolAddress((void**)&dg_Ur, g_Ur);
    cudaGetSymbolAddress((void**)&dg_UrT, g_UrT);
    cudaGetSymbolAddress((void**)&dg_HGT, g_HGT);
    cudaGetSymbolAddress((void**)&dg_T, g_T);
    cudaGetSymbolAddress((void**)&dg_HveT, g_HveT);
    cudaGetSymbolAddress((void**)&dg_UrHvT, g_UrHvT);

    const_kernel<<<64, 256>>>(rUr, iUr);
    v_kernel<<<(BSZ * MM + 255) / 256, 256>>>(theta, z, lambda1);
    at_kernel<<<dim3(64, 32), dim3(32, 8)>>>(A);
    k1a_kernel<<<BSZ, 256>>>(XXp, YYp, H, rUt, iUt);
    mega_gemm<<<dim3(2, BSZ * 24 / 64), 128>>>(dg_UrT, dg_HGT, dg_T);
    k3_kernel<<<BSZ, 256>>>(sigma2, rUt, iUt, tao, epsilon);
    mega_gemm<<<dim3(2, BSZ * 8 / 64), 128>>>(dg_Ur, dg_HveT, dg_UrHvT);
    k5_kernel<<<BSZ, 256>>>(X, Y, lambda_W, rUt, iUt, factor, out_H, out_lamW);
    mma_gemm1<<<dim3(NN / 64, BSZ / 64), 128>>>(Lambda_A, out_lamW, rho, kappa, out_u);
    mma_gemm2<<<dim3(MM / 64, BSZ / 64), 128>>>(A, out_u, theta, z, lambda1, relax, acc,
                                                out_z, out_l1);
    x_kernel<<<(BSZ * 16 * LT + 255) / 256, 256>>>(out_u, rXp, iXp, acc_new,
                                                   out_X, out_XXp, out_acc);
}

// round 7
// speedup vs baseline: 5.4095x; 1.1150x over previous
#include <cuda_runtime.h>
#include <cuda_bf16.h>
#include <math.h>
#include <stdint.h>

// Problem constants
#define NR 64
#define NT 8
#define LD 128
#define LP 16
#define LT 144          // LD + LP
#define BSZ 512
#define MM 1024
#define NN 2048         // LDPC_N

#define SQ2F 1.41421356237309504880f

// -------- scratch (device globals; no runtime allocation) --------
__device__ float g_Ur[128 * 128];     // Ur[i][j] row-major (k = j contiguous)
__device__ float g_UrT[128 * 128];    // UrT[i][j] row-major
__device__ float g_F[BSZ * NN];       // fbres permuted: [b][n]
__device__ float g_Vs[BSZ * MM];      // theta - z - lambda1
__device__ float g_AT[NN * MM];       // A^T
__device__ float g_HGT[BSZ * 24 * 128];   // per batch: HG^T  [c][k]
__device__ float g_T[BSZ * 24 * 128];     // T = UrT@HG stored [b][c][r]
__device__ float g_EF[BSZ * 128];         // E(64) then F(64) per batch
__device__ float g_HveT[BSZ * 8 * 128];   // Hvest^T [c][r]
__device__ float g_UrHvT[BSZ * 8 * 128];  // UrHv   [c][r]

// ================= mma.sync helpers =================
__device__ __forceinline__ uint32_t smem_to_u32(const void* smem_ptr) {
    uint32_t addr;
    asm("{ .reg .u64 tmp; cvta.to.shared.u64 tmp, %1; cvt.u32.u64 %0, tmp; }"
        : "=r"(addr) : "l"(smem_ptr));
    return addr;
}

__device__ __forceinline__ void cp16(uint32_t s, const float* g) {
    asm volatile("cp.async.cg.shared.global [%0], [%1], 16;" :: "r"(s), "l"(g) : "memory");
}
#define CP_COMMIT() asm volatile("cp.async.commit_group;" ::: "memory")
#define CP_WAIT1()  asm volatile("cp.async.wait_group 1;" ::: "memory")
#define CP_WAIT0()  asm volatile("cp.async.wait_group 0;" ::: "memory")

__device__ __forceinline__ uint32_t f2tf(float f) {
    uint32_t r;
    asm("cvt.rna.tf32.f32 %0, %1;" : "=r"(r) : "f"(f));
    return r;
}

__device__ __forceinline__ void mma_tf32(float* c, const uint32_t* a, const uint32_t* b) {
    asm volatile(
        "mma.sync.aligned.m16n8k8.row.col.f32.tf32.tf32.f32 "
        "{%0,%1,%2,%3}, {%4,%5,%6,%7}, {%8,%9}, {%0,%1,%2,%3};"
        : "+f"(c[0]), "+f"(c[1]), "+f"(c[2]), "+f"(c[3])
        : "r"(a[0]), "r"(a[1]), "r"(a[2]), "r"(a[3]), "r"(b[0]), "r"(b[1]));
}

// ---- shared tile mainloop: C[64x64] += P_tile[64,K] * Q_tile[64,K]^T ----
#define TILE_F (64 * 20)
template<bool PRECISE>
__device__ __forceinline__ void tile_gemm(const float* __restrict__ Pg0,
                                          const float* __restrict__ Qg0,
                                          int K, float c[2][4][4],
                                          float* sP, float* sQ)
{
    const int tid = threadIdx.x;
    const int lane = tid & 31, wid = tid >> 5;
    const int wm = wid & 1, wn = wid >> 1;
    const int lrow = tid >> 2, lquad = tid & 3;

    uint32_t sPb = smem_to_u32(sP), sQb = smem_to_u32(sQ);
    const int NK = K >> 4;
    const float* Pg = Pg0 + (size_t)lrow * K + lquad * 4;
    const float* Qg = Qg0 + (size_t)lrow * K + lquad * 4;
    const uint32_t spA0 = sPb + (uint32_t)(lrow * 20 + lquad * 4) * 4;
    const uint32_t spA1 = sPb + (uint32_t)((lrow + 32) * 20 + lquad * 4) * 4;
    const uint32_t sqA0 = sQb + (uint32_t)(lrow * 20 + lquad * 4) * 4;
    const uint32_t sqA1 = sQb + (uint32_t)((lrow + 32) * 20 + lquad * 4) * 4;

    {
        const float* p = Pg;  const float* q = Qg;
        cp16(spA0, p); cp16(spA1, p + (size_t)32 * K);
        cp16(sqA0, q); cp16(sqA1, q + (size_t)32 * K);
        CP_COMMIT();
        p = Pg + 16; q = Qg + 16;
        uint32_t off = TILE_F * 4;
        cp16(spA0 + off, p); cp16(spA1 + off, p + (size_t)32 * K);
        cp16(sqA0 + off, q); cp16(sqA1 + off, q + (size_t)32 * K);
        CP_COMMIT();
    }

    const int arow = lane >> 2, acol = lane & 3;
    for (int kt = 0; kt < NK; kt++) {
        CP_WAIT1();
        __syncthreads();
        const float* Pbuf = sP + (kt & 1) * TILE_F;
        const float* Qbuf = sQ + (kt & 1) * TILE_F;
        #pragma unroll
        for (int ks = 0; ks < 2; ks++) {
            const int k0 = ks * 8 + acol;
            uint32_t a[2][4], bq[4][2];
            uint32_t al[2][4], bl[4][2];
            #pragma unroll
            for (int mt = 0; mt < 2; mt++) {
                const int m = wm * 32 + mt * 16 + arow;
                float v0 = Pbuf[m * 20 + k0];
                float v1 = Pbuf[(m + 8) * 20 + k0];
                float v2 = Pbuf[m * 20 + k0 + 4];
                float v3 = Pbuf[(m + 8) * 20 + k0 + 4];
                a[mt][0] = f2tf(v0); a[mt][1] = f2tf(v1);
                a[mt][2] = f2tf(v2); a[mt][3] = f2tf(v3);
                if (PRECISE) {
                    al[mt][0] = f2tf(v0 - __uint_as_float(a[mt][0]));
                    al[mt][1] = f2tf(v1 - __uint_as_float(a[mt][1]));
                    al[mt][2] = f2tf(v2 - __uint_as_float(a[mt][2]));
                    al[mt][3] = f2tf(v3 - __uint_as_float(a[mt][3]));
                }
            }
            #pragma unroll
            for (int nt = 0; nt < 4; nt++) {
                const int n = wn * 32 + nt * 8 + arow;
                float w0 = Qbuf[n * 20 + k0];
                float w1 = Qbuf[n * 20 + k0 + 4];
                bq[nt][0] = f2tf(w0); bq[nt][1] = f2tf(w1);
                if (PRECISE) {
                    bl[nt][0] = f2tf(w0 - __uint_as_float(bq[nt][0]));
                    bl[nt][1] = f2tf(w1 - __uint_as_float(bq[nt][1]));
                }
            }
            #pragma unroll
            for (int mt = 0; mt < 2; mt++)
                #pragma unroll
                for (int nt = 0; nt < 4; nt++) {
                    if (PRECISE) {
                        mma_tf32(c[mt][nt], a[mt], bl[nt]);
                        mma_tf32(c[mt][nt], al[mt], bq[nt]);
                    }
                    mma_tf32(c[mt][nt], a[mt], bq[nt]);
                }
        }
        __syncthreads();
        if (kt + 2 < NK) {
            uint32_t off = (uint32_t)((kt & 1) * TILE_F) * 4;
            const float* p = Pg + (kt + 2) * 16;
            const float* q = Qg + (kt + 2) * 16;
            cp16(spA0 + off, p); cp16(spA1 + off, p + (size_t)32 * K);
            cp16(sqA0 + off, q); cp16(sqA1 + off, q + (size_t)32 * K);
        }
        CP_COMMIT();
    }
    CP_WAIT0();
}

// ================= K0: build Ur / UrT =================
__global__ void const_kernel(const float* __restrict__ rUr, const float* __restrict__ iUr) {
    int e = blockIdx.x * blockDim.x + threadIdx.x;
    if (e >= 128 * 128) return;
    int i = e >> 7, j = e & 127;
    float v, vt;
    if (i < 64) v = (j < 64) ? rUr[i * 64 + j] : -iUr[i * 64 + (j - 64)];
    else        v = (j < 64) ? iUr[(i - 64) * 64 + j] : rUr[(i - 64) * 64 + (j - 64)];
    g_Ur[e] = v;
    if (i < 64) vt = (j < 64) ? rUr[j * 64 + i] : iUr[(j - 64) * 64 + i];
    else        vt = (j < 64) ? -iUr[j * 64 + (i - 64)] : rUr[(j - 64) * 64 + (i - 64)];
    g_UrT[e] = vt;
}

// ================= K_v: V = theta - z - lambda1 =================
__global__ void v_kernel(const float* __restrict__ theta, const float* __restrict__ z,
                         const float* __restrict__ l1) {
    int e = blockIdx.x * blockDim.x + threadIdx.x;
    if (e < BSZ * MM) {
        int m = e & (MM - 1);
        g_Vs[e] = theta[m] - z[e] - l1[e];
    }
}

// ================= K_at: g_AT[n][m] = A[m][n] =================
__global__ void at_kernel(const float* __restrict__ A) {
    __shared__ float t[32][33];
    int n0 = blockIdx.x * 32, m0 = blockIdx.y * 32;
    int tx = threadIdx.x, ty = threadIdx.y;
    #pragma unroll
    for (int q = 0; q < 4; q++)
        t[ty + 8 * q][tx] = A[(size_t)(m0 + ty + 8 * q) * NN + n0 + tx];
    __syncthreads();
    #pragma unroll
    for (int q = 0; q < 4; q++)
        g_AT[(size_t)(n0 + ty + 8 * q) * MM + m0 + tx] = t[tx][ty + 8 * q];
}

// ================= K1a: per-batch front phases -> g_HGT, g_EF =================
__global__ __launch_bounds__(256)
void k1a_kernel(const float* __restrict__ XXp, const float* __restrict__ YYp,
                const float* __restrict__ H,
                const float* __restrict__ rUt, const float* __restrict__ iUt)
{
    __shared__ float sXXp[16 * LT];
    __shared__ float sUtXT[LT * 16];
    __shared__ float sS[256];
    __shared__ float sCh2[2][128 * 20];   // double-buffered YYp chunk, pad-20 rows
    __shared__ float sUt[128];

    const int b = blockIdx.x;
    const int tid = threadIdx.x;

    const float* XXpb = XXp + (size_t)b * 16 * LT;
    for (int i = tid; i < 16 * LT; i += 256) sXXp[i] = XXpb[i];
    if (tid < 128) sUt[tid] = (tid < 64) ? rUt[tid] : iUt[tid - 64];

    // kick off YYp chunk 0 while we compute UtXT etc.
    const float* YYpb = YYp + (size_t)b * 128 * LT;
    const uint32_t chBase = smem_to_u32(sCh2);
    #pragma unroll
    for (int q = 0; q < 2; q++) {
        int idx = q * 256 + tid;       // 512 cp16 = 128 rows x 4 segs
        int row = idx >> 2, seg = idx & 3;
        cp16(chBase + (uint32_t)(row * 20 + seg * 4) * 4, YYpb + row * LT + seg * 4);
    }
    CP_COMMIT();
    __syncthreads();

    // UtXT[l][i] = (UtT @ XXp)[i][l]
    for (int e = tid; e < 16 * LT; e += 256) {
        int i = e & 15, l = e >> 4;
        float acc = 0.f;
        if (i < 8) {
            #pragma unroll
            for (int k = 0; k < 8; k++) {
                acc += sUt[k * 8 + i] * sXXp[k * LT + l];
                acc += sUt[64 + k * 8 + i] * sXXp[(8 + k) * LT + l];
            }
        } else {
            int i2 = i - 8;
            #pragma unroll
            for (int k = 0; k < 8; k++) {
                acc -= sUt[64 + k * 8 + i2] * sXXp[k * LT + l];
                acc += sUt[k * 8 + i2] * sXXp[(8 + k) * LT + l];
            }
        }
        sUtXT[l * 16 + i] = acc;
    }
    __syncthreads();

    // Gram S
    {
        int i = tid >> 4, j = tid & 15;
        float acc = 0.f;
        #pragma unroll 4
        for (int l = 0; l < LT; l++) acc += sUtXT[l * 16 + i] * sUtXT[l * 16 + j];
        sS[tid] = acc;
    }
    __syncthreads();

    // EF -> global
    if (tid < 128) {
        int q = tid & 63, k = q >> 3, t = q & 7;
        float v;
        if (tid < 64) v = sS[k * 16 + t] + sS[(8 + k) * 16 + 8 + t];
        else          v = sS[k * 16 + 8 + t] - sS[(8 + k) * 16 + t];
        g_EF[(size_t)b * 128 + tid] = v;
    }

    // H transposed -> g_HGT cols 0..7 (coalesced writes)
    {
        const float* Hb = H + (size_t)b * 1024;
        for (int e = tid; e < 1024; e += 256) {
            int c = e >> 7, k = e & 127;
            g_HGT[(size_t)b * 3072 + e] = Hb[k * 8 + c];
        }
    }

    // G_re/G_im = YYp @ rex^T/imx^T -> g_HGT cols 8..23 (cp.async pipelined)
    {
        const int krow = tid >> 1, sel = tid & 1;
        float acc[8] = {};
        for (int lc = 0; lc < 9; lc++) {
            if (lc + 1 < 9) {
                uint32_t off = (uint32_t)(((lc + 1) & 1) * (128 * 20)) * 4;
                int l0n = (lc + 1) * 16;
                #pragma unroll
                for (int q = 0; q < 2; q++) {
                    int idx = q * 256 + tid;
                    int row = idx >> 2, seg = idx & 3;
                    cp16(chBase + off + (uint32_t)(row * 20 + seg * 4) * 4,
                         YYpb + row * LT + l0n + seg * 4);
                }
                CP_COMMIT();
                CP_WAIT1();
            } else {
                CP_WAIT0();
            }
            __syncthreads();
            const float* Ch = sCh2[lc & 1];
            const int l0 = lc * 16;
            #pragma unroll
            for (int j = 0; j < 16; j++) {
                float y = Ch[krow * 20 + j];
                int l = l0 + j;
                float4 u0 = *(const float4*)&sUtXT[l * 16 + sel * 8];
                float4 u1 = *(const float4*)&sUtXT[l * 16 + sel * 8 + 4];
                acc[0] += y * u0.x; acc[1] += y * u0.y; acc[2] += y * u0.z; acc[3] += y * u0.w;
                acc[4] += y * u1.x; acc[5] += y * u1.y; acc[6] += y * u1.z; acc[7] += y * u1.w;
            }
            __syncthreads();
        }
        #pragma unroll
        for (int t = 0; t < 8; t++)
            g_HGT[(size_t)b * 3072 + (8 + sel * 8 + t) * 128 + krow] = acc[t];
    }
}

// ================= mega GEMM (3xTF32 precise): Out[q][m0+p] = P[m0+p,:]·Q[q,:] =================
__global__ __launch_bounds__(128)
void mega_gemm(const float* __restrict__ P, const float* __restrict__ Q,
               float* __restrict__ Out)
{
    __shared__ float buf[4 * TILE_F];
    const int m0 = blockIdx.x * 64;
    const int q0 = blockIdx.y * 64;
    float c[2][4][4] = {};
    tile_gemm<true>(P + (size_t)m0 * 128, Q + (size_t)q0 * 128, 128, c, buf, buf + 2 * TILE_F);
    __syncthreads();

    const int tid = threadIdx.x;
    const int lane = tid & 31, wid = tid >> 5;
    const int wm = wid & 1, wn = wid >> 1;
    #pragma unroll
    for (int mt = 0; mt < 2; mt++)
        #pragma unroll
        for (int nt = 0; nt < 4; nt++)
            #pragma unroll
            for (int k = 0; k < 4; k++) {
                int p = wm * 32 + mt * 16 + (lane >> 2) + (k >> 1) * 8;
                int q = wn * 32 + nt * 8 + (lane & 3) * 2 + (k & 1);
                buf[p * 68 + q] = c[mt][nt][k];
            }
    __syncthreads();
    #pragma unroll 4
    for (int i = 0; i < 32; i++) {
        int idx = i * 128 + tid;
        int p = idx & 63, q = idx >> 6;
        Out[(size_t)(q0 + q) * 128 + m0 + p] = buf[p * 68 + q];
    }
}

// ================= K3: Hv, D, Hvest, soft-threshold -> g_HveT =================
__global__ __launch_bounds__(256)
void k3_kernel(const float* __restrict__ sigma2,
               const float* __restrict__ rUt, const float* __restrict__ iUt,
               const float* __restrict__ tao_p, const float* __restrict__ eps_p)
{
    __shared__ float sTc[24 * 128];
    __shared__ float sEF[128];
    __shared__ float sUt[128];
    __shared__ float sHv[1024];
    __shared__ float sHve[1024];

    const int b = blockIdx.x;
    const int tid = threadIdx.x;
    const float tao = tao_p[0];

    for (int i = tid; i < 3072; i += 256) sTc[i] = g_T[(size_t)b * 3072 + i];
    if (tid < 128) {
        sEF[tid] = g_EF[(size_t)b * 128 + tid];
        sUt[tid] = (tid < 64) ? rUt[tid] : iUt[tid - 64];
    }
    __syncthreads();

    {
        const int r = tid >> 1, c0 = (tid & 1) * 4;
        #pragma unroll
        for (int c = c0; c < c0 + 4; c++) {
            float acc = 0.f;
            if (r < 64) {
                #pragma unroll
                for (int k = 0; k < 8; k++)
                    acc += sTc[k * 128 + r] * sUt[k * 8 + c] - sTc[k * 128 + 64 + r] * sUt[64 + k * 8 + c];
            } else {
                #pragma unroll
                for (int k = 0; k < 8; k++)
                    acc += sTc[k * 128 + r] * sUt[k * 8 + c] + sTc[k * 128 + r - 64] * sUt[64 + k * 8 + c];
            }
            sHv[r * 8 + c] = acc;
        }
    }
    __syncthreads();

    {
        const int r = tid >> 1, t0 = (tid & 1) * 4;
        #pragma unroll
        for (int t = t0; t < t0 + 4; t++) {
            float s = 0.f;
            if (r < 64) {
                #pragma unroll
                for (int k = 0; k < 8; k++)
                    s += sHv[r * 8 + k] * sEF[k * 8 + t] + sHv[(64 + r) * 8 + k] * sEF[64 + k * 8 + t];
                s -= sTc[(8 + t) * 128 + r] + sTc[(16 + t) * 128 + 64 + r];
            } else {
                int r2 = r - 64;
                #pragma unroll
                for (int k = 0; k < 8; k++)
                    s += sHv[r * 8 + k] * sEF[k * 8 + t] - sHv[r2 * 8 + k] * sEF[64 + k * 8 + t];
                s -= sTc[(8 + t) * 128 + r] - sTc[(16 + t) * 128 + r2];
            }
            sHve[r * 8 + t] = sHv[r * 8 + t] - tao * s;
        }
    }
    __syncthreads();

    {
        float thr = tao * eps_p[0] * sigma2[b];
        for (int e = tid; e < 512; e += 256) {
            float re = sHve[e], im = sHve[e + 512];
            float mag = sqrtf(re * re + im * im);
            float s = fmaxf(mag - thr, 0.f) / mag;
            sHve[e] = re * s;
            sHve[e + 512] = im * s;
        }
    }
    __syncthreads();

    for (int i = tid; i < 1024; i += 256) {
        int c = i >> 7, r = i & 127;
        g_HveT[(size_t)b * 1024 + i] = sHve[r * 8 + c];
    }
}

// ================= K5: H_new, W, WTW, F (fbres) =================
__global__ __launch_bounds__(256)
void k5_kernel(const float* __restrict__ X, const float* __restrict__ Y,
               const float* __restrict__ lambda_W,
               const float* __restrict__ rUt, const float* __restrict__ iUt,
               const float* __restrict__ factor_p,
               float* __restrict__ out_Hnew, float* __restrict__ out_lamW)
{
    __shared__ float sUc[1024];
    __shared__ float sUt[128];
    __shared__ float sHN[1024];
    __shared__ float sW[2048];
    __shared__ float sWTW[256];
    __shared__ float sCh[2][2048];

    const int b = blockIdx.x;
    const int tid = threadIdx.x;

    // kick off Y round 0 immediately
    const float* Yb = Y + (size_t)b * 128 * LD;
    const uint32_t chBase = smem_to_u32(sCh);
    #pragma unroll
    for (int q = 0; q < 2; q++) {
        int idx = q * 256 + tid;       // 512 cp16 = 16 rows x 32 segs
        int row = idx >> 5, seg = idx & 31;
        cp16(chBase + (uint32_t)(row * 128 + seg * 4) * 4, Yb + row * 128 + seg * 4);
    }
    CP_COMMIT();

    for (int i = tid; i < 1024; i += 256) sUc[i] = g_UrHvT[(size_t)b * 1024 + i];
    if (tid < 128) sUt[tid] = (tid < 64) ? rUt[tid] : iUt[tid - 64];
    __syncthreads();

    {
        const int r = tid >> 1, c0 = (tid & 1) * 4;
        #pragma unroll
        for (int c = c0; c < c0 + 4; c++) {
            float acc = 0.f;
            if (r < 64) {
                #pragma unroll
                for (int k = 0; k < 8; k++)
                    acc += sUc[k * 128 + r] * sUt[c * 8 + k] + sUc[k * 128 + 64 + r] * sUt[64 + c * 8 + k];
            } else {
                #pragma unroll
                for (int k = 0; k < 8; k++)
                    acc += sUc[k * 128 + r] * sUt[c * 8 + k] - sUc[k * 128 + r - 64] * sUt[64 + c * 8 + k];
            }
            sHN[r * 8 + c] = acc;
            out_Hnew[(size_t)b * 1024 + r * 8 + c] = acc;
        }
    }
    __syncthreads();

    for (int e = tid; e < 2048; e += 256) {
        int r = e >> 4, i = e & 15;
        float v;
        if (r < 64) v = (i < 8) ? sHN[r * 8 + i] : -sHN[(64 + r) * 8 + (i - 8)];
        else        v = (i < 8) ? sHN[r * 8 + i] : sHN[(r - 64) * 8 + (i - 8)];
        sW[e] = v;
    }
    __syncthreads();

    {
        int i = tid >> 4, j = tid & 15;
        float acc = 0.f;
        #pragma unroll 4
        for (int r = 0; r < 128; r++) acc += sW[r * 16 + i] * sW[r * 16 + j];
        sWTW[tid] = acc;
    }
    __syncthreads();

    // F = W^T Y + lamW*X - WTW@X -> g_F (cp.async pipelined Y staging)
    {
        float lamW = factor_p[0] * lambda_W[b];
        const float* Xb = X + (size_t)b * 16 * LD;
        float* Fb = g_F + (size_t)b * NN;
        const int l = tid & 127, ih = tid >> 7;
        float acc[8] = {};
        for (int rc = 0; rc < 8; rc++) {
            if (rc + 1 < 8) {
                uint32_t off = (uint32_t)(((rc + 1) & 1) * 2048) * 4;
                const float* src = Yb + (rc + 1) * 16 * 128;
                #pragma unroll
                for (int q = 0; q < 2; q++) {
                    int idx = q * 256 + tid;
                    int row = idx >> 5, seg = idx & 31;
                    cp16(chBase + off + (uint32_t)(row * 128 + seg * 4) * 4,
                         src + row * 128 + seg * 4);
                }
                CP_COMMIT();
                CP_WAIT1();
            } else {
                CP_WAIT0();
            }
            __syncthreads();
            const float* Ch = sCh[rc & 1];
            #pragma unroll
            for (int r = 0; r < 16; r++) {
                float y = Ch[r * 128 + l];
                float4 w0 = *(const float4*)&sW[(rc * 16 + r) * 16 + ih * 8];
                float4 w1 = *(const float4*)&sW[(rc * 16 + r) * 16 + ih * 8 + 4];
                acc[0] += w0.x * y; acc[1] += w0.y * y; acc[2] += w0.z * y; acc[3] += w0.w * y;
                acc[4] += w1.x * y; acc[5] += w1.y * y; acc[6] += w1.z * y; acc[7] += w1.w * y;
            }
            __syncthreads();
        }
        float xv[16];
        #pragma unroll
        for (int j = 0; j < 16; j++) xv[j] = Xb[j * 128 + l];
        #pragma unroll
        for (int q = 0; q < 8; q++) {
            int i = ih * 8 + q;
            float v = acc[q] + lamW * xv[i];
            #pragma unroll
            for (int j = 0; j < 16; j++) v -= sWTW[i * 16 + j] * xv[j];
            int n = l * 16 + (i & 7) * 2 + (i >> 3);
            Fb[n] = 2.f * lamW - 2.f * SQ2F * v;
        }
        if (tid == 0) out_lamW[b] = lamW;
    }
}

// ================= MMA GEMM1: C[b,n] = V[b,:]·AT[n,:]; epilogue -> u_new =================
__global__ __launch_bounds__(128)
void mma_gemm1(const float* __restrict__ La, const float* __restrict__ lamWv,
               const float* __restrict__ rho_p, const float* __restrict__ kappa_p,
               float* __restrict__ out_u)
{
    __shared__ float sP[2 * TILE_F];
    __shared__ float sQ[2 * TILE_F];
    const int n0 = blockIdx.x * 64, b0 = blockIdx.y * 64;
    float c[2][4][4] = {};
    tile_gemm<false>(g_Vs + (size_t)b0 * MM, g_AT + (size_t)n0 * MM, MM, c, sP, sQ);

    const int lane = threadIdx.x & 31, wid = threadIdx.x >> 5;
    const int wm = wid & 1, wn = wid >> 1;
    const float rho = rho_p[0], kappa = kappa_p[0];
    #pragma unroll
    for (int mt = 0; mt < 2; mt++)
        #pragma unroll
        for (int rr = 0; rr < 2; rr++) {
            const int b = b0 + wm * 32 + mt * 16 + (lane >> 2) + rr * 8;
            const float lamW = lamWv[b];
            const float den = 4.f * lamW - 2.f * kappa;
            const float* gFb = g_F + (size_t)b * NN;
            float* uout = out_u + (size_t)b * NN;
            #pragma unroll
            for (int nt = 0; nt < 4; nt++) {
                const int n = n0 + wn * 32 + nt * 8 + (lane & 3) * 2;
                float2 fb = *(const float2*)(gFb + n);
                float la0 = La[n], la1 = La[n + 1];
                float c0 = c[mt][nt][rr * 2 + 0];
                float c1 = c[mt][nt][rr * 2 + 1];
                float u0 = (rho * c0 + fb.x - kappa) * (1.f / (rho * la0 + den));
                float u1 = (rho * c1 + fb.y - kappa) * (1.f / (rho * la1 + den));
                u0 = fminf(fmaxf(u0, 0.f), 1.f);
                u1 = fminf(fmaxf(u1, 0.f), 1.f);
                *(float2*)(uout + n) = make_float2(u0, u1);
            }
        }
}

// ================= MMA GEMM2: C[b,m] = u[b,:]·A[m,:]; epilogue -> z,l1 =================
__global__ __launch_bounds__(128)
void mma_gemm2(const float* __restrict__ A, const float* __restrict__ u_in,
               const float* __restrict__ theta, const float* __restrict__ z_old,
               const float* __restrict__ l1_old, const float* __restrict__ relax_p,
               const float* __restrict__ acc_p,
               float* __restrict__ out_z, float* __restrict__ out_l1)
{
    __shared__ float sP[2 * TILE_F];
    __shared__ float sQ[2 * TILE_F];
    const int m0 = blockIdx.x * 64, b0 = blockIdx.y * 64;
    float c[2][4][4] = {};
    tile_gemm<false>(u_in + (size_t)b0 * NN, A + (size_t)m0 * NN, NN, c, sP, sQ);

    const int lane = threadIdx.x & 31, wid = threadIdx.x >> 5;
    const int wm = wid & 1, wn = wid >> 1;
    const float relax = relax_p[0], acc = acc_p[0];
    #pragma unroll
    for (int mt = 0; mt < 2; mt++)
        #pragma unroll
        for (int rr = 0; rr < 2; rr++) {
            const int b = b0 + wm * 32 + mt * 16 + (lane >> 2) + rr * 8;
            const float* zob = z_old + (size_t)b * MM;
            const float* lob = l1_old + (size_t)b * MM;
            float* zout = out_z + (size_t)b * MM;
            float* lout = out_l1 + (size_t)b * MM;
            #pragma unroll
            for (int nt = 0; nt < 4; nt++) {
                const int m = m0 + wn * 32 + nt * 8 + (lane & 3) * 2;
                float2 zo = *(const float2*)(zob + m);
                float2 lo = *(const float2*)(lob + m);
                float th0 = theta[m], th1 = theta[m + 1];
                float c0 = c[mt][nt][rr * 2 + 0];
                float c1 = c[mt][nt][rr * 2 + 1];
                float zt0 = th0 - relax * c0 - (1.f - relax) * (th0 - zo.x) - lo.x;
                float zt1 = th1 - relax * c1 - (1.f - relax) * (th1 - zo.y) - lo.y;
                float zn0 = fmaxf(zt0, 0.f), zn1 = fmaxf(zt1, 0.f);
                float ln0 = zn0 - zt0, ln1 = zn1 - zt1;
                *(float2*)(zout + m) = make_float2(zn0 + acc * (zn0 - zo.x),
                                                   zn1 + acc * (zn1 - zo.y));
                *(float2*)(lout + m) = make_float2(ln0 + acc * (ln0 - lo.x),
                                                   ln1 + acc * (ln1 - lo.y));
            }
        }
}

// ================= K4: X_new / XXp_new / acc_new =================
__global__ void x_kernel(const float* __restrict__ u_new, const float* __restrict__ rXp,
                         const float* __restrict__ iXp, const float* __restrict__ accnew_in,
                         float* __restrict__ out_X, float* __restrict__ out_XXp,
                         float* __restrict__ out_acc)
{
    int e = blockIdx.x * blockDim.x + threadIdx.x;
    const int total = BSZ * 16 * LT;
    if (e < total) {
        int b = e / (16 * LT);
        int rem = e - b * (16 * LT);
        int row = rem / LT, l = rem - row * LT;
        int t = row & 7, ci = row >> 3;
        float v;
        if (l < LD) {
            float u = u_new[(size_t)b * NN + l * 16 + t * 2 + ci];
            v = (1.f - 2.f * u) / SQ2F;
            out_X[(size_t)b * 16 * LD + row * LD + l] = v;
        } else {
            int lp = l - LD;
            v = (ci == 0) ? rXp[(size_t)b * NT * LP + t * LP + lp]
                          : iXp[(size_t)b * NT * LP + t * LP + lp];
        }
        out_XXp[e] = v;
    }
    if (e == 0) out_acc[0] = accnew_in[0];
}

// ================= launch =================
extern "C" void kernel_launch(void* const* d_in, const int* in_sizes, int n_in,
                              void* d_out, int out_size) {
    (void)in_sizes; (void)n_in; (void)out_size;
    const float* sigma2   = (const float*)d_in[0];
    const float* X        = (const float*)d_in[1];
    const float* XXp      = (const float*)d_in[2];
    const float* Y        = (const float*)d_in[3];
    const float* YYp      = (const float*)d_in[4];
    const float* rXp      = (const float*)d_in[5];
    const float* iXp      = (const float*)d_in[6];
    const float* H        = (const float*)d_in[7];
    const float* lambda_W = (const float*)d_in[8];
    const float* z        = (const float*)d_in[10];
    const float* lambda1  = (const float*)d_in[11];
    const float* acc_new  = (const float*)d_in[12];
    const float* A        = (const float*)d_in[13];
    const float* Lambda_A = (const float*)d_in[14];
    const float* theta    = (const float*)d_in[15];
    const float* rUr      = (const float*)d_in[16];
    const float* iUr      = (const float*)d_in[17];
    const float* rUt      = (const float*)d_in[18];
    const float* iUt      = (const float*)d_in[19];
    const float* rho      = (const float*)d_in[20];
    const float* kappa    = (const float*)d_in[21];
    const float* epsilon  = (const float*)d_in[22];
    const float* tao      = (const float*)d_in[23];
    const float* factor   = (const float*)d_in[24];
    const float* relax    = (const float*)d_in[25];
    const float* acc      = (const float*)d_in[26];

    float* out = (float*)d_out;
    float* out_X    = out;
    float* out_XXp  = out + 1048576;
    float* out_H    = out + 2228224;
    float* out_lamW = out + 2752512;
    float* out_u    = out + 2753024;
    float* out_z    = out + 3801600;
    float* out_l1   = out + 4325888;
    float* out_acc  = out + 4850176;

    float* dg_Ur, *dg_UrT, *dg_HGT, *dg_T, *dg_HveT, *dg_UrHvT;
    cudaGetSymbolAddress((void**)&dg_Ur, g_Ur);
    cudaGetSymbolAddress((void**)&dg_UrT, g_UrT);
    cudaGetSymbolAddress((void**)&dg_HGT, g_HGT);
    cudaGetSymbolAddress((void**)&dg_T, g_T);
    cudaGetSymbolAddress((void**)&dg_HveT, g_HveT);
    cudaGetSymbolAddress((void**)&dg_UrHvT, g_UrHvT);

    const_kernel<<<64, 256>>>(rUr, iUr);
    v_kernel<<<(BSZ * MM + 255) / 256, 256>>>(theta, z, lambda1);
    at_kernel<<<dim3(64, 32), dim3(32, 8)>>>(A);
    k1a_kernel<<<BSZ, 256>>>(XXp, YYp, H, rUt, iUt);
    mega_gemm<<<dim3(2, BSZ * 24 / 64), 128>>>(dg_UrT, dg_HGT, dg_T);
    k3_kernel<<<BSZ, 256>>>(sigma2, rUt, iUt, tao, epsilon);
    mega_gemm<<<dim3(2, BSZ * 8 / 64), 128>>>(dg_Ur, dg_HveT, dg_UrHvT);
    k5_kernel<<<BSZ, 256>>>(X, Y, lambda_W, rUt, iUt, factor, out_H, out_lamW);
    mma_gemm1<<<dim3(NN / 64, BSZ / 64), 128>>>(Lambda_A, out_lamW, rho, kappa, out_u);
    mma_gemm2<<<dim3(MM / 64, BSZ / 64), 128>>>(A, out_u, theta, z, lambda1, relax, acc,
                                                out_z, out_l1);
    x_kernel<<<(BSZ * 16 * LT + 255) / 256, 256>>>(out_u, rXp, iXp, acc_new,
                                                   out_X, out_XXp, out_acc);
}

// round 8
// speedup vs baseline: 6.2028x; 1.1466x over previous
#include <cuda_runtime.h>
#include <cuda_bf16.h>
#include <math.h>
#include <stdint.h>

// Problem constants
#define NR 64
#define NT 8
#define LD 128
#define LP 16
#define LT 144          // LD + LP
#define BSZ 512
#define MM 1024
#define NN 2048         // LDPC_N

#define SQ2F 1.41421356237309504880f

// -------- scratch (device globals; no runtime allocation) --------
__device__ float g_Ur[128 * 128];
__device__ float g_UrT[128 * 128];
__device__ float g_F[BSZ * NN];       // fbres permuted: [b][n]
__device__ float g_Vs[BSZ * MM];      // theta - z - lambda1
__device__ float g_AT[NN * MM];       // A^T
__device__ float g_HGT[BSZ * 24 * 128];
__device__ float g_T[BSZ * 24 * 128];
__device__ float g_EF[BSZ * 128];
__device__ float g_HveT[BSZ * 8 * 128];
__device__ float g_UrHvT[BSZ * 8 * 128];
__device__ float g_C1[2 * BSZ * NN];  // split-K partials for gemm1
__device__ float g_C2[2 * BSZ * MM];  // split-K partials for gemm2

// ================= mma.sync helpers =================
__device__ __forceinline__ uint32_t smem_to_u32(const void* smem_ptr) {
    uint32_t addr;
    asm("{ .reg .u64 tmp; cvta.to.shared.u64 tmp, %1; cvt.u32.u64 %0, tmp; }"
        : "=r"(addr) : "l"(smem_ptr));
    return addr;
}

__device__ __forceinline__ void cp16(uint32_t s, const float* g) {
    asm volatile("cp.async.cg.shared.global [%0], [%1], 16;" :: "r"(s), "l"(g) : "memory");
}
#define CP_COMMIT() asm volatile("cp.async.commit_group;" ::: "memory")
#define CP_WAIT1()  asm volatile("cp.async.wait_group 1;" ::: "memory")
#define CP_WAIT0()  asm volatile("cp.async.wait_group 0;" ::: "memory")

__device__ __forceinline__ uint32_t f2tf(float f) {
    uint32_t r;
    asm("cvt.rna.tf32.f32 %0, %1;" : "=r"(r) : "f"(f));
    return r;
}

__device__ __forceinline__ void mma_tf32(float* c, const uint32_t* a, const uint32_t* b) {
    asm volatile(
        "mma.sync.aligned.m16n8k8.row.col.f32.tf32.tf32.f32 "
        "{%0,%1,%2,%3}, {%4,%5,%6,%7}, {%8,%9}, {%0,%1,%2,%3};"
        : "+f"(c[0]), "+f"(c[1]), "+f"(c[2]), "+f"(c[3])
        : "r"(a[0]), "r"(a[1]), "r"(a[2]), "r"(a[3]), "r"(b[0]), "r"(b[1]));
}

// ---- shared tile mainloop: C[64x64] += P[64,klen] * Q[64,klen]^T, row stride ld ----
#define TILE_F (64 * 20)
template<bool PRECISE>
__device__ __forceinline__ void tile_gemm(const float* __restrict__ Pg0,
                                          const float* __restrict__ Qg0,
                                          int ld, int klen, float c[2][4][4],
                                          float* sP, float* sQ)
{
    const int tid = threadIdx.x;
    const int lane = tid & 31, wid = tid >> 5;
    const int wm = wid & 1, wn = wid >> 1;
    const int lrow = tid >> 2, lquad = tid & 3;

    uint32_t sPb = smem_to_u32(sP), sQb = smem_to_u32(sQ);
    const int NK = klen >> 4;
    const float* Pg = Pg0 + (size_t)lrow * ld + lquad * 4;
    const float* Qg = Qg0 + (size_t)lrow * ld + lquad * 4;
    const uint32_t spA0 = sPb + (uint32_t)(lrow * 20 + lquad * 4) * 4;
    const uint32_t spA1 = sPb + (uint32_t)((lrow + 32) * 20 + lquad * 4) * 4;
    const uint32_t sqA0 = sQb + (uint32_t)(lrow * 20 + lquad * 4) * 4;
    const uint32_t sqA1 = sQb + (uint32_t)((lrow + 32) * 20 + lquad * 4) * 4;

    {
        const float* p = Pg;  const float* q = Qg;
        cp16(spA0, p); cp16(spA1, p + (size_t)32 * ld);
        cp16(sqA0, q); cp16(sqA1, q + (size_t)32 * ld);
        CP_COMMIT();
        p = Pg + 16; q = Qg + 16;
        uint32_t off = TILE_F * 4;
        cp16(spA0 + off, p); cp16(spA1 + off, p + (size_t)32 * ld);
        cp16(sqA0 + off, q); cp16(sqA1 + off, q + (size_t)32 * ld);
        CP_COMMIT();
    }

    const int arow = lane >> 2, acol = lane & 3;
    for (int kt = 0; kt < NK; kt++) {
        CP_WAIT1();
        __syncthreads();
        const float* Pbuf = sP + (kt & 1) * TILE_F;
        const float* Qbuf = sQ + (kt & 1) * TILE_F;
        #pragma unroll
        for (int ks = 0; ks < 2; ks++) {
            const int k0 = ks * 8 + acol;
            uint32_t a[2][4], bq[4][2];
            uint32_t al[2][4], bl[4][2];
            #pragma unroll
            for (int mt = 0; mt < 2; mt++) {
                const int m = wm * 32 + mt * 16 + arow;
                float v0 = Pbuf[m * 20 + k0];
                float v1 = Pbuf[(m + 8) * 20 + k0];
                float v2 = Pbuf[m * 20 + k0 + 4];
                float v3 = Pbuf[(m + 8) * 20 + k0 + 4];
                a[mt][0] = f2tf(v0); a[mt][1] = f2tf(v1);
                a[mt][2] = f2tf(v2); a[mt][3] = f2tf(v3);
                if (PRECISE) {
                    al[mt][0] = f2tf(v0 - __uint_as_float(a[mt][0]));
                    al[mt][1] = f2tf(v1 - __uint_as_float(a[mt][1]));
                    al[mt][2] = f2tf(v2 - __uint_as_float(a[mt][2]));
                    al[mt][3] = f2tf(v3 - __uint_as_float(a[mt][3]));
                }
            }
            #pragma unroll
            for (int nt = 0; nt < 4; nt++) {
                const int n = wn * 32 + nt * 8 + arow;
                float w0 = Qbuf[n * 20 + k0];
                float w1 = Qbuf[n * 20 + k0 + 4];
                bq[nt][0] = f2tf(w0); bq[nt][1] = f2tf(w1);
                if (PRECISE) {
                    bl[nt][0] = f2tf(w0 - __uint_as_float(bq[nt][0]));
                    bl[nt][1] = f2tf(w1 - __uint_as_float(bq[nt][1]));
                }
            }
            #pragma unroll
            for (int mt = 0; mt < 2; mt++)
                #pragma unroll
                for (int nt = 0; nt < 4; nt++) {
                    if (PRECISE) {
                        mma_tf32(c[mt][nt], a[mt], bl[nt]);
                        mma_tf32(c[mt][nt], al[mt], bq[nt]);
                    }
                    mma_tf32(c[mt][nt], a[mt], bq[nt]);
                }
        }
        __syncthreads();
        if (kt + 2 < NK) {
            uint32_t off = (uint32_t)((kt & 1) * TILE_F) * 4;
            const float* p = Pg + (kt + 2) * 16;
            const float* q = Qg + (kt + 2) * 16;
            cp16(spA0 + off, p); cp16(spA1 + off, p + (size_t)32 * ld);
            cp16(sqA0 + off, q); cp16(sqA1 + off, q + (size_t)32 * ld);
        }
        CP_COMMIT();
    }
    CP_WAIT0();
}

// ================= K0: build Ur / UrT =================
__global__ void const_kernel(const float* __restrict__ rUr, const float* __restrict__ iUr) {
    int e = blockIdx.x * blockDim.x + threadIdx.x;
    if (e >= 128 * 128) return;
    int i = e >> 7, j = e & 127;
    float v, vt;
    if (i < 64) v = (j < 64) ? rUr[i * 64 + j] : -iUr[i * 64 + (j - 64)];
    else        v = (j < 64) ? iUr[(i - 64) * 64 + j] : rUr[(i - 64) * 64 + (j - 64)];
    g_Ur[e] = v;
    if (i < 64) vt = (j < 64) ? rUr[j * 64 + i] : iUr[(j - 64) * 64 + i];
    else        vt = (j < 64) ? -iUr[j * 64 + (i - 64)] : rUr[(j - 64) * 64 + (i - 64)];
    g_UrT[e] = vt;
}

// ================= K_v: V = theta - z - lambda1 =================
__global__ void v_kernel(const float* __restrict__ theta, const float* __restrict__ z,
                         const float* __restrict__ l1) {
    int e = blockIdx.x * blockDim.x + threadIdx.x;
    if (e < BSZ * MM) {
        int m = e & (MM - 1);
        g_Vs[e] = theta[m] - z[e] - l1[e];
    }
}

// ================= K_at: g_AT[n][m] = A[m][n] =================
__global__ void at_kernel(const float* __restrict__ A) {
    __shared__ float t[32][33];
    int n0 = blockIdx.x * 32, m0 = blockIdx.y * 32;
    int tx = threadIdx.x, ty = threadIdx.y;
    #pragma unroll
    for (int q = 0; q < 4; q++)
        t[ty + 8 * q][tx] = A[(size_t)(m0 + ty + 8 * q) * NN + n0 + tx];
    __syncthreads();
    #pragma unroll
    for (int q = 0; q < 4; q++)
        g_AT[(size_t)(n0 + ty + 8 * q) * MM + m0 + tx] = t[tx][ty + 8 * q];
}

// ================= K1a: per-batch front phases (512 thr) =================
__global__ __launch_bounds__(512)
void k1a_kernel(const float* __restrict__ XXp, const float* __restrict__ YYp,
                const float* __restrict__ H,
                const float* __restrict__ rUt, const float* __restrict__ iUt)
{
    __shared__ float sXXp[16 * LT];
    __shared__ float sUtXT[LT * 16];
    __shared__ float sS[256];
    __shared__ float sCh2[2][128 * 20];
    __shared__ float sUt[128];

    const int b = blockIdx.x;
    const int tid = threadIdx.x;

    const float* XXpb = XXp + (size_t)b * 16 * LT;
    for (int i = tid; i < 16 * LT; i += 512) sXXp[i] = XXpb[i];
    if (tid < 128) sUt[tid] = (tid < 64) ? rUt[tid] : iUt[tid - 64];

    // kick off YYp chunk 0: 512 cp16 = 128 rows x 4 segs
    const float* YYpb = YYp + (size_t)b * 128 * LT;
    const uint32_t chBase = smem_to_u32(sCh2);
    {
        int row = tid >> 2, seg = tid & 3;
        cp16(chBase + (uint32_t)(row * 20 + seg * 4) * 4, YYpb + row * LT + seg * 4);
    }
    CP_COMMIT();
    __syncthreads();

    // UtXT[l][i]
    for (int e = tid; e < 16 * LT; e += 512) {
        int i = e & 15, l = e >> 4;
        float acc = 0.f;
        if (i < 8) {
            #pragma unroll
            for (int k = 0; k < 8; k++) {
                acc += sUt[k * 8 + i] * sXXp[k * LT + l];
                acc += sUt[64 + k * 8 + i] * sXXp[(8 + k) * LT + l];
            }
        } else {
            int i2 = i - 8;
            #pragma unroll
            for (int k = 0; k < 8; k++) {
                acc -= sUt[64 + k * 8 + i2] * sXXp[k * LT + l];
                acc += sUt[k * 8 + i2] * sXXp[(8 + k) * LT + l];
            }
        }
        sUtXT[l * 16 + i] = acc;
    }
    __syncthreads();

    // Gram S (256 threads)
    if (tid < 256) {
        int i = tid >> 4, j = tid & 15;
        float acc = 0.f;
        #pragma unroll 4
        for (int l = 0; l < LT; l++) acc += sUtXT[l * 16 + i] * sUtXT[l * 16 + j];
        sS[tid] = acc;
    }
    __syncthreads();

    if (tid < 128) {
        int q = tid & 63, k = q >> 3, t = q & 7;
        float v;
        if (tid < 64) v = sS[k * 16 + t] + sS[(8 + k) * 16 + 8 + t];
        else          v = sS[k * 16 + 8 + t] - sS[(8 + k) * 16 + t];
        g_EF[(size_t)b * 128 + tid] = v;
    }

    // H transposed -> g_HGT cols 0..7 (coalesced)
    {
        const float* Hb = H + (size_t)b * 1024;
        for (int e = tid; e < 1024; e += 512) {
            int c = e >> 7, k = e & 127;
            g_HGT[(size_t)b * 3072 + e] = Hb[k * 8 + c];
        }
    }

    // G = YYp @ UtXT -> g_HGT cols 8..23 (pipelined, 4-col split per thread)
    {
        const int krow = tid >> 2, cb = tid & 3;
        float acc[4] = {};
        for (int lc = 0; lc < 9; lc++) {
            if (lc + 1 < 9) {
                uint32_t off = (uint32_t)(((lc + 1) & 1) * (128 * 20)) * 4;
                int l0n = (lc + 1) * 16;
                int row = tid >> 2, seg = tid & 3;
                cp16(chBase + off + (uint32_t)(row * 20 + seg * 4) * 4,
                     YYpb + row * LT + l0n + seg * 4);
                CP_COMMIT();
                CP_WAIT1();
            } else {
                CP_WAIT0();
            }
            __syncthreads();
            const float* Ch = sCh2[lc & 1];
            const int l0 = lc * 16;
            #pragma unroll
            for (int j = 0; j < 16; j++) {
                float y = Ch[krow * 20 + j];
                int l = l0 + j;
                float4 u0 = *(const float4*)&sUtXT[l * 16 + cb * 4];
                acc[0] += y * u0.x; acc[1] += y * u0.y; acc[2] += y * u0.z; acc[3] += y * u0.w;
            }
            __syncthreads();
        }
        #pragma unroll
        for (int t = 0; t < 4; t++)
            g_HGT[(size_t)b * 3072 + (8 + cb * 4 + t) * 128 + krow] = acc[t];
    }
}

// ================= mega GEMM (3xTF32 precise) =================
__global__ __launch_bounds__(128)
void mega_gemm(const float* __restrict__ P, const float* __restrict__ Q,
               float* __restrict__ Out)
{
    __shared__ float buf[4 * TILE_F];
    const int m0 = blockIdx.x * 64;
    const int q0 = blockIdx.y * 64;
    float c[2][4][4] = {};
    tile_gemm<true>(P + (size_t)m0 * 128, Q + (size_t)q0 * 128, 128, 128, c,
                    buf, buf + 2 * TILE_F);
    __syncthreads();

    const int tid = threadIdx.x;
    const int lane = tid & 31, wid = tid >> 5;
    const int wm = wid & 1, wn = wid >> 1;
    #pragma unroll
    for (int mt = 0; mt < 2; mt++)
        #pragma unroll
        for (int nt = 0; nt < 4; nt++)
            #pragma unroll
            for (int k = 0; k < 4; k++) {
                int p = wm * 32 + mt * 16 + (lane >> 2) + (k >> 1) * 8;
                int q = wn * 32 + nt * 8 + (lane & 3) * 2 + (k & 1);
                buf[p * 68 + q] = c[mt][nt][k];
            }
    __syncthreads();
    #pragma unroll 4
    for (int i = 0; i < 32; i++) {
        int idx = i * 128 + tid;
        int p = idx & 63, q = idx >> 6;
        Out[(size_t)(q0 + q) * 128 + m0 + p] = buf[p * 68 + q];
    }
}

// ================= K3: Hv, D, Hvest, soft-threshold =================
__global__ __launch_bounds__(256)
void k3_kernel(const float* __restrict__ sigma2,
               const float* __restrict__ rUt, const float* __restrict__ iUt,
               const float* __restrict__ tao_p, const float* __restrict__ eps_p)
{
    __shared__ float sTc[24 * 128];
    __shared__ float sEF[128];
    __shared__ float sUt[128];
    __shared__ float sHv[1024];
    __shared__ float sHve[1024];

    const int b = blockIdx.x;
    const int tid = threadIdx.x;
    const float tao = tao_p[0];

    for (int i = tid; i < 3072; i += 256) sTc[i] = g_T[(size_t)b * 3072 + i];
    if (tid < 128) {
        sEF[tid] = g_EF[(size_t)b * 128 + tid];
        sUt[tid] = (tid < 64) ? rUt[tid] : iUt[tid - 64];
    }
    __syncthreads();

    {
        const int r = tid >> 1, c0 = (tid & 1) * 4;
        #pragma unroll
        for (int c = c0; c < c0 + 4; c++) {
            float acc = 0.f;
            if (r < 64) {
                #pragma unroll
                for (int k = 0; k < 8; k++)
                    acc += sTc[k * 128 + r] * sUt[k * 8 + c] - sTc[k * 128 + 64 + r] * sUt[64 + k * 8 + c];
            } else {
                #pragma unroll
                for (int k = 0; k < 8; k++)
                    acc += sTc[k * 128 + r] * sUt[k * 8 + c] + sTc[k * 128 + r - 64] * sUt[64 + k * 8 + c];
            }
            sHv[r * 8 + c] = acc;
        }
    }
    __syncthreads();

    {
        const int r = tid >> 1, t0 = (tid & 1) * 4;
        #pragma unroll
        for (int t = t0; t < t0 + 4; t++) {
            float s = 0.f;
            if (r < 64) {
                #pragma unroll
                for (int k = 0; k < 8; k++)
                    s += sHv[r * 8 + k] * sEF[k * 8 + t] + sHv[(64 + r) * 8 + k] * sEF[64 + k * 8 + t];
                s -= sTc[(8 + t) * 128 + r] + sTc[(16 + t) * 128 + 64 + r];
            } else {
                int r2 = r - 64;
                #pragma unroll
                for (int k = 0; k < 8; k++)
                    s += sHv[r * 8 + k] * sEF[k * 8 + t] - sHv[r2 * 8 + k] * sEF[64 + k * 8 + t];
                s -= sTc[(8 + t) * 128 + r] - sTc[(16 + t) * 128 + r2];
            }
            sHve[r * 8 + t] = sHv[r * 8 + t] - tao * s;
        }
    }
    __syncthreads();

    {
        float thr = tao * eps_p[0] * sigma2[b];
        for (int e = tid; e < 512; e += 256) {
            float re = sHve[e], im = sHve[e + 512];
            float mag = sqrtf(re * re + im * im);
            float s = fmaxf(mag - thr, 0.f) / mag;
            sHve[e] = re * s;
            sHve[e + 512] = im * s;
        }
    }
    __syncthreads();

    for (int i = tid; i < 1024; i += 256) {
        int c = i >> 7, r = i & 127;
        g_HveT[(size_t)b * 1024 + i] = sHve[r * 8 + c];
    }
}

// ================= K5: H_new, W, WTW, F (512 thr) =================
__global__ __launch_bounds__(512)
void k5_kernel(const float* __restrict__ X, const float* __restrict__ Y,
               const float* __restrict__ lambda_W,
               const float* __restrict__ rUt, const float* __restrict__ iUt,
               const float* __restrict__ factor_p,
               float* __restrict__ out_Hnew, float* __restrict__ out_lamW)
{
    __shared__ float sUc[1024];
    __shared__ float sUt[128];
    __shared__ float sHN[1024];
    __shared__ float sW[2048];
    __shared__ float sWTW[256];
    __shared__ float sCh[2][2048];

    const int b = blockIdx.x;
    const int tid = threadIdx.x;

    // kick off Y round 0: 512 cp16 = 16 rows x 32 segs
    const float* Yb = Y + (size_t)b * 128 * LD;
    const uint32_t chBase = smem_to_u32(sCh);
    {
        int row = tid >> 5, seg = tid & 31;
        cp16(chBase + (uint32_t)(row * 128 + seg * 4) * 4, Yb + row * 128 + seg * 4);
    }
    CP_COMMIT();

    for (int i = tid; i < 1024; i += 512) sUc[i] = g_UrHvT[(size_t)b * 1024 + i];
    if (tid < 128) sUt[tid] = (tid < 64) ? rUt[tid] : iUt[tid - 64];
    __syncthreads();

    // H_new = blkb(UrHv) @ UtT2 ; r = tid>>2, 2 cols each
    {
        const int r = tid >> 2, c0 = (tid & 3) * 2;
        #pragma unroll
        for (int c = c0; c < c0 + 2; c++) {
            float acc = 0.f;
            if (r < 64) {
                #pragma unroll
                for (int k = 0; k < 8; k++)
                    acc += sUc[k * 128 + r] * sUt[c * 8 + k] + sUc[k * 128 + 64 + r] * sUt[64 + c * 8 + k];
            } else {
                #pragma unroll
                for (int k = 0; k < 8; k++)
                    acc += sUc[k * 128 + r] * sUt[c * 8 + k] - sUc[k * 128 + r - 64] * sUt[64 + c * 8 + k];
            }
            sHN[r * 8 + c] = acc;
            out_Hnew[(size_t)b * 1024 + r * 8 + c] = acc;
        }
    }
    __syncthreads();

    for (int e = tid; e < 2048; e += 512) {
        int r = e >> 4, i = e & 15;
        float v;
        if (r < 64) v = (i < 8) ? sHN[r * 8 + i] : -sHN[(64 + r) * 8 + (i - 8)];
        else        v = (i < 8) ? sHN[r * 8 + i] : sHN[(r - 64) * 8 + (i - 8)];
        sW[e] = v;
    }
    __syncthreads();

    if (tid < 256) {
        int i = tid >> 4, j = tid & 15;
        float acc = 0.f;
        #pragma unroll 4
        for (int r = 0; r < 128; r++) acc += sW[r * 16 + i] * sW[r * 16 + j];
        sWTW[tid] = acc;
    }
    __syncthreads();

    // F: l = tid&127, ih = tid>>7 (4 groups of 4 i each)
    {
        float lamW = factor_p[0] * lambda_W[b];
        const float* Xb = X + (size_t)b * 16 * LD;
        float* Fb = g_F + (size_t)b * NN;
        const int l = tid & 127, ih = tid >> 7;
        float acc[4] = {};
        for (int rc = 0; rc < 8; rc++) {
            if (rc + 1 < 8) {
                uint32_t off = (uint32_t)(((rc + 1) & 1) * 2048) * 4;
                const float* src = Yb + (rc + 1) * 16 * 128;
                int row = tid >> 5, seg = tid & 31;
                cp16(chBase + off + (uint32_t)(row * 128 + seg * 4) * 4,
                     src + row * 128 + seg * 4);
                CP_COMMIT();
                CP_WAIT1();
            } else {
                CP_WAIT0();
            }
            __syncthreads();
            const float* Ch = sCh[rc & 1];
            #pragma unroll
            for (int r = 0; r < 16; r++) {
                float y = Ch[r * 128 + l];
                float4 w0 = *(const float4*)&sW[(rc * 16 + r) * 16 + ih * 4];
                acc[0] += w0.x * y; acc[1] += w0.y * y; acc[2] += w0.z * y; acc[3] += w0.w * y;
            }
            __syncthreads();
        }
        float xv[16];
        #pragma unroll
        for (int j = 0; j < 16; j++) xv[j] = Xb[j * 128 + l];
        #pragma unroll
        for (int q = 0; q < 4; q++) {
            int i = ih * 4 + q;
            float v = acc[q] + lamW * xv[i];
            #pragma unroll
            for (int j = 0; j < 16; j++) v -= sWTW[i * 16 + j] * xv[j];
            int n = l * 16 + (i & 7) * 2 + (i >> 3);
            Fb[n] = 2.f * lamW - 2.f * SQ2F * v;
        }
        if (tid == 0) out_lamW[b] = lamW;
    }
}

// ================= split-K MMA GEMM1: partial C[b,n] =================
__global__ __launch_bounds__(128)
void mma_gemm1(float* __restrict__ dummy)
{
    __shared__ float sP[2 * TILE_F];
    __shared__ float sQ[2 * TILE_F];
    const int n0 = blockIdx.x * 64, b0 = blockIdx.y * 64, kh = blockIdx.z;
    float c[2][4][4] = {};
    tile_gemm<false>(g_Vs + (size_t)b0 * MM + kh * 512,
                     g_AT + (size_t)n0 * MM + kh * 512, MM, 512, c, sP, sQ);

    float* Cp = g_C1 + (size_t)kh * BSZ * NN;
    const int lane = threadIdx.x & 31, wid = threadIdx.x >> 5;
    const int wm = wid & 1, wn = wid >> 1;
    #pragma unroll
    for (int mt = 0; mt < 2; mt++)
        #pragma unroll
        for (int rr = 0; rr < 2; rr++) {
            const int b = b0 + wm * 32 + mt * 16 + (lane >> 2) + rr * 8;
            float* Cb = Cp + (size_t)b * NN;
            #pragma unroll
            for (int nt = 0; nt < 4; nt++) {
                const int n = n0 + wn * 32 + nt * 8 + (lane & 3) * 2;
                *(float2*)(Cb + n) = make_float2(c[mt][nt][rr * 2 + 0],
                                                 c[mt][nt][rr * 2 + 1]);
            }
        }
    (void)dummy;
}

// ================= epi1: combine partials -> u_new =================
__global__ void epi1_kernel(const float* __restrict__ La, const float* __restrict__ lamWv,
                            const float* __restrict__ rho_p, const float* __restrict__ kappa_p,
                            float* __restrict__ out_u)
{
    int idx = blockIdx.x * blockDim.x + threadIdx.x;
    if (idx >= BSZ * NN / 4) return;
    float4 p0 = ((const float4*)g_C1)[idx];
    float4 p1 = ((const float4*)(g_C1 + (size_t)BSZ * NN))[idx];
    int e4 = idx * 4;
    int b = e4 >> 11, n = e4 & 2047;
    float rho = rho_p[0], kappa = kappa_p[0];
    float lamW = lamWv[b];
    float den = 4.f * lamW - 2.f * kappa;
    float4 fb = ((const float4*)g_F)[idx];
    float4 la = *(const float4*)(La + n);
    float4 u;
    u.x = fminf(fmaxf((rho * (p0.x + p1.x) + fb.x - kappa) / (rho * la.x + den), 0.f), 1.f);
    u.y = fminf(fmaxf((rho * (p0.y + p1.y) + fb.y - kappa) / (rho * la.y + den), 0.f), 1.f);
    u.z = fminf(fmaxf((rho * (p0.z + p1.z) + fb.z - kappa) / (rho * la.z + den), 0.f), 1.f);
    u.w = fminf(fmaxf((rho * (p0.w + p1.w) + fb.w - kappa) / (rho * la.w + den), 0.f), 1.f);
    ((float4*)out_u)[idx] = u;
}

// ================= split-K MMA GEMM2: partial C[b,m] =================
__global__ __launch_bounds__(128)
void mma_gemm2(const float* __restrict__ A, const float* __restrict__ u_in)
{
    __shared__ float sP[2 * TILE_F];
    __shared__ float sQ[2 * TILE_F];
    const int m0 = blockIdx.x * 64, b0 = blockIdx.y * 64, kh = blockIdx.z;
    float c[2][4][4] = {};
    tile_gemm<false>(u_in + (size_t)b0 * NN + kh * 1024,
                     A + (size_t)m0 * NN + kh * 1024, NN, 1024, c, sP, sQ);

    float* Cp = g_C2 + (size_t)kh * BSZ * MM;
    const int lane = threadIdx.x & 31, wid = threadIdx.x >> 5;
    const int wm = wid & 1, wn = wid >> 1;
    #pragma unroll
    for (int mt = 0; mt < 2; mt++)
        #pragma unroll
        for (int rr = 0; rr < 2; rr++) {
            const int b = b0 + wm * 32 + mt * 16 + (lane >> 2) + rr * 8;
            float* Cb = Cp + (size_t)b * MM;
            #pragma unroll
            for (int nt = 0; nt < 4; nt++) {
                const int m = m0 + wn * 32 + nt * 8 + (lane & 3) * 2;
                *(float2*)(Cb + m) = make_float2(c[mt][nt][rr * 2 + 0],
                                                 c[mt][nt][rr * 2 + 1]);
            }
        }
}

// ================= epi2: combine partials -> z_new, lambda1_new =================
__global__ void epi2_kernel(const float* __restrict__ theta, const float* __restrict__ z_old,
                            const float* __restrict__ l1_old, const float* __restrict__ relax_p,
                            const float* __restrict__ acc_p,
                            float* __restrict__ out_z, float* __restrict__ out_l1)
{
    int idx = blockIdx.x * blockDim.x + threadIdx.x;
    if (idx >= BSZ * MM / 4) return;
    float4 p0 = ((const float4*)g_C2)[idx];
    float4 p1 = ((const float4*)(g_C2 + (size_t)BSZ * MM))[idx];
    int e4 = idx * 4;
    int m = e4 & 1023;
    float relax = relax_p[0], acc = acc_p[0];
    float4 th = *(const float4*)(theta + m);
    float4 zo = ((const float4*)z_old)[idx];
    float4 lo = ((const float4*)l1_old)[idx];
    float4 zn, ln;
    #define DO(comp) { \
        float ct = p0.comp + p1.comp; \
        float zt = th.comp - relax * ct - (1.f - relax) * (th.comp - zo.comp) - lo.comp; \
        float z1 = fmaxf(zt, 0.f); \
        float l1v = z1 - zt; \
        zn.comp = z1 + acc * (z1 - zo.comp); \
        ln.comp = l1v + acc * (l1v - lo.comp); }
    DO(x) DO(y) DO(z) DO(w)
    #undef DO
    ((float4*)out_z)[idx] = zn;
    ((float4*)out_l1)[idx] = ln;
}

// ================= K4: X_new / XXp_new / acc_new =================
__global__ void x_kernel(const float* __restrict__ u_new, const float* __restrict__ rXp,
                         const float* __restrict__ iXp, const float* __restrict__ accnew_in,
                         float* __restrict__ out_X, float* __restrict__ out_XXp,
                         float* __restrict__ out_acc)
{
    int e = blockIdx.x * blockDim.x + threadIdx.x;
    const int total = BSZ * 16 * LT;
    if (e < total) {
        int b = e / (16 * LT);
        int rem = e - b * (16 * LT);
        int row = rem / LT, l = rem - row * LT;
        int t = row & 7, ci = row >> 3;
        float v;
        if (l < LD) {
            float u = u_new[(size_t)b * NN + l * 16 + t * 2 + ci];
            v = (1.f - 2.f * u) / SQ2F;
            out_X[(size_t)b * 16 * LD + row * LD + l] = v;
        } else {
            int lp = l - LD;
            v = (ci == 0) ? rXp[(size_t)b * NT * LP + t * LP + lp]
                          : iXp[(size_t)b * NT * LP + t * LP + lp];
        }
        out_XXp[e] = v;
    }
    if (e == 0) out_acc[0] = accnew_in[0];
}

// ================= launch =================
extern "C" void kernel_launch(void* const* d_in, const int* in_sizes, int n_in,
                              void* d_out, int out_size) {
    (void)in_sizes; (void)n_in; (void)out_size;
    const float* sigma2   = (const float*)d_in[0];
    const float* X        = (const float*)d_in[1];
    const float* XXp      = (const float*)d_in[2];
    const float* Y        = (const float*)d_in[3];
    const float* YYp      = (const float*)d_in[4];
    const float* rXp      = (const float*)d_in[5];
    const float* iXp      = (const float*)d_in[6];
    const float* H        = (const float*)d_in[7];
    const float* lambda_W = (const float*)d_in[8];
    const float* z        = (const float*)d_in[10];
    const float* lambda1  = (const float*)d_in[11];
    const float* acc_new  = (const float*)d_in[12];
    const float* A        = (const float*)d_in[13];
    const float* Lambda_A = (const float*)d_in[14];
    const float* theta    = (const float*)d_in[15];
    const float* rUr      = (const float*)d_in[16];
    const float* iUr      = (const float*)d_in[17];
    const float* rUt      = (const float*)d_in[18];
    const float* iUt      = (const float*)d_in[19];
    const float* rho      = (const float*)d_in[20];
    const float* kappa    = (const float*)d_in[21];
    const float* epsilon  = (const float*)d_in[22];
    const float* tao      = (const float*)d_in[23];
    const float* factor   = (const float*)d_in[24];
    const float* relax    = (const float*)d_in[25];
    const float* acc      = (const float*)d_in[26];

    float* out = (float*)d_out;
    float* out_X    = out;
    float* out_XXp  = out + 1048576;
    float* out_H    = out + 2228224;
    float* out_lamW = out + 2752512;
    float* out_u    = out + 2753024;
    float* out_z    = out + 3801600;
    float* out_l1   = out + 4325888;
    float* out_acc  = out + 4850176;

    float* dg_Ur, *dg_UrT, *dg_HGT, *dg_T, *dg_HveT, *dg_UrHvT;
    cudaGetSymbolAddress((void**)&dg_Ur, g_Ur);
    cudaGetSymbolAddress((void**)&dg_UrT, g_UrT);
    cudaGetSymbolAddress((void**)&dg_HGT, g_HGT);
    cudaGetSymbolAddress((void**)&dg_T, g_T);
    cudaGetSymbolAddress((void**)&dg_HveT, g_HveT);
    cudaGetSymbolAddress((void**)&dg_UrHvT, g_UrHvT);

    const_kernel<<<64, 256>>>(rUr, iUr);
    v_kernel<<<(BSZ * MM + 255) / 256, 256>>>(theta, z, lambda1);
    at_kernel<<<dim3(64, 32), dim3(32, 8)>>>(A);
    k1a_kernel<<<BSZ, 512>>>(XXp, YYp, H, rUt, iUt);
    mega_gemm<<<dim3(2, BSZ * 24 / 64), 128>>>(dg_UrT, dg_HGT, dg_T);
    k3_kernel<<<BSZ, 256>>>(sigma2, rUt, iUt, tao, epsilon);
    mega_gemm<<<dim3(2, BSZ * 8 / 64), 128>>>(dg_Ur, dg_HveT, dg_UrHvT);
    k5_kernel<<<BSZ, 512>>>(X, Y, lambda_W, rUt, iUt, factor, out_H, out_lamW);
    mma_gemm1<<<dim3(NN / 64, BSZ / 64, 2), 128>>>(nullptr);
    epi1_kernel<<<(BSZ * NN / 4 + 255) / 256, 256>>>(Lambda_A, out_lamW, rho, kappa, out_u);
    mma_gemm2<<<dim3(MM / 64, BSZ / 64, 2), 128>>>(A, out_u);
    epi2_kernel<<<(BSZ * MM / 4 + 255) / 256, 256>>>(theta, z, lambda1, relax, acc,
                                                     out_z, out_l1);
    x_kernel<<<(BSZ * 16 * LT + 255) / 256, 256>>>(out_u, rXp, iXp, acc_new,
                                                   out_X, out_XXp, out_acc);
}

// round 9
// speedup vs baseline: 6.4979x; 1.0476x over previous
#include <cuda_runtime.h>
#include <cuda_bf16.h>
#include <math.h>
#include <stdint.h>

// Problem constants
#define NR 64
#define NT 8
#define LD 128
#define LP 16
#define LT 144          // LD + LP
#define BSZ 512
#define MM 1024
#define NN 2048         // LDPC_N

#define SQ2F 1.41421356237309504880f

// -------- scratch (device globals; no runtime allocation) --------
__device__ float g_Ur[128 * 128];
__device__ float g_UrT[128 * 128];
__device__ float g_F[BSZ * NN];       // fbres permuted: [b][n]
__device__ float g_Vs[BSZ * MM];      // theta - z - lambda1
__device__ float g_AT[NN * MM];       // A^T
__device__ float g_HGT[BSZ * 24 * 128];
__device__ float g_T[BSZ * 24 * 128];
__device__ float g_EF[BSZ * 128];
__device__ float g_HveT[BSZ * 8 * 128];
__device__ float g_UrHvT[BSZ * 8 * 128];
__device__ float g_C1[2 * BSZ * NN];  // split-K partials for gemm1
__device__ float g_C2[2 * BSZ * MM];  // split-K partials for gemm2

// ================= mma.sync helpers =================
__device__ __forceinline__ uint32_t smem_to_u32(const void* smem_ptr) {
    uint32_t addr;
    asm("{ .reg .u64 tmp; cvta.to.shared.u64 tmp, %1; cvt.u32.u64 %0, tmp; }"
        : "=r"(addr) : "l"(smem_ptr));
    return addr;
}

__device__ __forceinline__ void cp16(uint32_t s, const float* g) {
    asm volatile("cp.async.cg.shared.global [%0], [%1], 16;" :: "r"(s), "l"(g) : "memory");
}
#define CP_COMMIT() asm volatile("cp.async.commit_group;" ::: "memory")
#define CP_WAIT1()  asm volatile("cp.async.wait_group 1;" ::: "memory")
#define CP_WAIT0()  asm volatile("cp.async.wait_group 0;" ::: "memory")

__device__ __forceinline__ uint32_t f2tf(float f) {
    uint32_t r;
    asm("cvt.rna.tf32.f32 %0, %1;" : "=r"(r) : "f"(f));
    return r;
}

__device__ __forceinline__ void mma_tf32(float* c, const uint32_t* a, const uint32_t* b) {
    asm volatile(
        "mma.sync.aligned.m16n8k8.row.col.f32.tf32.tf32.f32 "
        "{%0,%1,%2,%3}, {%4,%5,%6,%7}, {%8,%9}, {%0,%1,%2,%3};"
        : "+f"(c[0]), "+f"(c[1]), "+f"(c[2]), "+f"(c[3])
        : "r"(a[0]), "r"(a[1]), "r"(a[2]), "r"(a[3]), "r"(b[0]), "r"(b[1]));
}

// ---- shared tile mainloop: C[64x64] += P[64,klen] * Q[64,klen]^T, row stride ld ----
#define TILE_F (64 * 20)
template<bool PRECISE>
__device__ __forceinline__ void tile_gemm(const float* __restrict__ Pg0,
                                          const float* __restrict__ Qg0,
                                          int ld, int klen, float c[2][4][4],
                                          float* sP, float* sQ)
{
    const int tid = threadIdx.x;
    const int lane = tid & 31, wid = tid >> 5;
    const int wm = wid & 1, wn = wid >> 1;
    const int lrow = tid >> 2, lquad = tid & 3;

    uint32_t sPb = smem_to_u32(sP), sQb = smem_to_u32(sQ);
    const int NK = klen >> 4;
    const float* Pg = Pg0 + (size_t)lrow * ld + lquad * 4;
    const float* Qg = Qg0 + (size_t)lrow * ld + lquad * 4;
    const uint32_t spA0 = sPb + (uint32_t)(lrow * 20 + lquad * 4) * 4;
    const uint32_t spA1 = sPb + (uint32_t)((lrow + 32) * 20 + lquad * 4) * 4;
    const uint32_t sqA0 = sQb + (uint32_t)(lrow * 20 + lquad * 4) * 4;
    const uint32_t sqA1 = sQb + (uint32_t)((lrow + 32) * 20 + lquad * 4) * 4;

    {
        const float* p = Pg;  const float* q = Qg;
        cp16(spA0, p); cp16(spA1, p + (size_t)32 * ld);
        cp16(sqA0, q); cp16(sqA1, q + (size_t)32 * ld);
        CP_COMMIT();
        p = Pg + 16; q = Qg + 16;
        uint32_t off = TILE_F * 4;
        cp16(spA0 + off, p); cp16(spA1 + off, p + (size_t)32 * ld);
        cp16(sqA0 + off, q); cp16(sqA1 + off, q + (size_t)32 * ld);
        CP_COMMIT();
    }

    const int arow = lane >> 2, acol = lane & 3;
    for (int kt = 0; kt < NK; kt++) {
        CP_WAIT1();
        __syncthreads();
        const float* Pbuf = sP + (kt & 1) * TILE_F;
        const float* Qbuf = sQ + (kt & 1) * TILE_F;
        #pragma unroll
        for (int ks = 0; ks < 2; ks++) {
            const int k0 = ks * 8 + acol;
            uint32_t a[2][4], bq[4][2];
            uint32_t al[2][4], bl[4][2];
            #pragma unroll
            for (int mt = 0; mt < 2; mt++) {
                const int m = wm * 32 + mt * 16 + arow;
                float v0 = Pbuf[m * 20 + k0];
                float v1 = Pbuf[(m + 8) * 20 + k0];
                float v2 = Pbuf[m * 20 + k0 + 4];
                float v3 = Pbuf[(m + 8) * 20 + k0 + 4];
                a[mt][0] = f2tf(v0); a[mt][1] = f2tf(v1);
                a[mt][2] = f2tf(v2); a[mt][3] = f2tf(v3);
                if (PRECISE) {
                    al[mt][0] = f2tf(v0 - __uint_as_float(a[mt][0]));
                    al[mt][1] = f2tf(v1 - __uint_as_float(a[mt][1]));
                    al[mt][2] = f2tf(v2 - __uint_as_float(a[mt][2]));
                    al[mt][3] = f2tf(v3 - __uint_as_float(a[mt][3]));
                }
            }
            #pragma unroll
            for (int nt = 0; nt < 4; nt++) {
                const int n = wn * 32 + nt * 8 + arow;
                float w0 = Qbuf[n * 20 + k0];
                float w1 = Qbuf[n * 20 + k0 + 4];
                bq[nt][0] = f2tf(w0); bq[nt][1] = f2tf(w1);
                if (PRECISE) {
                    bl[nt][0] = f2tf(w0 - __uint_as_float(bq[nt][0]));
                    bl[nt][1] = f2tf(w1 - __uint_as_float(bq[nt][1]));
                }
            }
            #pragma unroll
            for (int mt = 0; mt < 2; mt++)
                #pragma unroll
                for (int nt = 0; nt < 4; nt++) {
                    if (PRECISE) {
                        mma_tf32(c[mt][nt], a[mt], bl[nt]);
                        mma_tf32(c[mt][nt], al[mt], bq[nt]);
                    }
                    mma_tf32(c[mt][nt], a[mt], bq[nt]);
                }
        }
        __syncthreads();
        if (kt + 2 < NK) {
            uint32_t off = (uint32_t)((kt & 1) * TILE_F) * 4;
            const float* p = Pg + (kt + 2) * 16;
            const float* q = Qg + (kt + 2) * 16;
            cp16(spA0 + off, p); cp16(spA1 + off, p + (size_t)32 * ld);
            cp16(sqA0 + off, q); cp16(sqA1 + off, q + (size_t)32 * ld);
        }
        CP_COMMIT();
    }
    CP_WAIT0();
}

// ================= K0: build Ur / UrT =================
__global__ void const_kernel(const float* __restrict__ rUr, const float* __restrict__ iUr) {
    int e = blockIdx.x * blockDim.x + threadIdx.x;
    if (e >= 128 * 128) return;
    int i = e >> 7, j = e & 127;
    float v, vt;
    if (i < 64) v = (j < 64) ? rUr[i * 64 + j] : -iUr[i * 64 + (j - 64)];
    else        v = (j < 64) ? iUr[(i - 64) * 64 + j] : rUr[(i - 64) * 64 + (j - 64)];
    g_Ur[e] = v;
    if (i < 64) vt = (j < 64) ? rUr[j * 64 + i] : iUr[(j - 64) * 64 + i];
    else        vt = (j < 64) ? -iUr[j * 64 + (i - 64)] : rUr[(j - 64) * 64 + (i - 64)];
    g_UrT[e] = vt;
}

// ================= K_v: V = theta - z - lambda1 =================
__global__ void v_kernel(const float* __restrict__ theta, const float* __restrict__ z,
                         const float* __restrict__ l1) {
    int e = blockIdx.x * blockDim.x + threadIdx.x;
    if (e < BSZ * MM) {
        int m = e & (MM - 1);
        g_Vs[e] = theta[m] - z[e] - l1[e];
    }
}

// ================= K_at: g_AT[n][m] = A[m][n] =================
__global__ void at_kernel(const float* __restrict__ A) {
    __shared__ float t[32][33];
    int n0 = blockIdx.x * 32, m0 = blockIdx.y * 32;
    int tx = threadIdx.x, ty = threadIdx.y;
    #pragma unroll
    for (int q = 0; q < 4; q++)
        t[ty + 8 * q][tx] = A[(size_t)(m0 + ty + 8 * q) * NN + n0 + tx];
    __syncthreads();
    #pragma unroll
    for (int q = 0; q < 4; q++)
        g_AT[(size_t)(n0 + ty + 8 * q) * MM + m0 + tx] = t[tx][ty + 8 * q];
}

// ================= K1a: per-batch front phases (256 thr, mma G) =================
__global__ __launch_bounds__(256)
void k1a_kernel(const float* __restrict__ XXp, const float* __restrict__ YYp,
                const float* __restrict__ H,
                const float* __restrict__ rUt, const float* __restrict__ iUt)
{
    __shared__ float sXXp[16 * LT];
    __shared__ float sUtXT[LT * 16];
    __shared__ float sS[256];
    __shared__ float sCh2[2][128 * 20];
    __shared__ float sUt[128];

    const int b = blockIdx.x;
    const int tid = threadIdx.x;

    const float* XXpb = XXp + (size_t)b * 16 * LT;
    for (int i = tid; i < 16 * LT; i += 256) sXXp[i] = XXpb[i];
    if (tid < 128) sUt[tid] = (tid < 64) ? rUt[tid] : iUt[tid - 64];

    // kick off YYp chunk 0: 512 cp16 = 128 rows x 4 segs (2 per thread)
    const float* YYpb = YYp + (size_t)b * 128 * LT;
    const uint32_t chBase = smem_to_u32(sCh2);
    #pragma unroll
    for (int q = 0; q < 2; q++) {
        int idx = q * 256 + tid;
        int row = idx >> 2, seg = idx & 3;
        cp16(chBase + (uint32_t)(row * 20 + seg * 4) * 4, YYpb + row * LT + seg * 4);
    }
    CP_COMMIT();
    __syncthreads();

    // UtXT[l][i] = (UtT @ XXp)[i][l]
    for (int e = tid; e < 16 * LT; e += 256) {
        int i = e & 15, l = e >> 4;
        float acc = 0.f;
        if (i < 8) {
            #pragma unroll
            for (int k = 0; k < 8; k++) {
                acc += sUt[k * 8 + i] * sXXp[k * LT + l];
                acc += sUt[64 + k * 8 + i] * sXXp[(8 + k) * LT + l];
            }
        } else {
            int i2 = i - 8;
            #pragma unroll
            for (int k = 0; k < 8; k++) {
                acc -= sUt[64 + k * 8 + i2] * sXXp[k * LT + l];
                acc += sUt[k * 8 + i2] * sXXp[(8 + k) * LT + l];
            }
        }
        sUtXT[l * 16 + i] = acc;
    }
    __syncthreads();

    // Gram S
    {
        int i = tid >> 4, j = tid & 15;
        float acc = 0.f;
        #pragma unroll 4
        for (int l = 0; l < LT; l++) acc += sUtXT[l * 16 + i] * sUtXT[l * 16 + j];
        sS[tid] = acc;
    }
    __syncthreads();

    if (tid < 128) {
        int q = tid & 63, k = q >> 3, t = q & 7;
        float v;
        if (tid < 64) v = sS[k * 16 + t] + sS[(8 + k) * 16 + 8 + t];
        else          v = sS[k * 16 + 8 + t] - sS[(8 + k) * 16 + t];
        g_EF[(size_t)b * 128 + tid] = v;
    }

    // H transposed -> g_HGT cols 0..7 (coalesced)
    {
        const float* Hb = H + (size_t)b * 1024;
        for (int e = tid; e < 1024; e += 256) {
            int c = e >> 7, k = e & 127;
            g_HGT[(size_t)b * 3072 + e] = Hb[k * 8 + c];
        }
    }

    // G^T[i][krow] = sum_l UtX[i][l] * YYp[krow][l]  via 3xTF32 mma
    // m=16 (i), n=128 (krow, 16 tiles of 8, 8 warps x 2 tiles), k=144 (l)
    {
        const int lane = tid & 31, w = tid >> 5;
        const int arow = lane >> 2, acol = lane & 3;
        float cg[2][4] = {};
        for (int lc = 0; lc < 9; lc++) {
            if (lc + 1 < 9) {
                uint32_t off = (uint32_t)(((lc + 1) & 1) * (128 * 20)) * 4;
                int l0n = (lc + 1) * 16;
                #pragma unroll
                for (int q = 0; q < 2; q++) {
                    int idx = q * 256 + tid;
                    int row = idx >> 2, seg = idx & 3;
                    cp16(chBase + off + (uint32_t)(row * 20 + seg * 4) * 4,
                         YYpb + row * LT + l0n + seg * 4);
                }
                CP_COMMIT();
                CP_WAIT1();
            } else {
                CP_WAIT0();
            }
            __syncthreads();
            const float* Ch = sCh2[lc & 1];
            #pragma unroll
            for (int ks = 0; ks < 2; ks++) {
                const int kg = lc * 16 + ks * 8 + acol;
                float av0 = sUtXT[kg * 16 + arow];
                float av1 = sUtXT[kg * 16 + arow + 8];
                float av2 = sUtXT[(kg + 4) * 16 + arow];
                float av3 = sUtXT[(kg + 4) * 16 + arow + 8];
                uint32_t ah[4] = {f2tf(av0), f2tf(av1), f2tf(av2), f2tf(av3)};
                uint32_t al[4] = {f2tf(av0 - __uint_as_float(ah[0])),
                                  f2tf(av1 - __uint_as_float(ah[1])),
                                  f2tf(av2 - __uint_as_float(ah[2])),
                                  f2tf(av3 - __uint_as_float(ah[3]))};
                #pragma unroll
                for (int nt = 0; nt < 2; nt++) {
                    const int n = (w * 2 + nt) * 8 + arow;
                    float bv0 = Ch[n * 20 + ks * 8 + acol];
                    float bv1 = Ch[n * 20 + ks * 8 + acol + 4];
                    uint32_t bh[2] = {f2tf(bv0), f2tf(bv1)};
                    uint32_t bl[2] = {f2tf(bv0 - __uint_as_float(bh[0])),
                                      f2tf(bv1 - __uint_as_float(bh[1]))};
                    mma_tf32(cg[nt], ah, bl);
                    mma_tf32(cg[nt], al, bh);
                    mma_tf32(cg[nt], ah, bh);
                }
            }
            __syncthreads();
        }
        float* dst = g_HGT + (size_t)b * 3072;
        #pragma unroll
        for (int nt = 0; nt < 2; nt++) {
            const int col = (w * 2 + nt) * 8 + (lane & 3) * 2;
            *(float2*)(dst + (8 + arow) * 128 + col) = make_float2(cg[nt][0], cg[nt][1]);
            *(float2*)(dst + (16 + arow) * 128 + col) = make_float2(cg[nt][2], cg[nt][3]);
        }
    }
}

// ================= mega GEMM (3xTF32 precise) =================
__global__ __launch_bounds__(128)
void mega_gemm(const float* __restrict__ P, const float* __restrict__ Q,
               float* __restrict__ Out)
{
    __shared__ float buf[4 * TILE_F];
    const int m0 = blockIdx.x * 64;
    const int q0 = blockIdx.y * 64;
    float c[2][4][4] = {};
    tile_gemm<true>(P + (size_t)m0 * 128, Q + (size_t)q0 * 128, 128, 128, c,
                    buf, buf + 2 * TILE_F);
    __syncthreads();

    const int tid = threadIdx.x;
    const int lane = tid & 31, wid = tid >> 5;
    const int wm = wid & 1, wn = wid >> 1;
    #pragma unroll
    for (int mt = 0; mt < 2; mt++)
        #pragma unroll
        for (int nt = 0; nt < 4; nt++)
            #pragma unroll
            for (int k = 0; k < 4; k++) {
                int p = wm * 32 + mt * 16 + (lane >> 2) + (k >> 1) * 8;
                int q = wn * 32 + nt * 8 + (lane & 3) * 2 + (k & 1);
                buf[p * 68 + q] = c[mt][nt][k];
            }
    __syncthreads();
    #pragma unroll 4
    for (int i = 0; i < 32; i++) {
        int idx = i * 128 + tid;
        int p = idx & 63, q = idx >> 6;
        Out[(size_t)(q0 + q) * 128 + m0 + p] = buf[p * 68 + q];
    }
}

// ================= K3: Hv, D, Hvest, soft-threshold =================
__global__ __launch_bounds__(256)
void k3_kernel(const float* __restrict__ sigma2,
               const float* __restrict__ rUt, const float* __restrict__ iUt,
               const float* __restrict__ tao_p, const float* __restrict__ eps_p)
{
    __shared__ float sTc[24 * 128];
    __shared__ float sEF[128];
    __shared__ float sUt[128];
    __shared__ float sHv[1024];
    __shared__ float sHve[1024];

    const int b = blockIdx.x;
    const int tid = threadIdx.x;
    const float tao = tao_p[0];

    for (int i = tid; i < 3072; i += 256) sTc[i] = g_T[(size_t)b * 3072 + i];
    if (tid < 128) {
        sEF[tid] = g_EF[(size_t)b * 128 + tid];
        sUt[tid] = (tid < 64) ? rUt[tid] : iUt[tid - 64];
    }
    __syncthreads();

    {
        const int r = tid >> 1, c0 = (tid & 1) * 4;
        #pragma unroll
        for (int c = c0; c < c0 + 4; c++) {
            float acc = 0.f;
            if (r < 64) {
                #pragma unroll
                for (int k = 0; k < 8; k++)
                    acc += sTc[k * 128 + r] * sUt[k * 8 + c] - sTc[k * 128 + 64 + r] * sUt[64 + k * 8 + c];
            } else {
                #pragma unroll
                for (int k = 0; k < 8; k++)
                    acc += sTc[k * 128 + r] * sUt[k * 8 + c] + sTc[k * 128 + r - 64] * sUt[64 + k * 8 + c];
            }
            sHv[r * 8 + c] = acc;
        }
    }
    __syncthreads();

    {
        const int r = tid >> 1, t0 = (tid & 1) * 4;
        #pragma unroll
        for (int t = t0; t < t0 + 4; t++) {
            float s = 0.f;
            if (r < 64) {
                #pragma unroll
                for (int k = 0; k < 8; k++)
                    s += sHv[r * 8 + k] * sEF[k * 8 + t] + sHv[(64 + r) * 8 + k] * sEF[64 + k * 8 + t];
                s -= sTc[(8 + t) * 128 + r] + sTc[(16 + t) * 128 + 64 + r];
            } else {
                int r2 = r - 64;
                #pragma unroll
                for (int k = 0; k < 8; k++)
                    s += sHv[r * 8 + k] * sEF[k * 8 + t] - sHv[r2 * 8 + k] * sEF[64 + k * 8 + t];
                s -= sTc[(8 + t) * 128 + r] - sTc[(16 + t) * 128 + r2];
            }
            sHve[r * 8 + t] = sHv[r * 8 + t] - tao * s;
        }
    }
    __syncthreads();

    {
        float thr = tao * eps_p[0] * sigma2[b];
        for (int e = tid; e < 512; e += 256) {
            float re = sHve[e], im = sHve[e + 512];
            float mag = sqrtf(re * re + im * im);
            float s = fmaxf(mag - thr, 0.f) / mag;
            sHve[e] = re * s;
            sHve[e + 512] = im * s;
        }
    }
    __syncthreads();

    for (int i = tid; i < 1024; i += 256) {
        int c = i >> 7, r = i & 127;
        g_HveT[(size_t)b * 1024 + i] = sHve[r * 8 + c];
    }
}

// ================= K5: H_new, W, WTW, F via mma (512 thr) =================
#define CPAD 136
#define CHK (16 * CPAD)
__global__ __launch_bounds__(512)
void k5_kernel(const float* __restrict__ X, const float* __restrict__ Y,
               const float* __restrict__ lambda_W,
               const float* __restrict__ rUt, const float* __restrict__ iUt,
               const float* __restrict__ factor_p,
               float* __restrict__ out_Hnew, float* __restrict__ out_lamW)
{
    __shared__ float sUc[1024];
    __shared__ float sUt[128];
    __shared__ float sHN[1024];
    __shared__ float sW[128 * 24];
    __shared__ float sWTW[256];
    __shared__ float sX[2048];
    __shared__ float sCh[2][CHK];

    const int b = blockIdx.x;
    const int tid = threadIdx.x;

    // kick off Y round 0: 512 cp16 = 16 rows x 32 segs
    const float* Yb = Y + (size_t)b * 128 * LD;
    const uint32_t chBase = smem_to_u32(sCh);
    {
        int row = tid >> 5, seg = tid & 31;
        cp16(chBase + (uint32_t)(row * CPAD + seg * 4) * 4, Yb + row * 128 + seg * 4);
    }
    CP_COMMIT();

    for (int i = tid; i < 1024; i += 512) sUc[i] = g_UrHvT[(size_t)b * 1024 + i];
    {
        const float* Xb = X + (size_t)b * 16 * LD;
        for (int e = tid; e < 2048; e += 512) sX[e] = Xb[e];
    }
    if (tid < 128) sUt[tid] = (tid < 64) ? rUt[tid] : iUt[tid - 64];
    __syncthreads();

    // H_new = blkb(UrHv) @ UtT2
    {
        const int r = tid >> 2, c0 = (tid & 3) * 2;
        #pragma unroll
        for (int c = c0; c < c0 + 2; c++) {
            float acc = 0.f;
            if (r < 64) {
                #pragma unroll
                for (int k = 0; k < 8; k++)
                    acc += sUc[k * 128 + r] * sUt[c * 8 + k] + sUc[k * 128 + 64 + r] * sUt[64 + c * 8 + k];
            } else {
                #pragma unroll
                for (int k = 0; k < 8; k++)
                    acc += sUc[k * 128 + r] * sUt[c * 8 + k] - sUc[k * 128 + r - 64] * sUt[64 + c * 8 + k];
            }
            sHN[r * 8 + c] = acc;
            out_Hnew[(size_t)b * 1024 + r * 8 + c] = acc;
        }
    }
    __syncthreads();

    // W (stride 24)
    for (int e = tid; e < 2048; e += 512) {
        int r = e >> 4, i = e & 15;
        float v;
        if (r < 64) v = (i < 8) ? sHN[r * 8 + i] : -sHN[(64 + r) * 8 + (i - 8)];
        else        v = (i < 8) ? sHN[r * 8 + i] : sHN[(r - 64) * 8 + (i - 8)];
        sW[r * 24 + i] = v;
    }
    __syncthreads();

    if (tid < 256) {
        int i = tid >> 4, j = tid & 15;
        float acc = 0.f;
        #pragma unroll 4
        for (int r = 0; r < 128; r++) acc += sW[r * 24 + i] * sW[r * 24 + j];
        sWTW[tid] = acc;
    }
    __syncthreads();

    // F1 = W^T Y via 3xTF32 mma: m=16 (i), n=128 (l; 16 warps x 1 tile), k=128 (r)
    {
        const int lane = tid & 31, w = tid >> 5;
        const int arow = lane >> 2, acol = lane & 3;
        float cf[4] = {};
        for (int rc = 0; rc < 8; rc++) {
            if (rc + 1 < 8) {
                uint32_t off = (uint32_t)(((rc + 1) & 1) * CHK) * 4;
                const float* src = Yb + (rc + 1) * 16 * 128;
                int row = tid >> 5, seg = tid & 31;
                cp16(chBase + off + (uint32_t)(row * CPAD + seg * 4) * 4,
                     src + row * 128 + seg * 4);
                CP_COMMIT();
                CP_WAIT1();
            } else {
                CP_WAIT0();
            }
            __syncthreads();
            const float* Ch = sCh[rc & 1];
            #pragma unroll
            for (int ks = 0; ks < 2; ks++) {
                const int kg = rc * 16 + ks * 8 + acol;
                float av0 = sW[kg * 24 + arow];
                float av1 = sW[kg * 24 + arow + 8];
                float av2 = sW[(kg + 4) * 24 + arow];
                float av3 = sW[(kg + 4) * 24 + arow + 8];
                uint32_t ah[4] = {f2tf(av0), f2tf(av1), f2tf(av2), f2tf(av3)};
                uint32_t al[4] = {f2tf(av0 - __uint_as_float(ah[0])),
                                  f2tf(av1 - __uint_as_float(ah[1])),
                                  f2tf(av2 - __uint_as_float(ah[2])),
                                  f2tf(av3 - __uint_as_float(ah[3]))};
                const int n = w * 8 + arow;
                float bv0 = Ch[(ks * 8 + acol) * CPAD + n];
                float bv1 = Ch[(ks * 8 + acol + 4) * CPAD + n];
                uint32_t bh[2] = {f2tf(bv0), f2tf(bv1)};
                uint32_t bl[2] = {f2tf(bv0 - __uint_as_float(bh[0])),
                                  f2tf(bv1 - __uint_as_float(bh[1]))};
                mma_tf32(cf, ah, bl);
                mma_tf32(cf, al, bh);
                mma_tf32(cf, ah, bh);
            }
            __syncthreads();
        }

        // epilogue: fbres = 2λ − 2√2 (F1 + λx − WTW·x)
        float lamW = factor_p[0] * lambda_W[b];
        float* Fb = g_F + (size_t)b * NN;
        float wt0[16], wt1[16];
        #pragma unroll
        for (int j = 0; j < 16; j++) {
            wt0[j] = sWTW[arow * 16 + j];
            wt1[j] = sWTW[(arow + 8) * 16 + j];
        }
        #pragma unroll
        for (int ls = 0; ls < 2; ls++) {
            const int l = w * 8 + (lane & 3) * 2 + ls;
            float xi[16];
            #pragma unroll
            for (int j = 0; j < 16; j++) xi[j] = sX[j * 128 + l];
            float v0 = cf[ls] + lamW * xi[arow];
            float v1 = cf[2 + ls] + lamW * xi[arow + 8];
            #pragma unroll
            for (int j = 0; j < 16; j++) {
                v0 -= wt0[j] * xi[j];
                v1 -= wt1[j] * xi[j];
            }
            *(float2*)(Fb + l * 16 + arow * 2) =
                make_float2(2.f * lamW - 2.f * SQ2F * v0,
                            2.f * lamW - 2.f * SQ2F * v1);
        }
        if (tid == 0) out_lamW[b] = lamW;
    }
}

// ================= split-K MMA GEMM1: partial C[b,n] =================
__global__ __launch_bounds__(128)
void mma_gemm1(float* __restrict__ dummy)
{
    __shared__ float sP[2 * TILE_F];
    __shared__ float sQ[2 * TILE_F];
    const int n0 = blockIdx.x * 64, b0 = blockIdx.y * 64, kh = blockIdx.z;
    float c[2][4][4] = {};
    tile_gemm<false>(g_Vs + (size_t)b0 * MM + kh * 512,
                     g_AT + (size_t)n0 * MM + kh * 512, MM, 512, c, sP, sQ);

    float* Cp = g_C1 + (size_t)kh * BSZ * NN;
    const int lane = threadIdx.x & 31, wid = threadIdx.x >> 5;
    const int wm = wid & 1, wn = wid >> 1;
    #pragma unroll
    for (int mt = 0; mt < 2; mt++)
        #pragma unroll
        for (int rr = 0; rr < 2; rr++) {
            const int b = b0 + wm * 32 + mt * 16 + (lane >> 2) + rr * 8;
            float* Cb = Cp + (size_t)b * NN;
            #pragma unroll
            for (int nt = 0; nt < 4; nt++) {
                const int n = n0 + wn * 32 + nt * 8 + (lane & 3) * 2;
                *(float2*)(Cb + n) = make_float2(c[mt][nt][rr * 2 + 0],
                                                 c[mt][nt][rr * 2 + 1]);
            }
        }
    (void)dummy;
}

// ================= epi1: combine partials -> u_new =================
__global__ void epi1_kernel(const float* __restrict__ La, const float* __restrict__ lamWv,
                            const float* __restrict__ rho_p, const float* __restrict__ kappa_p,
                            float* __restrict__ out_u)
{
    int idx = blockIdx.x * blockDim.x + threadIdx.x;
    if (idx >= BSZ * NN / 4) return;
    float4 p0 = ((const float4*)g_C1)[idx];
    float4 p1 = ((const float4*)(g_C1 + (size_t)BSZ * NN))[idx];
    int e4 = idx * 4;
    int b = e4 >> 11, n = e4 & 2047;
    float rho = rho_p[0], kappa = kappa_p[0];
    float lamW = lamWv[b];
    float den = 4.f * lamW - 2.f * kappa;
    float4 fb = ((const float4*)g_F)[idx];
    float4 la = *(const float4*)(La + n);
    float4 u;
    u.x = fminf(fmaxf((rho * (p0.x + p1.x) + fb.x - kappa) / (rho * la.x + den), 0.f), 1.f);
    u.y = fminf(fmaxf((rho * (p0.y + p1.y) + fb.y - kappa) / (rho * la.y + den), 0.f), 1.f);
    u.z = fminf(fmaxf((rho * (p0.z + p1.z) + fb.z - kappa) / (rho * la.z + den), 0.f), 1.f);
    u.w = fminf(fmaxf((rho * (p0.w + p1.w) + fb.w - kappa) / (rho * la.w + den), 0.f), 1.f);
    ((float4*)out_u)[idx] = u;
}

// ================= split-K MMA GEMM2: partial C[b,m] =================
__global__ __launch_bounds__(128)
void mma_gemm2(const float* __restrict__ A, const float* __restrict__ u_in)
{
    __shared__ float sP[2 * TILE_F];
    __shared__ float sQ[2 * TILE_F];
    const int m0 = blockIdx.x * 64, b0 = blockIdx.y * 64, kh = blockIdx.z;
    float c[2][4][4] = {};
    tile_gemm<false>(u_in + (size_t)b0 * NN + kh * 1024,
                     A + (size_t)m0 * NN + kh * 1024, NN, 1024, c, sP, sQ);

    float* Cp = g_C2 + (size_t)kh * BSZ * MM;
    const int lane = threadIdx.x & 31, wid = threadIdx.x >> 5;
    const int wm = wid & 1, wn = wid >> 1;
    #pragma unroll
    for (int mt = 0; mt < 2; mt++)
        #pragma unroll
        for (int rr = 0; rr < 2; rr++) {
            const int b = b0 + wm * 32 + mt * 16 + (lane >> 2) + rr * 8;
            float* Cb = Cp + (size_t)b * MM;
            #pragma unroll
            for (int nt = 0; nt < 4; nt++) {
                const int m = m0 + wn * 32 + nt * 8 + (lane & 3) * 2;
                *(float2*)(Cb + m) = make_float2(c[mt][nt][rr * 2 + 0],
                                                 c[mt][nt][rr * 2 + 1]);
            }
        }
}

// ================= epi2: combine partials -> z_new, lambda1_new =================
__global__ void epi2_kernel(const float* __restrict__ theta, const float* __restrict__ z_old,
                            const float* __restrict__ l1_old, const float* __restrict__ relax_p,
                            const float* __restrict__ acc_p,
                            float* __restrict__ out_z, float* __restrict__ out_l1)
{
    int idx = blockIdx.x * blockDim.x + threadIdx.x;
    if (idx >= BSZ * MM / 4) return;
    float4 p0 = ((const float4*)g_C2)[idx];
    float4 p1 = ((const float4*)(g_C2 + (size_t)BSZ * MM))[idx];
    int e4 = idx * 4;
    int m = e4 & 1023;
    float relax = relax_p[0], acc = acc_p[0];
    float4 th = *(const float4*)(theta + m);
    float4 zo = ((const float4*)z_old)[idx];
    float4 lo = ((const float4*)l1_old)[idx];
    float4 zn, ln;
    #define DO(comp) { \
        float ct = p0.comp + p1.comp; \
        float zt = th.comp - relax * ct - (1.f - relax) * (th.comp - zo.comp) - lo.comp; \
        float z1 = fmaxf(zt, 0.f); \
        float l1v = z1 - zt; \
        zn.comp = z1 + acc * (z1 - zo.comp); \
        ln.comp = l1v + acc * (l1v - lo.comp); }
    DO(x) DO(y) DO(z) DO(w)
    #undef DO
    ((float4*)out_z)[idx] = zn;
    ((float4*)out_l1)[idx] = ln;
}

// ================= K4: X_new / XXp_new / acc_new =================
__global__ void x_kernel(const float* __restrict__ u_new, const float* __restrict__ rXp,
                         const float* __restrict__ iXp, const float* __restrict__ accnew_in,
                         float* __restrict__ out_X, float* __restrict__ out_XXp,
                         float* __restrict__ out_acc)
{
    int e = blockIdx.x * blockDim.x + threadIdx.x;
    const int total = BSZ * 16 * LT;
    if (e < total) {
        int b = e / (16 * LT);
        int rem = e - b * (16 * LT);
        int row = rem / LT, l = rem - row * LT;
        int t = row & 7, ci = row >> 3;
        float v;
        if (l < LD) {
            float u = u_new[(size_t)b * NN + l * 16 + t * 2 + ci];
            v = (1.f - 2.f * u) / SQ2F;
            out_X[(size_t)b * 16 * LD + row * LD + l] = v;
        } else {
            int lp = l - LD;
            v = (ci == 0) ? rXp[(size_t)b * NT * LP + t * LP + lp]
                          : iXp[(size_t)b * NT * LP + t * LP + lp];
        }
        out_XXp[e] = v;
    }
    if (e == 0) out_acc[0] = accnew_in[0];
}

// ================= launch =================
extern "C" void kernel_launch(void* const* d_in, const int* in_sizes, int n_in,
                              void* d_out, int out_size) {
    (void)in_sizes; (void)n_in; (void)out_size;
    const float* sigma2   = (const float*)d_in[0];
    const float* X        = (const float*)d_in[1];
    const float* XXp      = (const float*)d_in[2];
    const float* Y        = (const float*)d_in[3];
    const float* YYp      = (const float*)d_in[4];
    const float* rXp      = (const float*)d_in[5];
    const float* iXp      = (const float*)d_in[6];
    const float* H        = (const float*)d_in[7];
    const float* lambda_W = (const float*)d_in[8];
    const float* z        = (const float*)d_in[10];
    const float* lambda1  = (const float*)d_in[11];
    const float* acc_new  = (const float*)d_in[12];
    const float* A        = (const float*)d_in[13];
    const float* Lambda_A = (const float*)d_in[14];
    const float* theta    = (const float*)d_in[15];
    const float* rUr      = (const float*)d_in[16];
    const float* iUr      = (const float*)d_in[17];
    const float* rUt      = (const float*)d_in[18];
    const float* iUt      = (const float*)d_in[19];
    const float* rho      = (const float*)d_in[20];
    const float* kappa    = (const float*)d_in[21];
    const float* epsilon  = (const float*)d_in[22];
    const float* tao      = (const float*)d_in[23];
    const float* factor   = (const float*)d_in[24];
    const float* relax    = (const float*)d_in[25];
    const float* acc      = (const float*)d_in[26];

    float* out = (float*)d_out;
    float* out_X    = out;
    float* out_XXp  = out + 1048576;
    float* out_H    = out + 2228224;
    float* out_lamW = out + 2752512;
    float* out_u    = out + 2753024;
    float* out_z    = out + 3801600;
    float* out_l1   = out + 4325888;
    float* out_acc  = out + 4850176;

    float* dg_Ur, *dg_UrT, *dg_HGT, *dg_T, *dg_HveT, *dg_UrHvT;
    cudaGetSymbolAddress((void**)&dg_Ur, g_Ur);
    cudaGetSymbolAddress((void**)&dg_UrT, g_UrT);
    cudaGetSymbolAddress((void**)&dg_HGT, g_HGT);
    cudaGetSymbolAddress((void**)&dg_T, g_T);
    cudaGetSymbolAddress((void**)&dg_HveT, g_HveT);
    cudaGetSymbolAddress((void**)&dg_UrHvT, g_UrHvT);

    const_kernel<<<64, 256>>>(rUr, iUr);
    v_kernel<<<(BSZ * MM + 255) / 256, 256>>>(theta, z, lambda1);
    at_kernel<<<dim3(64, 32), dim3(32, 8)>>>(A);
    k1a_kernel<<<BSZ, 256>>>(XXp, YYp, H, rUt, iUt);
    mega_gemm<<<dim3(2, BSZ * 24 / 64), 128>>>(dg_UrT, dg_HGT, dg_T);
    k3_kernel<<<BSZ, 256>>>(sigma2, rUt, iUt, tao, epsilon);
    mega_gemm<<<dim3(2, BSZ * 8 / 64), 128>>>(dg_Ur, dg_HveT, dg_UrHvT);
    k5_kernel<<<BSZ, 512>>>(X, Y, lambda_W, rUt, iUt, factor, out_H, out_lamW);
    mma_gemm1<<<dim3(NN / 64, BSZ / 64, 2), 128>>>(nullptr);
    epi1_kernel<<<(BSZ * NN / 4 + 255) / 256, 256>>>(Lambda_A, out_lamW, rho, kappa, out_u);
    mma_gemm2<<<dim3(MM / 64, BSZ / 64, 2), 128>>>(A, out_u);
    epi2_kernel<<<(BSZ * MM / 4 + 255) / 256, 256>>>(theta, z, lambda1, relax, acc,
                                                     out_z, out_l1);
    x_kernel<<<(BSZ * 16 * LT + 255) / 256, 256>>>(out_u, rXp, iXp, acc_new,
                                                   out_X, out_XXp, out_acc);
}